// round 1
// baseline (speedup 1.0000x reference)
#include <cuda_runtime.h>
#include <math.h>

// Problem constants
constexpr int B_   = 2;
constexpr int L_   = 2048;
constexpr int D_   = 1024;
constexpr int H_   = 16;
constexpr int HD_  = 64;
constexpr int WIN_ = 256;
constexpr int M_   = B_ * L_;   // 4096 rows
constexpr int K_   = D_;        // 1024 reduction dim

// Scratch (allocation-free: __device__ globals)
__device__ float g_q[(size_t)B_ * H_ * L_ * HD_];   // [b,h,l,d]
__device__ float g_k[(size_t)B_ * H_ * L_ * HD_];
__device__ float g_v[(size_t)B_ * H_ * L_ * HD_];
__device__ float g_o[(size_t)B_ * L_ * D_];         // attn out, [b,l,h*64+d]

// ---------------------------------------------------------------------------
// GEMM: C[m,n] = sum_k A[m,k] * W[n,k]   (A: MxK row-major, W: NxK row-major)
// MODE 0: A = x, W selected by blockIdx.z in {Wq,Wk,Wv}, epilogue scatters to
//         g_q/g_k/g_v in [B,H,L,HD] layout.
// MODE 1: A = g_o (internal), W = Wo, epilogue writes plain [M, D] to Cout.
// Tile: BM=BN=128, BK=16, 256 threads, 8x8 register tile per thread.
// ---------------------------------------------------------------------------
template <int MODE>
__global__ __launch_bounds__(256) void gemm_kernel(
    const float* __restrict__ A,
    const float* __restrict__ W0,
    const float* __restrict__ W1,
    const float* __restrict__ W2,
    float* __restrict__ Cout)
{
    __shared__ float As[16][132];
    __shared__ float Bs[16][132];

    const int tid = threadIdx.x;
    const int tx  = tid & 15;
    const int ty  = tid >> 4;
    const int m0  = blockIdx.y * 128;
    const int n0  = blockIdx.x * 128;

    const float* Ap = (MODE == 0) ? A : g_o;
    const float* Wp;
    if (MODE == 0) {
        Wp = (blockIdx.z == 0) ? W0 : ((blockIdx.z == 1) ? W1 : W2);
    } else {
        Wp = W0;
    }

    float acc[8][8];
#pragma unroll
    for (int i = 0; i < 8; i++)
#pragma unroll
        for (int j = 0; j < 8; j++) acc[i][j] = 0.0f;

    for (int kt = 0; kt < K_; kt += 16) {
        // Load A tile (128x16) and W tile (128x16), stored transposed in smem.
        // 512 float4 per tile, 2 per thread.
#pragma unroll
        for (int r = 0; r < 2; r++) {
            int f   = tid + r * 256;          // [0,512)
            int row = f >> 2;                 // [0,128)
            int kc  = (f & 3) * 4;            // {0,4,8,12}
            float4 av = *(const float4*)(Ap + (size_t)(m0 + row) * K_ + kt + kc);
            As[kc + 0][row] = av.x;
            As[kc + 1][row] = av.y;
            As[kc + 2][row] = av.z;
            As[kc + 3][row] = av.w;
            float4 bv = *(const float4*)(Wp + (size_t)(n0 + row) * K_ + kt + kc);
            Bs[kc + 0][row] = bv.x;
            Bs[kc + 1][row] = bv.y;
            Bs[kc + 2][row] = bv.z;
            Bs[kc + 3][row] = bv.w;
        }
        __syncthreads();

#pragma unroll
        for (int kk = 0; kk < 16; kk++) {
            float a[8], b[8];
            float4 a0 = *(const float4*)&As[kk][ty * 8];
            float4 a1 = *(const float4*)&As[kk][ty * 8 + 4];
            float4 b0 = *(const float4*)&Bs[kk][tx * 8];
            float4 b1 = *(const float4*)&Bs[kk][tx * 8 + 4];
            a[0] = a0.x; a[1] = a0.y; a[2] = a0.z; a[3] = a0.w;
            a[4] = a1.x; a[5] = a1.y; a[6] = a1.z; a[7] = a1.w;
            b[0] = b0.x; b[1] = b0.y; b[2] = b0.z; b[3] = b0.w;
            b[4] = b1.x; b[5] = b1.y; b[6] = b1.z; b[7] = b1.w;
#pragma unroll
            for (int i = 0; i < 8; i++)
#pragma unroll
                for (int j = 0; j < 8; j++)
                    acc[i][j] = fmaf(a[i], b[j], acc[i][j]);
        }
        __syncthreads();
    }

    if (MODE == 0) {
        float* Out = (blockIdx.z == 0) ? g_q : ((blockIdx.z == 1) ? g_k : g_v);
#pragma unroll
        for (int i = 0; i < 8; i++) {
            int m = m0 + ty * 8 + i;
            int b = m >> 11;            // m / L_
            int l = m & (L_ - 1);
#pragma unroll
            for (int j = 0; j < 8; j++) {
                int n = n0 + tx * 8 + j;
                int h = n >> 6;
                int d = n & 63;
                Out[(((size_t)(b * H_ + h)) * L_ + l) * HD_ + d] = acc[i][j];
            }
        }
    } else {
#pragma unroll
        for (int i = 0; i < 8; i++) {
            int m = m0 + ty * 8 + i;
#pragma unroll
            for (int j = 0; j < 8; j++) {
                int n = n0 + tx * 8 + j;
                Cout[(size_t)m * D_ + n] = acc[i][j];
            }
        }
    }
}

// ---------------------------------------------------------------------------
// RoPE (in-place on g_q, g_k). Each thread owns a (d, d+32) pair.
// q'[d]    = q[d]*cos[d]    - q[d+32]*sin[d]       (d < 32)
// q'[d+32] = q[d+32]*cos[d+32] + q[d]*sin[d+32]
// ---------------------------------------------------------------------------
__global__ __launch_bounds__(256) void rope_kernel(
    const float* __restrict__ cosT,
    const float* __restrict__ sinT)
{
    int idx = blockIdx.x * blockDim.x + threadIdx.x;  // [0, B*H*L*32)
    int d = idx & 31;
    int r = idx >> 5;                                 // (b*H+h)*L + l
    int l = r & (L_ - 1);
    size_t base = (size_t)r * HD_;

    float c0 = cosT[l * HD_ + d];
    float s0 = sinT[l * HD_ + d];
    float c1 = cosT[l * HD_ + d + 32];
    float s1 = sinT[l * HD_ + d + 32];

    float q1 = g_q[base + d], q2 = g_q[base + d + 32];
    g_q[base + d]      = q1 * c0 - q2 * s0;
    g_q[base + d + 32] = q2 * c1 + q1 * s1;

    float k1 = g_k[base + d], k2 = g_k[base + d + 32];
    g_k[base + d]      = k1 * c0 - k2 * s0;
    g_k[base + d + 32] = k2 * c1 + k1 * s1;
}

// ---------------------------------------------------------------------------
// Sliding-window attention: one warp per query. Online softmax over the
// window [max(0, l-WIN), l]. q held in 2 regs/lane; per key: dot via warp
// shfl-xor reduce, then rescale accumulate of v.
// Output into g_o [B, L, D] (heads re-interleaved).
// ---------------------------------------------------------------------------
__global__ __launch_bounds__(256) void attn_kernel()
{
    int gw   = (blockIdx.x * blockDim.x + threadIdx.x) >> 5;  // [0, B*H*L)
    int lane = threadIdx.x & 31;

    int l  = gw & (L_ - 1);
    int bh = gw >> 11;                 // b*H + h

    const float* qp    = g_q + (size_t)gw * HD_;
    const float* kbase = g_k + (size_t)bh * L_ * HD_;
    const float* vbase = g_v + (size_t)bh * L_ * HD_;

    float q0 = qp[lane];
    float q1 = qp[lane + 32];

    int j0 = l - WIN_;
    if (j0 < 0) j0 = 0;

    float m = -INFINITY, ssum = 0.0f, acc0 = 0.0f, acc1 = 0.0f;

#pragma unroll 2
    for (int j = j0; j <= l; j++) {
        const float* kp = kbase + (size_t)j * HD_;
        float s = fmaf(q0, kp[lane], q1 * kp[lane + 32]);
        s += __shfl_xor_sync(0xFFFFFFFFu, s, 16);
        s += __shfl_xor_sync(0xFFFFFFFFu, s, 8);
        s += __shfl_xor_sync(0xFFFFFFFFu, s, 4);
        s += __shfl_xor_sync(0xFFFFFFFFu, s, 2);
        s += __shfl_xor_sync(0xFFFFFFFFu, s, 1);
        s *= 0.125f;                     // 1/sqrt(64)

        float mn = fmaxf(m, s);
        float sc = __expf(m - mn);       // exp(-inf)=0 on first iter
        float p  = __expf(s - mn);

        const float* vp = vbase + (size_t)j * HD_;
        acc0 = fmaf(p, vp[lane],      acc0 * sc);
        acc1 = fmaf(p, vp[lane + 32], acc1 * sc);
        ssum = fmaf(1.0f, p, ssum * sc);
        m = mn;
    }

    float inv = 1.0f / ssum;
    int b = bh >> 4;       // / H_
    int h = bh & (H_ - 1);
    float* op = g_o + ((size_t)(b * L_ + l)) * D_ + h * HD_;
    op[lane]      = acc0 * inv;
    op[lane + 32] = acc1 * inv;
}

// ---------------------------------------------------------------------------
extern "C" void kernel_launch(void* const* d_in, const int* in_sizes, int n_in,
                              void* d_out, int out_size)
{
    const float* x    = (const float*)d_in[0];
    const float* cosT = (const float*)d_in[1];
    const float* sinT = (const float*)d_in[2];
    const float* Wq   = (const float*)d_in[3];
    const float* Wk   = (const float*)d_in[4];
    const float* Wv   = (const float*)d_in[5];
    const float* Wo   = (const float*)d_in[6];
    float* out        = (float*)d_out;

    // 1) Fused QKV projection (z selects Wq/Wk/Wv), scatter to [B,H,L,HD]
    gemm_kernel<0><<<dim3(D_ / 128, M_ / 128, 3), 256>>>(x, Wq, Wk, Wv, nullptr);

    // 2) RoPE in-place on q, k
    rope_kernel<<<(B_ * H_ * L_ * 32) / 256, 256>>>(cosT, sinT);

    // 3) Sliding-window attention (warp per query)
    attn_kernel<<<(B_ * H_ * L_) / 8, 256>>>();

    // 4) Output projection: out = g_o @ Wo^T
    gemm_kernel<1><<<dim3(D_ / 128, M_ / 128, 1), 256>>>(nullptr, Wo, nullptr, nullptr, out);
}

// round 3
// speedup vs baseline: 1.2428x; 1.2428x over previous
#include <cuda_runtime.h>
#include <math.h>

// Problem constants
constexpr int B_   = 2;
constexpr int L_   = 2048;
constexpr int D_   = 1024;
constexpr int H_   = 16;
constexpr int HD_  = 64;
constexpr int WIN_ = 256;
constexpr int M_   = B_ * L_;   // 4096 rows
constexpr int K_   = D_;        // 1024 reduction dim

// Scratch (allocation-free: __device__ globals)
__device__ float g_q   [(size_t)B_ * H_ * L_ * HD_];              // [b,h,l,d]
__device__ float g_klin[(size_t)B_ * H_ * L_ * HD_];              // k, linear [b,h,l,d]
__device__ float g_kt  [(size_t)B_ * H_ * HD_ * L_];              // k, transposed [b,h,d,l]
__device__ float g_v   [(size_t)B_ * H_ * L_ * HD_ + 32 * HD_];   // [b,h,l,d] + chunk-tail pad
__device__ float g_o   [(size_t)B_ * L_ * D_];                    // attn out, [b,l,h*64+d]

// ---------------------------------------------------------------------------
// GEMM: C[m,n] = sum_k A[m,k] * W[n,k]   (A: MxK row-major, W: NxK row-major)
// MODE 0: A = x, W selected by blockIdx.z in {Wq,Wk,Wv}; epilogue scatters to
//         g_q / g_klin / g_v in [B,H,L,HD] layout.
// MODE 1: A = g_o, W = Wo, epilogue writes [M, D] to Cout.
// Tile: BM=BN=128, BK=16, 256 threads, 8x8 register tile, reg-staged
// double buffering (LDG next tile during compute, STS after).
// ---------------------------------------------------------------------------
template <int MODE>
__global__ __launch_bounds__(256, 2) void gemm_kernel(
    const float* __restrict__ A,
    const float* __restrict__ W0,
    const float* __restrict__ W1,
    const float* __restrict__ W2,
    float* __restrict__ Cout)
{
    __shared__ float As[16][132];
    __shared__ float Bs[16][132];

    const int tid = threadIdx.x;
    const int tx  = tid & 15;
    const int ty  = tid >> 4;
    const int m0  = blockIdx.y * 128;
    const int n0  = blockIdx.x * 128;

    const float* Ap = (MODE == 0) ? A : g_o;
    const float* Wp;
    if (MODE == 0) {
        Wp = (blockIdx.z == 0) ? W0 : ((blockIdx.z == 1) ? W1 : W2);
    } else {
        Wp = W0;
    }

    // per-thread staged-load coords: rows row0 and row0+64, k-cols kc0..kc0+3
    const int row0 = tid >> 2;          // [0,64)
    const int kc0  = (tid & 3) * 4;     // {0,4,8,12}
    const float* Abase = Ap + (size_t)(m0 + row0) * K_ + kc0;
    const float* Wbase = Wp + (size_t)(n0 + row0) * K_ + kc0;

    float4 sa0, sb0, sa1, sb1;

    float acc[8][8];
#pragma unroll
    for (int i = 0; i < 8; i++)
#pragma unroll
        for (int j = 0; j < 8; j++) acc[i][j] = 0.0f;

    // prologue: load tile 0
    sa0 = *(const float4*)(Abase);
    sb0 = *(const float4*)(Wbase);
    sa1 = *(const float4*)(Abase + (size_t)64 * K_);
    sb1 = *(const float4*)(Wbase + (size_t)64 * K_);

    for (int kt = 0; kt < K_; kt += 16) {
        // store staged regs into smem
        As[kc0 + 0][row0] = sa0.x; As[kc0 + 1][row0] = sa0.y;
        As[kc0 + 2][row0] = sa0.z; As[kc0 + 3][row0] = sa0.w;
        Bs[kc0 + 0][row0] = sb0.x; Bs[kc0 + 1][row0] = sb0.y;
        Bs[kc0 + 2][row0] = sb0.z; Bs[kc0 + 3][row0] = sb0.w;
        As[kc0 + 0][row0 + 64] = sa1.x; As[kc0 + 1][row0 + 64] = sa1.y;
        As[kc0 + 2][row0 + 64] = sa1.z; As[kc0 + 3][row0 + 64] = sa1.w;
        Bs[kc0 + 0][row0 + 64] = sb1.x; Bs[kc0 + 1][row0 + 64] = sb1.y;
        Bs[kc0 + 2][row0 + 64] = sb1.z; Bs[kc0 + 3][row0 + 64] = sb1.w;
        __syncthreads();

        // prefetch next tile into regs (overlaps with compute below)
        if (kt + 16 < K_) {
            sa0 = *(const float4*)(Abase + kt + 16);
            sb0 = *(const float4*)(Wbase + kt + 16);
            sa1 = *(const float4*)(Abase + (size_t)64 * K_ + kt + 16);
            sb1 = *(const float4*)(Wbase + (size_t)64 * K_ + kt + 16);
        }

#pragma unroll
        for (int kk = 0; kk < 16; kk++) {
            float a[8], b[8];
            float4 a0 = *(const float4*)&As[kk][ty * 8];
            float4 a1 = *(const float4*)&As[kk][ty * 8 + 4];
            float4 b0 = *(const float4*)&Bs[kk][tx * 8];
            float4 b1 = *(const float4*)&Bs[kk][tx * 8 + 4];
            a[0] = a0.x; a[1] = a0.y; a[2] = a0.z; a[3] = a0.w;
            a[4] = a1.x; a[5] = a1.y; a[6] = a1.z; a[7] = a1.w;
            b[0] = b0.x; b[1] = b0.y; b[2] = b0.z; b[3] = b0.w;
            b[4] = b1.x; b[5] = b1.y; b[6] = b1.z; b[7] = b1.w;
#pragma unroll
            for (int i = 0; i < 8; i++)
#pragma unroll
                for (int j = 0; j < 8; j++)
                    acc[i][j] = fmaf(a[i], b[j], acc[i][j]);
        }
        __syncthreads();
    }

    if (MODE == 0) {
        float* Out = (blockIdx.z == 0) ? g_q : ((blockIdx.z == 1) ? g_klin : g_v);
#pragma unroll
        for (int i = 0; i < 8; i++) {
            int m = m0 + ty * 8 + i;
            int b = m >> 11;            // m / L_
            int l = m & (L_ - 1);
#pragma unroll
            for (int j = 0; j < 8; j++) {
                int n = n0 + tx * 8 + j;
                int h = n >> 6;
                int d = n & 63;
                Out[(((size_t)(b * H_ + h)) * L_ + l) * HD_ + d] = acc[i][j];
            }
        }
    } else {
#pragma unroll
        for (int i = 0; i < 8; i++) {
            int m = m0 + ty * 8 + i;
#pragma unroll
            for (int j = 0; j < 8; j++) {
                int n = n0 + tx * 8 + j;
                Cout[(size_t)m * D_ + n] = acc[i][j];
            }
        }
    }
}

// ---------------------------------------------------------------------------
// RoPE + K-transpose. Block = (bh, l-tile of 64). 256 threads.
//  - q: rope applied in place ([b,h,l,d] layout kept).
//  - k: read from g_klin [b,h,l,d], rope applied, transposed via smem tile,
//       written to g_kt [b,h,d,l]. SEPARATE buffers -> no cross-block race.
// ---------------------------------------------------------------------------
__global__ __launch_bounds__(256) void rope_transpose_kernel(
    const float* __restrict__ cosT,
    const float* __restrict__ sinT)
{
    __shared__ float kt_s[64][65];

    const int bh = blockIdx.x;          // [0, 32)
    const int l0 = blockIdx.y * 64;
    const int tid = threadIdx.x;
    const int dp   = tid & 31;          // d in [0,32) (pairs with d+32)
    const int lrow = tid >> 5;          // [0,8)

    const float* kbuf = g_klin + (size_t)bh * L_ * HD_;   // linear [l][d]
    float* qbuf = g_q + (size_t)bh * L_ * HD_;

#pragma unroll
    for (int r = 0; r < 8; r++) {
        int ll = lrow + r * 8;          // local l in [0,64)
        int l  = l0 + ll;
        float c0 = cosT[l * HD_ + dp];
        float s0 = sinT[l * HD_ + dp];
        float c1 = cosT[l * HD_ + dp + 32];
        float s1 = sinT[l * HD_ + dp + 32];

        size_t base = (size_t)l * HD_;

        float q1 = qbuf[base + dp], q2 = qbuf[base + dp + 32];
        qbuf[base + dp]      = q1 * c0 - q2 * s0;
        qbuf[base + dp + 32] = q2 * c1 + q1 * s1;

        float k1 = kbuf[base + dp], k2 = kbuf[base + dp + 32];
        kt_s[dp][ll]      = k1 * c0 - k2 * s0;
        kt_s[dp + 32][ll] = k2 * c1 + k1 * s1;
    }
    __syncthreads();

    // write transposed: g_kt[bh][d][l0 + c] (coalesced along c)
    float* ktbuf = g_kt + (size_t)bh * HD_ * L_;
#pragma unroll
    for (int i = 0; i < 16; i++) {
        int idx = tid + i * 256;        // [0, 4096)
        int d = idx >> 6;
        int c = idx & 63;
        ktbuf[(size_t)d * L_ + l0 + c] = kt_s[d][c];
    }
}

// ---------------------------------------------------------------------------
// Sliding-window attention: one warp per query, one lane per key (32-key
// aligned chunks). Online softmax vectorized across lanes.
//   scores: s_lane = sum_d q[d] * kt[d][c0+lane]   (coalesced LDG, q via shfl)
//   softmax: warp max/sum reduce per CHUNK (not per key), 2 MUFU per chunk
//   PV: broadcast p_j, accumulate v[j][lane], v[j][lane+32]
// ---------------------------------------------------------------------------
__global__ __launch_bounds__(256) void attn_kernel()
{
    const int gw   = (blockIdx.x * blockDim.x + threadIdx.x) >> 5;  // [0, B*H*L)
    const int lane = threadIdx.x & 31;

    const int l  = gw & (L_ - 1);
    const int bh = gw >> 11;                 // b*H + h

    const float* qp = g_q + (size_t)gw * HD_;
    const float q0 = qp[lane];
    const float q1 = qp[lane + 32];

    const int lo    = (l - WIN_ > 0) ? (l - WIN_) : 0;   // inclusive window start
    const int start = lo & ~31;                          // aligned chunk start

    const float* ktb = g_kt + (size_t)bh * HD_ * L_;
    const float* vb  = g_v  + (size_t)bh * L_ * HD_;

    float m = -INFINITY, ssum = 0.0f, acc0 = 0.0f, acc1 = 0.0f;

    for (int c0 = start; c0 <= l; c0 += 32) {
        const int j = c0 + lane;

        // ---- scores: 4 partial fma chains, coalesced kt loads ----
        const float* ktp = ktb + c0 + lane;
        float p0 = 0.f, p1 = 0.f, p2 = 0.f, p3 = 0.f;
#pragma unroll
        for (int d = 0; d < 32; d += 4) {
            p0 = fmaf(__shfl_sync(0xFFFFFFFFu, q0, d + 0), ktp[(size_t)(d + 0) * L_], p0);
            p1 = fmaf(__shfl_sync(0xFFFFFFFFu, q0, d + 1), ktp[(size_t)(d + 1) * L_], p1);
            p2 = fmaf(__shfl_sync(0xFFFFFFFFu, q0, d + 2), ktp[(size_t)(d + 2) * L_], p2);
            p3 = fmaf(__shfl_sync(0xFFFFFFFFu, q0, d + 3), ktp[(size_t)(d + 3) * L_], p3);
        }
#pragma unroll
        for (int d = 0; d < 32; d += 4) {
            p0 = fmaf(__shfl_sync(0xFFFFFFFFu, q1, d + 0), ktp[(size_t)(d + 32) * L_], p0);
            p1 = fmaf(__shfl_sync(0xFFFFFFFFu, q1, d + 1), ktp[(size_t)(d + 33) * L_], p1);
            p2 = fmaf(__shfl_sync(0xFFFFFFFFu, q1, d + 2), ktp[(size_t)(d + 34) * L_], p2);
            p3 = fmaf(__shfl_sync(0xFFFFFFFFu, q1, d + 3), ktp[(size_t)(d + 35) * L_], p3);
        }
        float s = ((p0 + p1) + (p2 + p3)) * 0.125f;      // 1/sqrt(64)
        if (j < lo || j > l) s = -INFINITY;               // window mask

        // ---- online softmax (per-chunk reduce) ----
        float cm = s;
        cm = fmaxf(cm, __shfl_xor_sync(0xFFFFFFFFu, cm, 16));
        cm = fmaxf(cm, __shfl_xor_sync(0xFFFFFFFFu, cm, 8));
        cm = fmaxf(cm, __shfl_xor_sync(0xFFFFFFFFu, cm, 4));
        cm = fmaxf(cm, __shfl_xor_sync(0xFFFFFFFFu, cm, 2));
        cm = fmaxf(cm, __shfl_xor_sync(0xFFFFFFFFu, cm, 1));
        const float mn    = fmaxf(m, cm);
        const float scale = __expf(m - mn);               // 0 on first chunk
        const float p     = __expf(s - mn);               // 0 for masked lanes

        float ps = p;
        ps += __shfl_xor_sync(0xFFFFFFFFu, ps, 16);
        ps += __shfl_xor_sync(0xFFFFFFFFu, ps, 8);
        ps += __shfl_xor_sync(0xFFFFFFFFu, ps, 4);
        ps += __shfl_xor_sync(0xFFFFFFFFu, ps, 2);
        ps += __shfl_xor_sync(0xFFFFFFFFu, ps, 1);

        ssum = ssum * scale + ps;
        acc0 *= scale;
        acc1 *= scale;
        m = mn;

        // ---- PV: broadcast p_j, accumulate v (g_v is tail-padded) ----
        const float* vp = vb + (size_t)c0 * HD_;
#pragma unroll
        for (int jj = 0; jj < 32; jj++) {
            float pb = __shfl_sync(0xFFFFFFFFu, p, jj);
            acc0 = fmaf(pb, vp[jj * HD_ + lane],      acc0);
            acc1 = fmaf(pb, vp[jj * HD_ + lane + 32], acc1);
        }
    }

    const float inv = 1.0f / ssum;
    const int b = bh >> 4;
    const int h = bh & (H_ - 1);
    float* op = g_o + ((size_t)(b * L_ + l)) * D_ + h * HD_;
    op[lane]      = acc0 * inv;
    op[lane + 32] = acc1 * inv;
}

// ---------------------------------------------------------------------------
extern "C" void kernel_launch(void* const* d_in, const int* in_sizes, int n_in,
                              void* d_out, int out_size)
{
    const float* x    = (const float*)d_in[0];
    const float* cosT = (const float*)d_in[1];
    const float* sinT = (const float*)d_in[2];
    const float* Wq   = (const float*)d_in[3];
    const float* Wk   = (const float*)d_in[4];
    const float* Wv   = (const float*)d_in[5];
    const float* Wo   = (const float*)d_in[6];
    float* out        = (float*)d_out;

    // 1) Fused QKV projection; k lands linearly in g_klin
    gemm_kernel<0><<<dim3(D_ / 128, M_ / 128, 3), 256>>>(x, Wq, Wk, Wv, nullptr);

    // 2) RoPE on q (in place) + rope&transpose k: g_klin -> g_kt [b,h,d,l]
    rope_transpose_kernel<<<dim3(B_ * H_, L_ / 64), 256>>>(cosT, sinT);

    // 3) Sliding-window attention (warp/query, lane/key)
    attn_kernel<<<(B_ * H_ * L_) / 8, 256>>>();

    // 4) Output projection
    gemm_kernel<1><<<dim3(D_ / 128, M_ / 128, 1), 256>>>(nullptr, Wo, nullptr, nullptr, out);
}

// round 5
// speedup vs baseline: 1.7911x; 1.4412x over previous
#include <cuda_runtime.h>
#include <cuda_bf16.h>
#include <math.h>
#include <stdint.h>

// Problem constants
constexpr int B_   = 2;
constexpr int L_   = 2048;
constexpr int D_   = 1024;
constexpr int H_   = 16;
constexpr int HD_  = 64;
constexpr int WIN_ = 256;
constexpr int M_   = B_ * L_;   // 4096 rows
constexpr int K_   = D_;        // 1024 reduction dim

// Scratch (allocation-free: __device__ globals)
__device__ float g_q   [(size_t)B_ * H_ * L_ * HD_];              // [b,h,l,d]
__device__ float g_klin[(size_t)B_ * H_ * L_ * HD_];              // k, linear [b,h,l,d]
__device__ float g_kt  [(size_t)B_ * H_ * HD_ * L_];              // k, transposed [b,h,d,l]
__device__ float g_v   [(size_t)B_ * H_ * L_ * HD_ + 32 * HD_];   // [b,h,l,d] + chunk-tail pad
__device__ float g_o   [(size_t)B_ * L_ * D_];                    // attn out, [b,l,h*64+d]

// split-bf16 operands
__device__ __nv_bfloat16 g_xhi[(size_t)M_ * K_];
__device__ __nv_bfloat16 g_xlo[(size_t)M_ * K_];
__device__ __nv_bfloat16 g_whi[(size_t)4 * K_ * K_];   // Wq,Wk,Wv,Wo
__device__ __nv_bfloat16 g_wlo[(size_t)4 * K_ * K_];
__device__ __nv_bfloat16 g_ohi[(size_t)M_ * K_];
__device__ __nv_bfloat16 g_olo[(size_t)M_ * K_];

// mma.sync m16n8k16 bf16 (baseline PTX, works on plain sm_103 target)
#define MMA16816(d, a, b) \
    asm volatile("mma.sync.aligned.m16n8k16.row.col.f32.bf16.bf16.f32 " \
        "{%0,%1,%2,%3}, {%4,%5,%6,%7}, {%8,%9}, {%0,%1,%2,%3};" \
        : "+f"((d)[0]), "+f"((d)[1]), "+f"((d)[2]), "+f"((d)[3]) \
        : "r"((a)[0]), "r"((a)[1]), "r"((a)[2]), "r"((a)[3]), \
          "r"((b)[0]), "r"((b)[1]))

// ===========================================================================
// split: fp32 -> (hi, lo) bf16 pair.  4 elems/thread.
// ===========================================================================
__global__ __launch_bounds__(256) void split_kernel(
    const float* __restrict__ src,
    __nv_bfloat16* __restrict__ hi,
    __nv_bfloat16* __restrict__ lo)
{
    int i = (blockIdx.x * 256 + threadIdx.x) * 4;
    float4 v = *(const float4*)(src + i);
    __nv_bfloat16 h0 = __float2bfloat16(v.x);
    __nv_bfloat16 h1 = __float2bfloat16(v.y);
    __nv_bfloat16 h2 = __float2bfloat16(v.z);
    __nv_bfloat16 h3 = __float2bfloat16(v.w);
    __nv_bfloat16 l0 = __float2bfloat16(v.x - __bfloat162float(h0));
    __nv_bfloat16 l1 = __float2bfloat16(v.y - __bfloat162float(h1));
    __nv_bfloat16 l2 = __float2bfloat16(v.z - __bfloat162float(h2));
    __nv_bfloat16 l3 = __float2bfloat16(v.w - __bfloat162float(h3));
    uint2 ho, loo;
    ho.x  = (uint32_t)__bfloat16_as_ushort(h0) | ((uint32_t)__bfloat16_as_ushort(h1) << 16);
    ho.y  = (uint32_t)__bfloat16_as_ushort(h2) | ((uint32_t)__bfloat16_as_ushort(h3) << 16);
    loo.x = (uint32_t)__bfloat16_as_ushort(l0) | ((uint32_t)__bfloat16_as_ushort(l1) << 16);
    loo.y = (uint32_t)__bfloat16_as_ushort(l2) | ((uint32_t)__bfloat16_as_ushort(l3) << 16);
    *(uint2*)(hi + i) = ho;
    *(uint2*)(lo + i) = loo;
}

// ===========================================================================
// HMMA split-bf16 GEMM: C[m,n] = sum_k A[m,k]*W[n,k]
//   A = Ahi + Alo, W = Whi + Wlo; accumulate Ahi*Whi + Ahi*Wlo + Alo*Whi
//   into ONE fragment set (fp32 accum).
// Tile: BM=BN=128, BK=32, 256 threads. Warp grid 2(M)x4(N): warp tile 64x32
// = 4 m-frags x 4 n-frags of m16n8k16. Smem stride 40 bf16 (conflict-free).
// MODE 0: W = whi/wlo + z*K*K (z=blockIdx.z in {0,1,2}); scatter epilogue.
// MODE 1: W = slot 3 (Wo); linear [M,D] epilogue.
// ===========================================================================
constexpr int STR = 40;   // smem row stride in bf16 (32 data + 8 pad)

template <int MODE>
__global__ __launch_bounds__(256) void gemm_mma(
    const __nv_bfloat16* __restrict__ Ahi,
    const __nv_bfloat16* __restrict__ Alo,
    const __nv_bfloat16* __restrict__ WhiAll,
    const __nv_bfloat16* __restrict__ WloAll,
    float* __restrict__ Cout)
{
    __shared__ __nv_bfloat16 sAh[128 * STR];
    __shared__ __nv_bfloat16 sAl[128 * STR];
    __shared__ __nv_bfloat16 sWh[128 * STR];
    __shared__ __nv_bfloat16 sWl[128 * STR];

    const int tid    = threadIdx.x;
    const int wid    = tid >> 5;
    const int lane   = tid & 31;
    const int warp_m = wid & 1;        // 0..1 (64 rows each)
    const int warp_n = wid >> 1;       // 0..3 (32 cols each)
    const int m0     = blockIdx.y * 128;
    const int n0     = blockIdx.x * 128;
    const int z      = (MODE == 0) ? blockIdx.z : 3;

    const __nv_bfloat16* Whi = WhiAll + (size_t)z * K_ * K_;
    const __nv_bfloat16* Wlo = WloAll + (size_t)z * K_ * K_;

    // global-load geometry: unit = 16B (8 bf16); 512 units/matrix, 2/thread
    const int grow = tid >> 2;          // [0,64)
    const int gseg = (tid & 3) * 8;     // bf16 offset {0,8,16,24}

    float acc[4][4][4];
#pragma unroll
    for (int i = 0; i < 4; i++)
#pragma unroll
        for (int j = 0; j < 4; j++)
#pragma unroll
            for (int r = 0; r < 4; r++) acc[i][j][r] = 0.0f;

    uint4 st[8];
    auto ldg_chunk = [&](int kt0) {
#pragma unroll
        for (int t = 0; t < 2; t++) {
            int r = grow + t * 64;
            size_t ao = (size_t)(m0 + r) * K_ + kt0 + gseg;
            size_t wo = (size_t)(n0 + r) * K_ + kt0 + gseg;
            st[t * 4 + 0] = *(const uint4*)(Ahi + ao);
            st[t * 4 + 1] = *(const uint4*)(Alo + ao);
            st[t * 4 + 2] = *(const uint4*)(Whi + wo);
            st[t * 4 + 3] = *(const uint4*)(Wlo + wo);
        }
    };

    ldg_chunk(0);

    for (int c = 0; c < K_ / 32; c++) {
        // store staged chunk to smem
#pragma unroll
        for (int t = 0; t < 2; t++) {
            int so = (grow + t * 64) * STR + gseg;
            *(uint4*)(sAh + so) = st[t * 4 + 0];
            *(uint4*)(sAl + so) = st[t * 4 + 1];
            *(uint4*)(sWh + so) = st[t * 4 + 2];
            *(uint4*)(sWl + so) = st[t * 4 + 3];
        }
        __syncthreads();

        // prefetch next chunk (overlaps compute)
        if (c + 1 < K_ / 32) ldg_chunk((c + 1) * 32);

        const int lr = lane >> 2;            // 0..7
        const int kp = (lane & 3) * 2;       // 0,2,4,6

#pragma unroll
        for (int ks = 0; ks < 32; ks += 16) {
            // B fragments (hi & lo) for 4 n-tiles
            uint32_t bh[4][2], bl[4][2];
#pragma unroll
            for (int j = 0; j < 4; j++) {
                int nrow = warp_n * 32 + j * 8 + lr;
                int kk   = ks + kp;
                bh[j][0] = *(const uint32_t*)(sWh + nrow * STR + kk);
                bh[j][1] = *(const uint32_t*)(sWh + nrow * STR + kk + 8);
                bl[j][0] = *(const uint32_t*)(sWl + nrow * STR + kk);
                bl[j][1] = *(const uint32_t*)(sWl + nrow * STR + kk + 8);
            }
#pragma unroll
            for (int i = 0; i < 4; i++) {
                int mrow = warp_m * 64 + i * 16 + lr;
                int kk   = ks + kp;
                uint32_t ah[4], al[4];
                ah[0] = *(const uint32_t*)(sAh + mrow * STR + kk);
                ah[1] = *(const uint32_t*)(sAh + (mrow + 8) * STR + kk);
                ah[2] = *(const uint32_t*)(sAh + mrow * STR + kk + 8);
                ah[3] = *(const uint32_t*)(sAh + (mrow + 8) * STR + kk + 8);
                al[0] = *(const uint32_t*)(sAl + mrow * STR + kk);
                al[1] = *(const uint32_t*)(sAl + (mrow + 8) * STR + kk);
                al[2] = *(const uint32_t*)(sAl + mrow * STR + kk + 8);
                al[3] = *(const uint32_t*)(sAl + (mrow + 8) * STR + kk + 8);
#pragma unroll
                for (int j = 0; j < 4; j++) {
                    MMA16816(acc[i][j], ah, bh[j]);
                    MMA16816(acc[i][j], ah, bl[j]);
                    MMA16816(acc[i][j], al, bh[j]);
                }
            }
        }
        __syncthreads();
    }

    // epilogue: thread owns 2x2 per (i,j) frag; cols come in aligned pairs
    const int lr = lane >> 2;
    const int lc = (lane & 3) * 2;
#pragma unroll
    for (int i = 0; i < 4; i++) {
        int mr = m0 + warp_m * 64 + i * 16 + lr;
#pragma unroll
        for (int rr = 0; rr < 2; rr++) {
            int m = mr + rr * 8;
            if (MODE == 0) {
                float* Out = (blockIdx.z == 0) ? g_q : ((blockIdx.z == 1) ? g_klin : g_v);
                int bb = m >> 11;
                int l  = m & (L_ - 1);
#pragma unroll
                for (int j = 0; j < 4; j++) {
                    int n = n0 + warp_n * 32 + j * 8 + lc;
                    int h = n >> 6;
                    int d = n & 63;
                    float2 v = make_float2(acc[i][j][rr * 2 + 0], acc[i][j][rr * 2 + 1]);
                    *(float2*)&Out[(((size_t)(bb * H_ + h)) * L_ + l) * HD_ + d] = v;
                }
            } else {
#pragma unroll
                for (int j = 0; j < 4; j++) {
                    int n = n0 + warp_n * 32 + j * 8 + lc;
                    float2 v = make_float2(acc[i][j][rr * 2 + 0], acc[i][j][rr * 2 + 1]);
                    *(float2*)&Cout[(size_t)m * D_ + n] = v;
                }
            }
        }
    }
}

// ---------------------------------------------------------------------------
// RoPE + K-transpose (unchanged, passing)
// ---------------------------------------------------------------------------
__global__ __launch_bounds__(256) void rope_transpose_kernel(
    const float* __restrict__ cosT,
    const float* __restrict__ sinT)
{
    __shared__ float kt_s[64][65];

    const int bh = blockIdx.x;
    const int l0 = blockIdx.y * 64;
    const int tid = threadIdx.x;
    const int dp   = tid & 31;
    const int lrow = tid >> 5;

    const float* kbuf = g_klin + (size_t)bh * L_ * HD_;
    float* qbuf = g_q + (size_t)bh * L_ * HD_;

#pragma unroll
    for (int r = 0; r < 8; r++) {
        int ll = lrow + r * 8;
        int l  = l0 + ll;
        float c0 = cosT[l * HD_ + dp];
        float s0 = sinT[l * HD_ + dp];
        float c1 = cosT[l * HD_ + dp + 32];
        float s1 = sinT[l * HD_ + dp + 32];

        size_t base = (size_t)l * HD_;

        float q1 = qbuf[base + dp], q2 = qbuf[base + dp + 32];
        qbuf[base + dp]      = q1 * c0 - q2 * s0;
        qbuf[base + dp + 32] = q2 * c1 + q1 * s1;

        float k1 = kbuf[base + dp], k2 = kbuf[base + dp + 32];
        kt_s[dp][ll]      = k1 * c0 - k2 * s0;
        kt_s[dp + 32][ll] = k2 * c1 + k1 * s1;
    }
    __syncthreads();

    float* ktbuf = g_kt + (size_t)bh * HD_ * L_;
#pragma unroll
    for (int i = 0; i < 16; i++) {
        int idx = tid + i * 256;
        int d = idx >> 6;
        int c = idx & 63;
        ktbuf[(size_t)d * L_ + l0 + c] = kt_s[d][c];
    }
}

// ---------------------------------------------------------------------------
// Sliding-window attention (unchanged, passing)
// ---------------------------------------------------------------------------
__global__ __launch_bounds__(256) void attn_kernel()
{
    const int gw   = (blockIdx.x * blockDim.x + threadIdx.x) >> 5;
    const int lane = threadIdx.x & 31;

    const int l  = gw & (L_ - 1);
    const int bh = gw >> 11;

    const float* qp = g_q + (size_t)gw * HD_;
    const float q0 = qp[lane];
    const float q1 = qp[lane + 32];

    const int lo    = (l - WIN_ > 0) ? (l - WIN_) : 0;
    const int start = lo & ~31;

    const float* ktb = g_kt + (size_t)bh * HD_ * L_;
    const float* vb  = g_v  + (size_t)bh * L_ * HD_;

    float m = -INFINITY, ssum = 0.0f, acc0 = 0.0f, acc1 = 0.0f;

    for (int c0 = start; c0 <= l; c0 += 32) {
        const int j = c0 + lane;

        const float* ktp = ktb + c0 + lane;
        float p0 = 0.f, p1 = 0.f, p2 = 0.f, p3 = 0.f;
#pragma unroll
        for (int d = 0; d < 32; d += 4) {
            p0 = fmaf(__shfl_sync(0xFFFFFFFFu, q0, d + 0), ktp[(size_t)(d + 0) * L_], p0);
            p1 = fmaf(__shfl_sync(0xFFFFFFFFu, q0, d + 1), ktp[(size_t)(d + 1) * L_], p1);
            p2 = fmaf(__shfl_sync(0xFFFFFFFFu, q0, d + 2), ktp[(size_t)(d + 2) * L_], p2);
            p3 = fmaf(__shfl_sync(0xFFFFFFFFu, q0, d + 3), ktp[(size_t)(d + 3) * L_], p3);
        }
#pragma unroll
        for (int d = 0; d < 32; d += 4) {
            p0 = fmaf(__shfl_sync(0xFFFFFFFFu, q1, d + 0), ktp[(size_t)(d + 32) * L_], p0);
            p1 = fmaf(__shfl_sync(0xFFFFFFFFu, q1, d + 1), ktp[(size_t)(d + 33) * L_], p1);
            p2 = fmaf(__shfl_sync(0xFFFFFFFFu, q1, d + 2), ktp[(size_t)(d + 34) * L_], p2);
            p3 = fmaf(__shfl_sync(0xFFFFFFFFu, q1, d + 3), ktp[(size_t)(d + 35) * L_], p3);
        }
        float s = ((p0 + p1) + (p2 + p3)) * 0.125f;
        if (j < lo || j > l) s = -INFINITY;

        float cm = s;
        cm = fmaxf(cm, __shfl_xor_sync(0xFFFFFFFFu, cm, 16));
        cm = fmaxf(cm, __shfl_xor_sync(0xFFFFFFFFu, cm, 8));
        cm = fmaxf(cm, __shfl_xor_sync(0xFFFFFFFFu, cm, 4));
        cm = fmaxf(cm, __shfl_xor_sync(0xFFFFFFFFu, cm, 2));
        cm = fmaxf(cm, __shfl_xor_sync(0xFFFFFFFFu, cm, 1));
        const float mn    = fmaxf(m, cm);
        const float scale = __expf(m - mn);
        const float p     = __expf(s - mn);

        float ps = p;
        ps += __shfl_xor_sync(0xFFFFFFFFu, ps, 16);
        ps += __shfl_xor_sync(0xFFFFFFFFu, ps, 8);
        ps += __shfl_xor_sync(0xFFFFFFFFu, ps, 4);
        ps += __shfl_xor_sync(0xFFFFFFFFu, ps, 2);
        ps += __shfl_xor_sync(0xFFFFFFFFu, ps, 1);

        ssum = ssum * scale + ps;
        acc0 *= scale;
        acc1 *= scale;
        m = mn;

        const float* vp = vb + (size_t)c0 * HD_;
#pragma unroll
        for (int jj = 0; jj < 32; jj++) {
            float pb = __shfl_sync(0xFFFFFFFFu, p, jj);
            acc0 = fmaf(pb, vp[jj * HD_ + lane],      acc0);
            acc1 = fmaf(pb, vp[jj * HD_ + lane + 32], acc1);
        }
    }

    const float inv = 1.0f / ssum;
    const int b = bh >> 4;
    const int h = bh & (H_ - 1);
    float* op = g_o + ((size_t)(b * L_ + l)) * D_ + h * HD_;
    op[lane]      = acc0 * inv;
    op[lane + 32] = acc1 * inv;
}

// ---------------------------------------------------------------------------
extern "C" void kernel_launch(void* const* d_in, const int* in_sizes, int n_in,
                              void* d_out, int out_size)
{
    const float* x    = (const float*)d_in[0];
    const float* cosT = (const float*)d_in[1];
    const float* sinT = (const float*)d_in[2];
    const float* Wq   = (const float*)d_in[3];
    const float* Wk   = (const float*)d_in[4];
    const float* Wv   = (const float*)d_in[5];
    const float* Wo   = (const float*)d_in[6];
    float* out        = (float*)d_out;

    // resolve device-global addresses (host side, pure lookups)
    __nv_bfloat16 *xhi, *xlo, *whi, *wlo, *ohi, *olo;
    cudaGetSymbolAddress((void**)&xhi, g_xhi);
    cudaGetSymbolAddress((void**)&xlo, g_xlo);
    cudaGetSymbolAddress((void**)&whi, g_whi);
    cudaGetSymbolAddress((void**)&wlo, g_wlo);
    cudaGetSymbolAddress((void**)&ohi, g_ohi);
    cudaGetSymbolAddress((void**)&olo, g_olo);
    float* o;
    cudaGetSymbolAddress((void**)&o, g_o);

    // 1) split operands to bf16 hi/lo
    split_kernel<<<(M_ * K_) / 1024, 256>>>(x, xhi, xlo);
    split_kernel<<<(K_ * K_) / 1024, 256>>>(Wq, whi + 0 * (size_t)K_ * K_, wlo + 0 * (size_t)K_ * K_);
    split_kernel<<<(K_ * K_) / 1024, 256>>>(Wk, whi + 1 * (size_t)K_ * K_, wlo + 1 * (size_t)K_ * K_);
    split_kernel<<<(K_ * K_) / 1024, 256>>>(Wv, whi + 2 * (size_t)K_ * K_, wlo + 2 * (size_t)K_ * K_);
    split_kernel<<<(K_ * K_) / 1024, 256>>>(Wo, whi + 3 * (size_t)K_ * K_, wlo + 3 * (size_t)K_ * K_);

    // 2) QKV projection on tensor cores (z selects Wq/Wk/Wv)
    gemm_mma<0><<<dim3(D_ / 128, M_ / 128, 3), 256>>>(xhi, xlo, whi, wlo, nullptr);

    // 3) RoPE on q (in place) + rope&transpose k: g_klin -> g_kt
    rope_transpose_kernel<<<dim3(B_ * H_, L_ / 64), 256>>>(cosT, sinT);

    // 4) Sliding-window attention
    attn_kernel<<<(B_ * H_ * L_) / 8, 256>>>();

    // 5) split attention output, then output projection on tensor cores
    split_kernel<<<(M_ * K_) / 1024, 256>>>(o, ohi, olo);
    gemm_mma<1><<<dim3(D_ / 128, M_ / 128, 1), 256>>>(ohi, olo, whi, wlo, out);
}

// round 6
// speedup vs baseline: 3.0738x; 1.7162x over previous
#include <cuda_runtime.h>
#include <cuda_bf16.h>
#include <math.h>
#include <stdint.h>

// Problem constants
constexpr int B_   = 2;
constexpr int L_   = 2048;
constexpr int D_   = 1024;
constexpr int H_   = 16;
constexpr int HD_  = 64;
constexpr int WIN_ = 256;
constexpr int M_   = B_ * L_;   // 4096 rows
constexpr int K_   = D_;        // 1024 reduction dim

// Scratch (allocation-free: __device__ globals)
__device__ float g_q   [(size_t)B_ * H_ * L_ * HD_];   // [b,h,l,d] (rope'd in place)
__device__ float g_klin[(size_t)B_ * H_ * L_ * HD_];   // k [b,h,l,d] (rope'd in place)
__device__ float g_vt  [(size_t)B_ * H_ * HD_ * L_];   // v transposed [b,h,d,l]
__device__ float g_v   [(size_t)B_ * H_ * L_ * HD_];   // v [b,h,l,d]
__device__ float g_o   [(size_t)B_ * L_ * D_];         // attn out, [b,l,h*64+d]

// split-bf16 operands
__device__ __nv_bfloat16 g_xhi[(size_t)M_ * K_];
__device__ __nv_bfloat16 g_xlo[(size_t)M_ * K_];
__device__ __nv_bfloat16 g_whi[(size_t)4 * K_ * K_];   // Wq,Wk,Wv,Wo
__device__ __nv_bfloat16 g_wlo[(size_t)4 * K_ * K_];
__device__ __nv_bfloat16 g_ohi[(size_t)M_ * K_];
__device__ __nv_bfloat16 g_olo[(size_t)M_ * K_];

// mma.sync m16n8k16 bf16 (baseline PTX, works on plain sm_103 target)
#define MMA16816(d, a, b) \
    asm volatile("mma.sync.aligned.m16n8k16.row.col.f32.bf16.bf16.f32 " \
        "{%0,%1,%2,%3}, {%4,%5,%6,%7}, {%8,%9}, {%0,%1,%2,%3};" \
        : "+f"((d)[0]), "+f"((d)[1]), "+f"((d)[2]), "+f"((d)[3]) \
        : "r"((a)[0]), "r"((a)[1]), "r"((a)[2]), "r"((a)[3]), \
          "r"((b)[0]), "r"((b)[1]))

__device__ __forceinline__ uint32_t pack_bf16x2(float a, float b) {
    __nv_bfloat16 ha = __float2bfloat16(a), hb = __float2bfloat16(b);
    return (uint32_t)__bfloat16_as_ushort(ha) | ((uint32_t)__bfloat16_as_ushort(hb) << 16);
}
__device__ __forceinline__ void split2(float a, float b, uint32_t& hi, uint32_t& lo) {
    __nv_bfloat16 ha = __float2bfloat16(a), hb = __float2bfloat16(b);
    hi = (uint32_t)__bfloat16_as_ushort(ha) | ((uint32_t)__bfloat16_as_ushort(hb) << 16);
    lo = pack_bf16x2(a - __bfloat162float(ha), b - __bfloat162float(hb));
}

// ===========================================================================
// split: fp32 -> (hi, lo) bf16 pair.  4 elems/thread.
// ===========================================================================
__global__ __launch_bounds__(256) void split_kernel(
    const float* __restrict__ src,
    __nv_bfloat16* __restrict__ hi,
    __nv_bfloat16* __restrict__ lo)
{
    int i = (blockIdx.x * 256 + threadIdx.x) * 4;
    float4 v = *(const float4*)(src + i);
    uint2 ho, loo;
    split2(v.x, v.y, ho.x, loo.x);
    split2(v.z, v.w, ho.y, loo.y);
    *(uint2*)(hi + i) = ho;
    *(uint2*)(lo + i) = loo;
}

// ===========================================================================
// HMMA split-bf16 GEMM (unchanged from R5, passing)
// ===========================================================================
constexpr int STR = 40;   // smem row stride in bf16 (32 data + 8 pad)

template <int MODE>
__global__ __launch_bounds__(256) void gemm_mma(
    const __nv_bfloat16* __restrict__ Ahi,
    const __nv_bfloat16* __restrict__ Alo,
    const __nv_bfloat16* __restrict__ WhiAll,
    const __nv_bfloat16* __restrict__ WloAll,
    float* __restrict__ Cout)
{
    __shared__ __nv_bfloat16 sAh[128 * STR];
    __shared__ __nv_bfloat16 sAl[128 * STR];
    __shared__ __nv_bfloat16 sWh[128 * STR];
    __shared__ __nv_bfloat16 sWl[128 * STR];

    const int tid    = threadIdx.x;
    const int wid    = tid >> 5;
    const int lane   = tid & 31;
    const int warp_m = wid & 1;
    const int warp_n = wid >> 1;
    const int m0     = blockIdx.y * 128;
    const int n0     = blockIdx.x * 128;
    const int z      = (MODE == 0) ? blockIdx.z : 3;

    const __nv_bfloat16* Whi = WhiAll + (size_t)z * K_ * K_;
    const __nv_bfloat16* Wlo = WloAll + (size_t)z * K_ * K_;

    const int grow = tid >> 2;
    const int gseg = (tid & 3) * 8;

    float acc[4][4][4];
#pragma unroll
    for (int i = 0; i < 4; i++)
#pragma unroll
        for (int j = 0; j < 4; j++)
#pragma unroll
            for (int r = 0; r < 4; r++) acc[i][j][r] = 0.0f;

    uint4 st[8];
    auto ldg_chunk = [&](int kt0) {
#pragma unroll
        for (int t = 0; t < 2; t++) {
            int r = grow + t * 64;
            size_t ao = (size_t)(m0 + r) * K_ + kt0 + gseg;
            size_t wo = (size_t)(n0 + r) * K_ + kt0 + gseg;
            st[t * 4 + 0] = *(const uint4*)(Ahi + ao);
            st[t * 4 + 1] = *(const uint4*)(Alo + ao);
            st[t * 4 + 2] = *(const uint4*)(Whi + wo);
            st[t * 4 + 3] = *(const uint4*)(Wlo + wo);
        }
    };

    ldg_chunk(0);

    for (int c = 0; c < K_ / 32; c++) {
#pragma unroll
        for (int t = 0; t < 2; t++) {
            int so = (grow + t * 64) * STR + gseg;
            *(uint4*)(sAh + so) = st[t * 4 + 0];
            *(uint4*)(sAl + so) = st[t * 4 + 1];
            *(uint4*)(sWh + so) = st[t * 4 + 2];
            *(uint4*)(sWl + so) = st[t * 4 + 3];
        }
        __syncthreads();

        if (c + 1 < K_ / 32) ldg_chunk((c + 1) * 32);

        const int lr = lane >> 2;
        const int kp = (lane & 3) * 2;

#pragma unroll
        for (int ks = 0; ks < 32; ks += 16) {
            uint32_t bh[4][2], bl[4][2];
#pragma unroll
            for (int j = 0; j < 4; j++) {
                int nrow = warp_n * 32 + j * 8 + lr;
                int kk   = ks + kp;
                bh[j][0] = *(const uint32_t*)(sWh + nrow * STR + kk);
                bh[j][1] = *(const uint32_t*)(sWh + nrow * STR + kk + 8);
                bl[j][0] = *(const uint32_t*)(sWl + nrow * STR + kk);
                bl[j][1] = *(const uint32_t*)(sWl + nrow * STR + kk + 8);
            }
#pragma unroll
            for (int i = 0; i < 4; i++) {
                int mrow = warp_m * 64 + i * 16 + lr;
                int kk   = ks + kp;
                uint32_t ah[4], al[4];
                ah[0] = *(const uint32_t*)(sAh + mrow * STR + kk);
                ah[1] = *(const uint32_t*)(sAh + (mrow + 8) * STR + kk);
                ah[2] = *(const uint32_t*)(sAh + mrow * STR + kk + 8);
                ah[3] = *(const uint32_t*)(sAh + (mrow + 8) * STR + kk + 8);
                al[0] = *(const uint32_t*)(sAl + mrow * STR + kk);
                al[1] = *(const uint32_t*)(sAl + (mrow + 8) * STR + kk);
                al[2] = *(const uint32_t*)(sAl + mrow * STR + kk + 8);
                al[3] = *(const uint32_t*)(sAl + (mrow + 8) * STR + kk + 8);
#pragma unroll
                for (int j = 0; j < 4; j++) {
                    MMA16816(acc[i][j], ah, bh[j]);
                    MMA16816(acc[i][j], ah, bl[j]);
                    MMA16816(acc[i][j], al, bh[j]);
                }
            }
        }
        __syncthreads();
    }

    const int lr = lane >> 2;
    const int lc = (lane & 3) * 2;
#pragma unroll
    for (int i = 0; i < 4; i++) {
        int mr = m0 + warp_m * 64 + i * 16 + lr;
#pragma unroll
        for (int rr = 0; rr < 2; rr++) {
            int m = mr + rr * 8;
            if (MODE == 0) {
                float* Out = (blockIdx.z == 0) ? g_q : ((blockIdx.z == 1) ? g_klin : g_v);
                int bb = m >> 11;
                int l  = m & (L_ - 1);
#pragma unroll
                for (int j = 0; j < 4; j++) {
                    int n = n0 + warp_n * 32 + j * 8 + lc;
                    int h = n >> 6;
                    int d = n & 63;
                    float2 v = make_float2(acc[i][j][rr * 2 + 0], acc[i][j][rr * 2 + 1]);
                    *(float2*)&Out[(((size_t)(bb * H_ + h)) * L_ + l) * HD_ + d] = v;
                }
            } else {
#pragma unroll
                for (int j = 0; j < 4; j++) {
                    int n = n0 + warp_n * 32 + j * 8 + lc;
                    float2 v = make_float2(acc[i][j][rr * 2 + 0], acc[i][j][rr * 2 + 1]);
                    *(float2*)&Cout[(size_t)m * D_ + n] = v;
                }
            }
        }
    }
}

// ---------------------------------------------------------------------------
// RoPE (q, k in place) + V transpose: g_v [l][d] -> g_vt [d][l].
// ---------------------------------------------------------------------------
__global__ __launch_bounds__(256) void rope_vt_kernel(
    const float* __restrict__ cosT,
    const float* __restrict__ sinT)
{
    __shared__ float vt_s[64][65];

    const int bh = blockIdx.x;
    const int l0 = blockIdx.y * 64;
    const int tid = threadIdx.x;
    const int dp   = tid & 31;
    const int lrow = tid >> 5;

    float* kbuf = g_klin + (size_t)bh * L_ * HD_;
    float* qbuf = g_q + (size_t)bh * L_ * HD_;
    const float* vbuf = g_v + (size_t)bh * L_ * HD_;

#pragma unroll
    for (int r = 0; r < 8; r++) {
        int ll = lrow + r * 8;
        int l  = l0 + ll;
        float c0 = cosT[l * HD_ + dp];
        float s0 = sinT[l * HD_ + dp];
        float c1 = cosT[l * HD_ + dp + 32];
        float s1 = sinT[l * HD_ + dp + 32];

        size_t base = (size_t)l * HD_;

        float q1 = qbuf[base + dp], q2 = qbuf[base + dp + 32];
        qbuf[base + dp]      = q1 * c0 - q2 * s0;
        qbuf[base + dp + 32] = q2 * c1 + q1 * s1;

        float k1 = kbuf[base + dp], k2 = kbuf[base + dp + 32];
        kbuf[base + dp]      = k1 * c0 - k2 * s0;
        kbuf[base + dp + 32] = k2 * c1 + k1 * s1;

        vt_s[dp][ll]      = vbuf[base + dp];
        vt_s[dp + 32][ll] = vbuf[base + dp + 32];
    }
    __syncthreads();

    float* vtbuf = g_vt + (size_t)bh * HD_ * L_;
#pragma unroll
    for (int i = 0; i < 16; i++) {
        int idx = tid + i * 256;
        int d = idx >> 6;
        int c = idx & 63;
        vtbuf[(size_t)d * L_ + l0 + c] = vt_s[d][c];
    }
}

// ===========================================================================
// Flash attention on HMMA. CTA = 64 queries of one (b,h); 4 warps x 16 rows.
// Key chunks of 64; S = QK^T and O += P V via split-bf16 m16n8k16.
// ===========================================================================
constexpr int SKT = 72;   // smem bf16 stride: 36 words -> conflict-free b-frag LDS

__global__ __launch_bounds__(128) void attn_mma_kernel()
{
    __shared__ __nv_bfloat16 sKh[64 * SKT], sKl[64 * SKT];
    __shared__ __nv_bfloat16 sVh[64 * SKT], sVl[64 * SKT];

    const int tid  = threadIdx.x;
    const int wid  = tid >> 5;
    const int lane = tid & 31;
    const int lr   = lane >> 2;
    const int kp   = (lane & 3) * 2;

    const int bh = blockIdx.x;          // b*H + h
    const int q0 = blockIdx.y * 64;

    const float* qb  = g_q    + ((size_t)bh * L_ + q0) * HD_;
    const float* kb  = g_klin + (size_t)bh * L_ * HD_;
    const float* vtb = g_vt   + (size_t)bh * HD_ * L_;

    // --- Q fragments (hi/lo), loaded once. Warp w owns rows w*16 .. w*16+15.
    uint32_t qh[4][4], ql[4][4];
#pragma unroll
    for (int ks = 0; ks < 4; ks++) {
#pragma unroll
        for (int e = 0; e < 4; e++) {
            int row  = wid * 16 + lr + (e & 1) * 8;
            int kcol = ks * 16 + kp + (e >= 2 ? 8 : 0);
            float2 v = *(const float2*)(qb + (size_t)row * HD_ + kcol);
            split2(v.x, v.y, qh[ks][e], ql[ks][e]);
        }
    }

    float o[8][4];
#pragma unroll
    for (int f = 0; f < 8; f++)
#pragma unroll
        for (int e = 0; e < 4; e++) o[f][e] = 0.0f;
    float m0 = -1e30f, m1 = -1e30f, sum0 = 0.0f, sum1 = 0.0f;

    const int rowa = q0 + wid * 16 + lr;        // this thread's row (lower)
    const int wmin = q0 + wid * 16;             // warp's min row
    const int wmax = wmin + 15;                 // warp's max row
    const int j0s  = (q0 - WIN_ > 0) ? (q0 - WIN_) : 0;

    for (int j0 = j0s; j0 <= q0; j0 += 64) {
        // --- cooperative load + bf16 hi/lo convert: K chunk + V^T chunk ---
        {
            const int r = tid >> 1;                 // row 0..63
            const int cb = (tid & 1) * 32;          // col half
            const float* krow = kb  + (size_t)(j0 + r) * HD_ + cb;
            const float* vrow = vtb + (size_t)r * L_ + j0 + cb;
            __nv_bfloat16* kh = sKh + r * SKT + cb;
            __nv_bfloat16* kl = sKl + r * SKT + cb;
            __nv_bfloat16* vh = sVh + r * SKT + cb;
            __nv_bfloat16* vl = sVl + r * SKT + cb;
#pragma unroll
            for (int it = 0; it < 8; it++) {
                float4 kv = *(const float4*)(krow + it * 4);
                float4 vv = *(const float4*)(vrow + it * 4);
                uint32_t a, b2;
                split2(kv.x, kv.y, a, b2);
                *(uint32_t*)(kh + it * 4)     = a;
                *(uint32_t*)(kl + it * 4)     = b2;
                split2(kv.z, kv.w, a, b2);
                *(uint32_t*)(kh + it * 4 + 2) = a;
                *(uint32_t*)(kl + it * 4 + 2) = b2;
                split2(vv.x, vv.y, a, b2);
                *(uint32_t*)(vh + it * 4)     = a;
                *(uint32_t*)(vl + it * 4)     = b2;
                split2(vv.z, vv.w, a, b2);
                *(uint32_t*)(vh + it * 4 + 2) = a;
                *(uint32_t*)(vl + it * 4 + 2) = b2;
            }
        }
        __syncthreads();

        // --- S = Q K^T (3 split MMAs), frag f covers keys j0 + f*8 .. +7 ---
        float sf[8][4];
#pragma unroll
        for (int f = 0; f < 8; f++)
#pragma unroll
            for (int e = 0; e < 4; e++) sf[f][e] = 0.0f;

#pragma unroll
        for (int ks = 0; ks < 4; ks++) {
#pragma unroll
            for (int f = 0; f < 8; f++) {
                const int nrow = f * 8 + lr;
                const int kc   = ks * 16 + kp;
                uint32_t bhf[2], blf[2];
                bhf[0] = *(const uint32_t*)(sKh + nrow * SKT + kc);
                bhf[1] = *(const uint32_t*)(sKh + nrow * SKT + kc + 8);
                blf[0] = *(const uint32_t*)(sKl + nrow * SKT + kc);
                blf[1] = *(const uint32_t*)(sKl + nrow * SKT + kc + 8);
                MMA16816(sf[f], qh[ks], bhf);
                MMA16816(sf[f], qh[ks], blf);
                MMA16816(sf[f], ql[ks], bhf);
            }
        }

        // --- scale + mask ---
        const bool full = (j0 + 63 <= wmin) && (j0 >= wmax - WIN_);
        if (full) {
#pragma unroll
            for (int f = 0; f < 8; f++)
#pragma unroll
                for (int e = 0; e < 4; e++) sf[f][e] *= 0.125f;
        } else {
#pragma unroll
            for (int f = 0; f < 8; f++) {
#pragma unroll
                for (int e = 0; e < 4; e++) {
                    const int col = j0 + f * 8 + kp + (e & 1);
                    const int row = rowa + (e >= 2 ? 8 : 0);
                    const bool ok = (col <= row) && (col >= row - WIN_);
                    sf[f][e] = ok ? sf[f][e] * 0.125f : -1e30f;
                }
            }
        }

        // --- online softmax (rows lr -> m0, lr+8 -> m1) ---
        float rm0 = -1e30f, rm1 = -1e30f;
#pragma unroll
        for (int f = 0; f < 8; f++) {
            rm0 = fmaxf(rm0, fmaxf(sf[f][0], sf[f][1]));
            rm1 = fmaxf(rm1, fmaxf(sf[f][2], sf[f][3]));
        }
        rm0 = fmaxf(rm0, __shfl_xor_sync(0xFFFFFFFFu, rm0, 1));
        rm0 = fmaxf(rm0, __shfl_xor_sync(0xFFFFFFFFu, rm0, 2));
        rm1 = fmaxf(rm1, __shfl_xor_sync(0xFFFFFFFFu, rm1, 1));
        rm1 = fmaxf(rm1, __shfl_xor_sync(0xFFFFFFFFu, rm1, 2));

        const float mn0 = fmaxf(m0, rm0);
        const float mn1 = fmaxf(m1, rm1);
        const float sc0 = __expf(m0 - mn0);
        const float sc1 = __expf(m1 - mn1);

        float rs0 = 0.0f, rs1 = 0.0f;
#pragma unroll
        for (int f = 0; f < 8; f++) {
            sf[f][0] = __expf(sf[f][0] - mn0);
            sf[f][1] = __expf(sf[f][1] - mn0);
            sf[f][2] = __expf(sf[f][2] - mn1);
            sf[f][3] = __expf(sf[f][3] - mn1);
            rs0 += sf[f][0] + sf[f][1];
            rs1 += sf[f][2] + sf[f][3];
        }
        rs0 += __shfl_xor_sync(0xFFFFFFFFu, rs0, 1);
        rs0 += __shfl_xor_sync(0xFFFFFFFFu, rs0, 2);
        rs1 += __shfl_xor_sync(0xFFFFFFFFu, rs1, 1);
        rs1 += __shfl_xor_sync(0xFFFFFFFFu, rs1, 2);

        sum0 = sum0 * sc0 + rs0;
        sum1 = sum1 * sc1 + rs1;
        m0 = mn0;
        m1 = mn1;
#pragma unroll
        for (int f = 0; f < 8; f++) {
            o[f][0] *= sc0;
            o[f][1] *= sc0;
            o[f][2] *= sc1;
            o[f][3] *= sc1;
        }

        // --- PV: P (in-register frag conversion) x V^T (3 split MMAs) ---
#pragma unroll
        for (int ks = 0; ks < 4; ks++) {
            uint32_t ph[4], pl[4];
            split2(sf[2 * ks][0],     sf[2 * ks][1],     ph[0], pl[0]);
            split2(sf[2 * ks][2],     sf[2 * ks][3],     ph[1], pl[1]);
            split2(sf[2 * ks + 1][0], sf[2 * ks + 1][1], ph[2], pl[2]);
            split2(sf[2 * ks + 1][2], sf[2 * ks + 1][3], ph[3], pl[3]);
#pragma unroll
            for (int f = 0; f < 8; f++) {
                const int nrow = f * 8 + lr;
                const int kc   = ks * 16 + kp;
                uint32_t bhf[2], blf[2];
                bhf[0] = *(const uint32_t*)(sVh + nrow * SKT + kc);
                bhf[1] = *(const uint32_t*)(sVh + nrow * SKT + kc + 8);
                blf[0] = *(const uint32_t*)(sVl + nrow * SKT + kc);
                blf[1] = *(const uint32_t*)(sVl + nrow * SKT + kc + 8);
                MMA16816(o[f], ph, bhf);
                MMA16816(o[f], ph, blf);
                MMA16816(o[f], pl, bhf);
            }
        }
        __syncthreads();
    }

    // --- epilogue: divide by ssum, scatter to g_o[b, l, h*64 + d] ---
    const float inv0 = 1.0f / sum0;
    const float inv1 = 1.0f / sum1;
    const int b = bh >> 4;
    const int h = bh & (H_ - 1);
#pragma unroll
    for (int f = 0; f < 8; f++) {
        const int d = f * 8 + kp;
        float2 v0 = make_float2(o[f][0] * inv0, o[f][1] * inv0);
        float2 v1 = make_float2(o[f][2] * inv1, o[f][3] * inv1);
        *(float2*)&g_o[((size_t)(b * L_ + rowa)) * D_ + h * HD_ + d]     = v0;
        *(float2*)&g_o[((size_t)(b * L_ + rowa + 8)) * D_ + h * HD_ + d] = v1;
    }
}

// ---------------------------------------------------------------------------
extern "C" void kernel_launch(void* const* d_in, const int* in_sizes, int n_in,
                              void* d_out, int out_size)
{
    const float* x    = (const float*)d_in[0];
    const float* cosT = (const float*)d_in[1];
    const float* sinT = (const float*)d_in[2];
    const float* Wq   = (const float*)d_in[3];
    const float* Wk   = (const float*)d_in[4];
    const float* Wv   = (const float*)d_in[5];
    const float* Wo   = (const float*)d_in[6];
    float* out        = (float*)d_out;

    __nv_bfloat16 *xhi, *xlo, *whi, *wlo, *ohi, *olo;
    cudaGetSymbolAddress((void**)&xhi, g_xhi);
    cudaGetSymbolAddress((void**)&xlo, g_xlo);
    cudaGetSymbolAddress((void**)&whi, g_whi);
    cudaGetSymbolAddress((void**)&wlo, g_wlo);
    cudaGetSymbolAddress((void**)&ohi, g_ohi);
    cudaGetSymbolAddress((void**)&olo, g_olo);
    float* o;
    cudaGetSymbolAddress((void**)&o, g_o);

    // 1) split operands to bf16 hi/lo
    split_kernel<<<(M_ * K_) / 1024, 256>>>(x, xhi, xlo);
    split_kernel<<<(K_ * K_) / 1024, 256>>>(Wq, whi + 0 * (size_t)K_ * K_, wlo + 0 * (size_t)K_ * K_);
    split_kernel<<<(K_ * K_) / 1024, 256>>>(Wk, whi + 1 * (size_t)K_ * K_, wlo + 1 * (size_t)K_ * K_);
    split_kernel<<<(K_ * K_) / 1024, 256>>>(Wv, whi + 2 * (size_t)K_ * K_, wlo + 2 * (size_t)K_ * K_);
    split_kernel<<<(K_ * K_) / 1024, 256>>>(Wo, whi + 3 * (size_t)K_ * K_, wlo + 3 * (size_t)K_ * K_);

    // 2) QKV projection on tensor cores
    gemm_mma<0><<<dim3(D_ / 128, M_ / 128, 3), 256>>>(xhi, xlo, whi, wlo, nullptr);

    // 3) RoPE q,k in place + transpose v -> g_vt
    rope_vt_kernel<<<dim3(B_ * H_, L_ / 64), 256>>>(cosT, sinT);

    // 4) Flash attention on tensor cores
    attn_mma_kernel<<<dim3(B_ * H_, L_ / 64), 128>>>();

    // 5) split attention output, then output projection on tensor cores
    split_kernel<<<(M_ * K_) / 1024, 256>>>(o, ohi, olo);
    gemm_mma<1><<<dim3(D_ / 128, M_ / 128, 1), 256>>>(ohi, olo, whi, wlo, out);
}

// round 7
// speedup vs baseline: 3.3189x; 1.0797x over previous
#include <cuda_runtime.h>
#include <cuda_bf16.h>
#include <math.h>
#include <stdint.h>

// Problem constants
constexpr int B_   = 2;
constexpr int L_   = 2048;
constexpr int D_   = 1024;
constexpr int H_   = 16;
constexpr int HD_  = 64;
constexpr int WIN_ = 256;
constexpr int M_   = B_ * L_;   // 4096 rows
constexpr int K_   = D_;        // 1024 reduction dim

// Scratch (allocation-free: __device__ globals)
__device__ float g_q   [(size_t)B_ * H_ * L_ * HD_];   // [b,h,l,d] (rope'd in place)
__device__ float g_klin[(size_t)B_ * H_ * L_ * HD_];   // k [b,h,l,d] (rope'd in place)
__device__ float g_vt  [(size_t)B_ * H_ * HD_ * L_];   // v transposed [b,h,d,l]
__device__ float g_v   [(size_t)B_ * H_ * L_ * HD_];   // v [b,h,l,d]

// split-bf16 operands
__device__ __nv_bfloat16 g_xhi[(size_t)M_ * K_];
__device__ __nv_bfloat16 g_xlo[(size_t)M_ * K_];
__device__ __nv_bfloat16 g_whi[(size_t)4 * K_ * K_];   // Wq,Wk,Wv,Wo
__device__ __nv_bfloat16 g_wlo[(size_t)4 * K_ * K_];
__device__ __nv_bfloat16 g_ohi[(size_t)M_ * K_];       // attn out hi (split fused in epilogue)
__device__ __nv_bfloat16 g_olo[(size_t)M_ * K_];

// mma.sync m16n8k16 bf16 (baseline PTX, works on plain sm_103 target)
#define MMA16816(d, a, b) \
    asm volatile("mma.sync.aligned.m16n8k16.row.col.f32.bf16.bf16.f32 " \
        "{%0,%1,%2,%3}, {%4,%5,%6,%7}, {%8,%9}, {%0,%1,%2,%3};" \
        : "+f"((d)[0]), "+f"((d)[1]), "+f"((d)[2]), "+f"((d)[3]) \
        : "r"((a)[0]), "r"((a)[1]), "r"((a)[2]), "r"((a)[3]), \
          "r"((b)[0]), "r"((b)[1]))

#define LDSM_X4(r0, r1, r2, r3, addr) \
    asm volatile("ldmatrix.sync.aligned.m8n8.x4.shared.b16 {%0,%1,%2,%3}, [%4];" \
        : "=r"(r0), "=r"(r1), "=r"(r2), "=r"(r3) : "r"(addr))

#define CP_ASYNC16(smaddr, gptr) \
    asm volatile("cp.async.cg.shared.global [%0], [%1], 16;" :: "r"(smaddr), "l"(gptr))
#define CP_COMMIT() asm volatile("cp.async.commit_group;" ::: "memory")
#define CP_WAIT(n)  asm volatile("cp.async.wait_group %0;" :: "n"(n) : "memory")

__device__ __forceinline__ uint32_t smem_u32(const void* p) {
    uint32_t a;
    asm("{ .reg .u64 t; cvta.to.shared.u64 t, %1; cvt.u32.u64 %0, t; }" : "=r"(a) : "l"(p));
    return a;
}
__device__ __forceinline__ uint32_t pack_bf16x2(float a, float b) {
    __nv_bfloat16 ha = __float2bfloat16(a), hb = __float2bfloat16(b);
    return (uint32_t)__bfloat16_as_ushort(ha) | ((uint32_t)__bfloat16_as_ushort(hb) << 16);
}
__device__ __forceinline__ void split2(float a, float b, uint32_t& hi, uint32_t& lo) {
    __nv_bfloat16 ha = __float2bfloat16(a), hb = __float2bfloat16(b);
    hi = (uint32_t)__bfloat16_as_ushort(ha) | ((uint32_t)__bfloat16_as_ushort(hb) << 16);
    lo = pack_bf16x2(a - __bfloat162float(ha), b - __bfloat162float(hb));
}

// ===========================================================================
// split: fp32 -> (hi, lo) bf16 pair.  4 elems/thread.
// ===========================================================================
__global__ __launch_bounds__(256) void split_kernel(
    const float* __restrict__ src,
    __nv_bfloat16* __restrict__ hi,
    __nv_bfloat16* __restrict__ lo)
{
    int i = (blockIdx.x * 256 + threadIdx.x) * 4;
    float4 v = *(const float4*)(src + i);
    uint2 ho, loo;
    split2(v.x, v.y, ho.x, loo.x);
    split2(v.z, v.w, ho.y, loo.y);
    *(uint2*)(hi + i) = ho;
    *(uint2*)(lo + i) = loo;
}

// ===========================================================================
// HMMA split-bf16 GEMM v2: ldmatrix fragments + cp.async 4-stage pipeline.
// C[m,n] = sum_k A[m,k]*W[n,k];  A = Ahi+Alo, W = Whi+Wlo (3 products).
// Tile BM=BN=128, BK=32, 256 threads, warp grid 2x4 (warp tile 64x32).
// ===========================================================================
constexpr int STR      = 40;                       // smem row stride (bf16)
constexpr int MAT_B    = 128 * STR * 2;            // 10240 bytes per matrix
constexpr int OFF_AH   = 0;
constexpr int OFF_AL   = MAT_B;
constexpr int OFF_WH   = 2 * MAT_B;
constexpr int OFF_WL   = 3 * MAT_B;
constexpr int STAGE_B  = 4 * MAT_B;                // 40960
constexpr int NSTAGE   = 4;
constexpr int SMEM_GEMM = NSTAGE * STAGE_B;        // 163840
constexpr int NCH      = K_ / 32;                  // 32

template <int MODE>
__global__ __launch_bounds__(256) void gemm_mma(
    const __nv_bfloat16* __restrict__ Ahi,
    const __nv_bfloat16* __restrict__ Alo,
    const __nv_bfloat16* __restrict__ WhiAll,
    const __nv_bfloat16* __restrict__ WloAll,
    float* __restrict__ Cout)
{
    extern __shared__ char dsm[];
    const uint32_t sb = smem_u32(dsm);

    const int tid    = threadIdx.x;
    const int wid    = tid >> 5;
    const int lane   = tid & 31;
    const int warp_m = wid & 1;
    const int warp_n = wid >> 1;
    const int m0     = blockIdx.y * 128;
    const int n0     = blockIdx.x * 128;
    const int z      = (MODE == 0) ? blockIdx.z : 3;

    const __nv_bfloat16* Whi = WhiAll + (size_t)z * K_ * K_;
    const __nv_bfloat16* Wlo = WloAll + (size_t)z * K_ * K_;

    // cp.async copy geometry: 512 x 16B per matrix; thread does rows grow, grow+64
    const int grow = tid >> 2;
    const int gseg = (tid & 3) * 8;                      // bf16 col offset
    const uint32_t cst0 = (uint32_t)grow * 80 + (uint32_t)(tid & 3) * 16;
    const uint32_t cst1 = cst0 + 64 * 80;

    // ldmatrix per-lane byte offsets (within matrix region)
    const int lm = lane & 7;
    const uint32_t a_off = (uint32_t)(warp_m * 64 + lm + ((lane >> 3) & 1) * 8) * 80
                         + (uint32_t)((lane >> 4) & 1) * 16;
    const uint32_t b_off = (uint32_t)(warp_n * 32 + lm + ((lane >> 4) & 1) * 8) * 80
                         + (uint32_t)((lane >> 3) & 1) * 16;

    float acc[4][4][4];
#pragma unroll
    for (int i = 0; i < 4; i++)
#pragma unroll
        for (int j = 0; j < 4; j++)
#pragma unroll
            for (int r = 0; r < 4; r++) acc[i][j][r] = 0.0f;

    auto load_stage = [&](int c, int s) {
        const uint32_t base = sb + (uint32_t)s * STAGE_B;
        const int kt0 = c * 32;
        size_t ao0 = (size_t)(m0 + grow) * K_ + kt0 + gseg;
        size_t wo0 = (size_t)(n0 + grow) * K_ + kt0 + gseg;
        size_t ao1 = ao0 + (size_t)64 * K_;
        size_t wo1 = wo0 + (size_t)64 * K_;
        CP_ASYNC16(base + OFF_AH + cst0, Ahi + ao0);
        CP_ASYNC16(base + OFF_AL + cst0, Alo + ao0);
        CP_ASYNC16(base + OFF_WH + cst0, Whi + wo0);
        CP_ASYNC16(base + OFF_WL + cst0, Wlo + wo0);
        CP_ASYNC16(base + OFF_AH + cst1, Ahi + ao1);
        CP_ASYNC16(base + OFF_AL + cst1, Alo + ao1);
        CP_ASYNC16(base + OFF_WH + cst1, Whi + wo1);
        CP_ASYNC16(base + OFF_WL + cst1, Wlo + wo1);
        CP_COMMIT();
    };

    load_stage(0, 0);
    load_stage(1, 1);

    for (int c = 0; c < NCH; c++) {
        if (c + 2 < NCH) { load_stage(c + 2, (c + 2) & 3); CP_WAIT(2); }
        else if (c + 1 < NCH) { CP_WAIT(1); }
        else { CP_WAIT(0); }
        __syncthreads();

        const uint32_t base = sb + (uint32_t)(c & 3) * STAGE_B;

#pragma unroll
        for (int ks = 0; ks < 2; ks++) {
            const uint32_t kadd = (uint32_t)ks * 32;    // 16 bf16 cols
            uint32_t bh[4][2], bl[4][2];
#pragma unroll
            for (int jp = 0; jp < 4; jp += 2) {
                const uint32_t badd = b_off + (uint32_t)jp * 8 * 80 + kadd;
                LDSM_X4(bh[jp][0], bh[jp][1], bh[jp + 1][0], bh[jp + 1][1],
                        base + OFF_WH + badd);
                LDSM_X4(bl[jp][0], bl[jp][1], bl[jp + 1][0], bl[jp + 1][1],
                        base + OFF_WL + badd);
            }
#pragma unroll
            for (int i = 0; i < 4; i++) {
                const uint32_t aadd = a_off + (uint32_t)i * 16 * 80 + kadd;
                uint32_t ah[4], al[4];
                LDSM_X4(ah[0], ah[1], ah[2], ah[3], base + OFF_AH + aadd);
                LDSM_X4(al[0], al[1], al[2], al[3], base + OFF_AL + aadd);
#pragma unroll
                for (int j = 0; j < 4; j++) {
                    MMA16816(acc[i][j], ah, bh[j]);
                    MMA16816(acc[i][j], ah, bl[j]);
                    MMA16816(acc[i][j], al, bh[j]);
                }
            }
        }
        __syncthreads();
    }

    // epilogue
    const int lr = lane >> 2;
    const int lc = (lane & 3) * 2;
#pragma unroll
    for (int i = 0; i < 4; i++) {
        int mr = m0 + warp_m * 64 + i * 16 + lr;
#pragma unroll
        for (int rr = 0; rr < 2; rr++) {
            int m = mr + rr * 8;
            if (MODE == 0) {
                float* Out = (blockIdx.z == 0) ? g_q : ((blockIdx.z == 1) ? g_klin : g_v);
                int bb = m >> 11;
                int l  = m & (L_ - 1);
#pragma unroll
                for (int j = 0; j < 4; j++) {
                    int n = n0 + warp_n * 32 + j * 8 + lc;
                    int h = n >> 6;
                    int d = n & 63;
                    float2 v = make_float2(acc[i][j][rr * 2 + 0], acc[i][j][rr * 2 + 1]);
                    *(float2*)&Out[(((size_t)(bb * H_ + h)) * L_ + l) * HD_ + d] = v;
                }
            } else {
#pragma unroll
                for (int j = 0; j < 4; j++) {
                    int n = n0 + warp_n * 32 + j * 8 + lc;
                    float2 v = make_float2(acc[i][j][rr * 2 + 0], acc[i][j][rr * 2 + 1]);
                    *(float2*)&Cout[(size_t)m * D_ + n] = v;
                }
            }
        }
    }
}

// ---------------------------------------------------------------------------
// RoPE (q, k in place) + V transpose: g_v [l][d] -> g_vt [d][l].
// ---------------------------------------------------------------------------
__global__ __launch_bounds__(256) void rope_vt_kernel(
    const float* __restrict__ cosT,
    const float* __restrict__ sinT)
{
    __shared__ float vt_s[64][65];

    const int bh = blockIdx.x;
    const int l0 = blockIdx.y * 64;
    const int tid = threadIdx.x;
    const int dp   = tid & 31;
    const int lrow = tid >> 5;

    float* kbuf = g_klin + (size_t)bh * L_ * HD_;
    float* qbuf = g_q + (size_t)bh * L_ * HD_;
    const float* vbuf = g_v + (size_t)bh * L_ * HD_;

#pragma unroll
    for (int r = 0; r < 8; r++) {
        int ll = lrow + r * 8;
        int l  = l0 + ll;
        float c0 = cosT[l * HD_ + dp];
        float s0 = sinT[l * HD_ + dp];
        float c1 = cosT[l * HD_ + dp + 32];
        float s1 = sinT[l * HD_ + dp + 32];

        size_t base = (size_t)l * HD_;

        float q1 = qbuf[base + dp], q2 = qbuf[base + dp + 32];
        qbuf[base + dp]      = q1 * c0 - q2 * s0;
        qbuf[base + dp + 32] = q2 * c1 + q1 * s1;

        float k1 = kbuf[base + dp], k2 = kbuf[base + dp + 32];
        kbuf[base + dp]      = k1 * c0 - k2 * s0;
        kbuf[base + dp + 32] = k2 * c1 + k1 * s1;

        vt_s[dp][ll]      = vbuf[base + dp];
        vt_s[dp + 32][ll] = vbuf[base + dp + 32];
    }
    __syncthreads();

    float* vtbuf = g_vt + (size_t)bh * HD_ * L_;
#pragma unroll
    for (int i = 0; i < 16; i++) {
        int idx = tid + i * 256;
        int d = idx >> 6;
        int c = idx & 63;
        vtbuf[(size_t)d * L_ + l0 + c] = vt_s[d][c];
    }
}

// ===========================================================================
// Flash attention on HMMA (proven in R6); epilogue now emits split bf16
// (g_ohi/g_olo) directly so gemm<1> consumes it without an extra pass.
// ===========================================================================
constexpr int SKT = 72;

__global__ __launch_bounds__(128) void attn_mma_kernel()
{
    __shared__ __nv_bfloat16 sKh[64 * SKT], sKl[64 * SKT];
    __shared__ __nv_bfloat16 sVh[64 * SKT], sVl[64 * SKT];

    const int tid  = threadIdx.x;
    const int wid  = tid >> 5;
    const int lane = tid & 31;
    const int lr   = lane >> 2;
    const int kp   = (lane & 3) * 2;

    const int bh = blockIdx.x;
    const int q0 = blockIdx.y * 64;

    const float* qb  = g_q    + ((size_t)bh * L_ + q0) * HD_;
    const float* kb  = g_klin + (size_t)bh * L_ * HD_;
    const float* vtb = g_vt   + (size_t)bh * HD_ * L_;

    uint32_t qh[4][4], ql[4][4];
#pragma unroll
    for (int ks = 0; ks < 4; ks++) {
#pragma unroll
        for (int e = 0; e < 4; e++) {
            int row  = wid * 16 + lr + (e & 1) * 8;
            int kcol = ks * 16 + kp + (e >= 2 ? 8 : 0);
            float2 v = *(const float2*)(qb + (size_t)row * HD_ + kcol);
            split2(v.x, v.y, qh[ks][e], ql[ks][e]);
        }
    }

    float o[8][4];
#pragma unroll
    for (int f = 0; f < 8; f++)
#pragma unroll
        for (int e = 0; e < 4; e++) o[f][e] = 0.0f;
    float m0 = -1e30f, m1 = -1e30f, sum0 = 0.0f, sum1 = 0.0f;

    const int rowa = q0 + wid * 16 + lr;
    const int wmin = q0 + wid * 16;
    const int wmax = wmin + 15;
    const int j0s  = (q0 - WIN_ > 0) ? (q0 - WIN_) : 0;

    for (int j0 = j0s; j0 <= q0; j0 += 64) {
        {
            const int r = tid >> 1;
            const int cb = (tid & 1) * 32;
            const float* krow = kb  + (size_t)(j0 + r) * HD_ + cb;
            const float* vrow = vtb + (size_t)r * L_ + j0 + cb;
            __nv_bfloat16* kh = sKh + r * SKT + cb;
            __nv_bfloat16* kl = sKl + r * SKT + cb;
            __nv_bfloat16* vh = sVh + r * SKT + cb;
            __nv_bfloat16* vl = sVl + r * SKT + cb;
#pragma unroll
            for (int it = 0; it < 8; it++) {
                float4 kv = *(const float4*)(krow + it * 4);
                float4 vv = *(const float4*)(vrow + it * 4);
                uint32_t a, b2;
                split2(kv.x, kv.y, a, b2);
                *(uint32_t*)(kh + it * 4)     = a;
                *(uint32_t*)(kl + it * 4)     = b2;
                split2(kv.z, kv.w, a, b2);
                *(uint32_t*)(kh + it * 4 + 2) = a;
                *(uint32_t*)(kl + it * 4 + 2) = b2;
                split2(vv.x, vv.y, a, b2);
                *(uint32_t*)(vh + it * 4)     = a;
                *(uint32_t*)(vl + it * 4)     = b2;
                split2(vv.z, vv.w, a, b2);
                *(uint32_t*)(vh + it * 4 + 2) = a;
                *(uint32_t*)(vl + it * 4 + 2) = b2;
            }
        }
        __syncthreads();

        float sf[8][4];
#pragma unroll
        for (int f = 0; f < 8; f++)
#pragma unroll
            for (int e = 0; e < 4; e++) sf[f][e] = 0.0f;

#pragma unroll
        for (int ks = 0; ks < 4; ks++) {
#pragma unroll
            for (int f = 0; f < 8; f++) {
                const int nrow = f * 8 + lr;
                const int kc   = ks * 16 + kp;
                uint32_t bhf[2], blf[2];
                bhf[0] = *(const uint32_t*)(sKh + nrow * SKT + kc);
                bhf[1] = *(const uint32_t*)(sKh + nrow * SKT + kc + 8);
                blf[0] = *(const uint32_t*)(sKl + nrow * SKT + kc);
                blf[1] = *(const uint32_t*)(sKl + nrow * SKT + kc + 8);
                MMA16816(sf[f], qh[ks], bhf);
                MMA16816(sf[f], qh[ks], blf);
                MMA16816(sf[f], ql[ks], bhf);
            }
        }

        const bool full = (j0 + 63 <= wmin) && (j0 >= wmax - WIN_);
        if (full) {
#pragma unroll
            for (int f = 0; f < 8; f++)
#pragma unroll
                for (int e = 0; e < 4; e++) sf[f][e] *= 0.125f;
        } else {
#pragma unroll
            for (int f = 0; f < 8; f++) {
#pragma unroll
                for (int e = 0; e < 4; e++) {
                    const int col = j0 + f * 8 + kp + (e & 1);
                    const int row = rowa + (e >= 2 ? 8 : 0);
                    const bool ok = (col <= row) && (col >= row - WIN_);
                    sf[f][e] = ok ? sf[f][e] * 0.125f : -1e30f;
                }
            }
        }

        float rm0 = -1e30f, rm1 = -1e30f;
#pragma unroll
        for (int f = 0; f < 8; f++) {
            rm0 = fmaxf(rm0, fmaxf(sf[f][0], sf[f][1]));
            rm1 = fmaxf(rm1, fmaxf(sf[f][2], sf[f][3]));
        }
        rm0 = fmaxf(rm0, __shfl_xor_sync(0xFFFFFFFFu, rm0, 1));
        rm0 = fmaxf(rm0, __shfl_xor_sync(0xFFFFFFFFu, rm0, 2));
        rm1 = fmaxf(rm1, __shfl_xor_sync(0xFFFFFFFFu, rm1, 1));
        rm1 = fmaxf(rm1, __shfl_xor_sync(0xFFFFFFFFu, rm1, 2));

        const float mn0 = fmaxf(m0, rm0);
        const float mn1 = fmaxf(m1, rm1);
        const float sc0 = __expf(m0 - mn0);
        const float sc1 = __expf(m1 - mn1);

        float rs0 = 0.0f, rs1 = 0.0f;
#pragma unroll
        for (int f = 0; f < 8; f++) {
            sf[f][0] = __expf(sf[f][0] - mn0);
            sf[f][1] = __expf(sf[f][1] - mn0);
            sf[f][2] = __expf(sf[f][2] - mn1);
            sf[f][3] = __expf(sf[f][3] - mn1);
            rs0 += sf[f][0] + sf[f][1];
            rs1 += sf[f][2] + sf[f][3];
        }
        rs0 += __shfl_xor_sync(0xFFFFFFFFu, rs0, 1);
        rs0 += __shfl_xor_sync(0xFFFFFFFFu, rs0, 2);
        rs1 += __shfl_xor_sync(0xFFFFFFFFu, rs1, 1);
        rs1 += __shfl_xor_sync(0xFFFFFFFFu, rs1, 2);

        sum0 = sum0 * sc0 + rs0;
        sum1 = sum1 * sc1 + rs1;
        m0 = mn0;
        m1 = mn1;
#pragma unroll
        for (int f = 0; f < 8; f++) {
            o[f][0] *= sc0;
            o[f][1] *= sc0;
            o[f][2] *= sc1;
            o[f][3] *= sc1;
        }

#pragma unroll
        for (int ks = 0; ks < 4; ks++) {
            uint32_t ph[4], pl[4];
            split2(sf[2 * ks][0],     sf[2 * ks][1],     ph[0], pl[0]);
            split2(sf[2 * ks][2],     sf[2 * ks][3],     ph[1], pl[1]);
            split2(sf[2 * ks + 1][0], sf[2 * ks + 1][1], ph[2], pl[2]);
            split2(sf[2 * ks + 1][2], sf[2 * ks + 1][3], ph[3], pl[3]);
#pragma unroll
            for (int f = 0; f < 8; f++) {
                const int nrow = f * 8 + lr;
                const int kc   = ks * 16 + kp;
                uint32_t bhf[2], blf[2];
                bhf[0] = *(const uint32_t*)(sVh + nrow * SKT + kc);
                bhf[1] = *(const uint32_t*)(sVh + nrow * SKT + kc + 8);
                blf[0] = *(const uint32_t*)(sVl + nrow * SKT + kc);
                blf[1] = *(const uint32_t*)(sVl + nrow * SKT + kc + 8);
                MMA16816(o[f], ph, bhf);
                MMA16816(o[f], ph, blf);
                MMA16816(o[f], pl, bhf);
            }
        }
        __syncthreads();
    }

    // --- epilogue: normalize + split to bf16 hi/lo, write g_ohi/g_olo ---
    const float inv0 = 1.0f / sum0;
    const float inv1 = 1.0f / sum1;
    const int b = bh >> 4;
    const int h = bh & (H_ - 1);
#pragma unroll
    for (int f = 0; f < 8; f++) {
        const int d = f * 8 + kp;
        const size_t i0 = ((size_t)(b * L_ + rowa)) * D_ + h * HD_ + d;
        const size_t i1 = ((size_t)(b * L_ + rowa + 8)) * D_ + h * HD_ + d;
        uint32_t hi0, lo0, hi1, lo1;
        split2(o[f][0] * inv0, o[f][1] * inv0, hi0, lo0);
        split2(o[f][2] * inv1, o[f][3] * inv1, hi1, lo1);
        *(uint32_t*)&g_ohi[i0] = hi0;
        *(uint32_t*)&g_olo[i0] = lo0;
        *(uint32_t*)&g_ohi[i1] = hi1;
        *(uint32_t*)&g_olo[i1] = lo1;
    }
}

// ---------------------------------------------------------------------------
extern "C" void kernel_launch(void* const* d_in, const int* in_sizes, int n_in,
                              void* d_out, int out_size)
{
    const float* x    = (const float*)d_in[0];
    const float* cosT = (const float*)d_in[1];
    const float* sinT = (const float*)d_in[2];
    const float* Wq   = (const float*)d_in[3];
    const float* Wk   = (const float*)d_in[4];
    const float* Wv   = (const float*)d_in[5];
    const float* Wo   = (const float*)d_in[6];
    float* out        = (float*)d_out;

    cudaFuncSetAttribute(gemm_mma<0>, cudaFuncAttributeMaxDynamicSharedMemorySize, SMEM_GEMM);
    cudaFuncSetAttribute(gemm_mma<1>, cudaFuncAttributeMaxDynamicSharedMemorySize, SMEM_GEMM);

    __nv_bfloat16 *xhi, *xlo, *whi, *wlo, *ohi, *olo;
    cudaGetSymbolAddress((void**)&xhi, g_xhi);
    cudaGetSymbolAddress((void**)&xlo, g_xlo);
    cudaGetSymbolAddress((void**)&whi, g_whi);
    cudaGetSymbolAddress((void**)&wlo, g_wlo);
    cudaGetSymbolAddress((void**)&ohi, g_ohi);
    cudaGetSymbolAddress((void**)&olo, g_olo);

    // 1) split operands to bf16 hi/lo
    split_kernel<<<(M_ * K_) / 1024, 256>>>(x, xhi, xlo);
    split_kernel<<<(K_ * K_) / 1024, 256>>>(Wq, whi + 0 * (size_t)K_ * K_, wlo + 0 * (size_t)K_ * K_);
    split_kernel<<<(K_ * K_) / 1024, 256>>>(Wk, whi + 1 * (size_t)K_ * K_, wlo + 1 * (size_t)K_ * K_);
    split_kernel<<<(K_ * K_) / 1024, 256>>>(Wv, whi + 2 * (size_t)K_ * K_, wlo + 2 * (size_t)K_ * K_);
    split_kernel<<<(K_ * K_) / 1024, 256>>>(Wo, whi + 3 * (size_t)K_ * K_, wlo + 3 * (size_t)K_ * K_);

    // 2) QKV projection on tensor cores
    gemm_mma<0><<<dim3(D_ / 128, M_ / 128, 3), 256, SMEM_GEMM>>>(xhi, xlo, whi, wlo, nullptr);

    // 3) RoPE q,k in place + transpose v -> g_vt
    rope_vt_kernel<<<dim3(B_ * H_, L_ / 64), 256>>>(cosT, sinT);

    // 4) Flash attention on tensor cores (epilogue emits split bf16)
    attn_mma_kernel<<<dim3(B_ * H_, L_ / 64), 128>>>();

    // 5) Output projection on tensor cores
    gemm_mma<1><<<dim3(D_ / 128, M_ / 128, 1), 256, SMEM_GEMM>>>(ohi, olo, whi, wlo, out);
}

// round 8
// speedup vs baseline: 4.7767x; 1.4392x over previous
#include <cuda_runtime.h>
#include <cuda_bf16.h>
#include <cuda_fp16.h>
#include <math.h>
#include <stdint.h>

// Problem constants
constexpr int B_   = 2;
constexpr int L_   = 2048;
constexpr int D_   = 1024;
constexpr int H_   = 16;
constexpr int HD_  = 64;
constexpr int WIN_ = 256;
constexpr int M_   = B_ * L_;   // 4096 rows
constexpr int K_   = D_;        // 1024 reduction dim

// Scratch (allocation-free: __device__ globals)
__device__ float g_q   [(size_t)B_ * H_ * L_ * HD_];   // [b,h,l,d] (rope'd in place)
__device__ float g_klin[(size_t)B_ * H_ * L_ * HD_];   // k [b,h,l,d] (rope'd in place)
__device__ float g_vt  [(size_t)B_ * H_ * HD_ * L_];   // v transposed [b,h,d,l]
__device__ float g_v   [(size_t)B_ * H_ * L_ * HD_];   // v [b,h,l,d]

// fp16 GEMM operands: A single-fp16, W split (hi+lo, exact to 2^-22)
__device__ __half g_xh [(size_t)M_ * K_];
__device__ __half g_whi[(size_t)4 * K_ * K_];   // Wq,Wk,Wv,Wo
__device__ __half g_wlo[(size_t)4 * K_ * K_];
__device__ __half g_oh [(size_t)M_ * K_];       // attn out (fp16, fused in epilogue)

// fp16 m16n8k16 mma (baseline PTX, works on plain sm_103 target)
#define MMA16816H(d, a, b) \
    asm volatile("mma.sync.aligned.m16n8k16.row.col.f32.f16.f16.f32 " \
        "{%0,%1,%2,%3}, {%4,%5,%6,%7}, {%8,%9}, {%0,%1,%2,%3};" \
        : "+f"((d)[0]), "+f"((d)[1]), "+f"((d)[2]), "+f"((d)[3]) \
        : "r"((a)[0]), "r"((a)[1]), "r"((a)[2]), "r"((a)[3]), \
          "r"((b)[0]), "r"((b)[1]))

// bf16 m16n8k16 mma (used by attention kernel, proven R6/R7)
#define MMA16816(d, a, b) \
    asm volatile("mma.sync.aligned.m16n8k16.row.col.f32.bf16.bf16.f32 " \
        "{%0,%1,%2,%3}, {%4,%5,%6,%7}, {%8,%9}, {%0,%1,%2,%3};" \
        : "+f"((d)[0]), "+f"((d)[1]), "+f"((d)[2]), "+f"((d)[3]) \
        : "r"((a)[0]), "r"((a)[1]), "r"((a)[2]), "r"((a)[3]), \
          "r"((b)[0]), "r"((b)[1]))

#define LDSM_X4(r0, r1, r2, r3, addr) \
    asm volatile("ldmatrix.sync.aligned.m8n8.x4.shared.b16 {%0,%1,%2,%3}, [%4];" \
        : "=r"(r0), "=r"(r1), "=r"(r2), "=r"(r3) : "r"(addr))

#define CP_ASYNC16(smaddr, gptr) \
    asm volatile("cp.async.cg.shared.global [%0], [%1], 16;" :: "r"(smaddr), "l"(gptr))
#define CP_COMMIT() asm volatile("cp.async.commit_group;" ::: "memory")
#define CP_WAIT(n)  asm volatile("cp.async.wait_group %0;" :: "n"(n) : "memory")

__device__ __forceinline__ uint32_t smem_u32(const void* p) {
    uint32_t a;
    asm("{ .reg .u64 t; cvta.to.shared.u64 t, %1; cvt.u32.u64 %0, t; }" : "=r"(a) : "l"(p));
    return a;
}
__device__ __forceinline__ uint32_t pack_bf16x2(float a, float b) {
    __nv_bfloat16 ha = __float2bfloat16(a), hb = __float2bfloat16(b);
    return (uint32_t)__bfloat16_as_ushort(ha) | ((uint32_t)__bfloat16_as_ushort(hb) << 16);
}
__device__ __forceinline__ void split2(float a, float b, uint32_t& hi, uint32_t& lo) {
    __nv_bfloat16 ha = __float2bfloat16(a), hb = __float2bfloat16(b);
    hi = (uint32_t)__bfloat16_as_ushort(ha) | ((uint32_t)__bfloat16_as_ushort(hb) << 16);
    lo = pack_bf16x2(a - __bfloat162float(ha), b - __bfloat162float(hb));
}
__device__ __forceinline__ uint32_t pack_h2(float a, float b) {
    __half2 h = __floats2half2_rn(a, b);
    return *(uint32_t*)&h;
}
__device__ __forceinline__ void splith2(float a, float b, uint32_t& hi, uint32_t& lo) {
    __half ha = __float2half_rn(a), hb = __float2half_rn(b);
    hi = (uint32_t)__half_as_ushort(ha) | ((uint32_t)__half_as_ushort(hb) << 16);
    lo = pack_h2(a - __half2float(ha), b - __half2float(hb));
}

// ===========================================================================
// convert: fp32 -> fp16.  4 elems/thread.
// ===========================================================================
__global__ __launch_bounds__(256) void convert_kernel(
    const float* __restrict__ src, __half* __restrict__ dst)
{
    int i = (blockIdx.x * 256 + threadIdx.x) * 4;
    float4 v = *(const float4*)(src + i);
    uint2 o;
    o.x = pack_h2(v.x, v.y);
    o.y = pack_h2(v.z, v.w);
    *(uint2*)(dst + i) = o;
}

// split: fp32 -> (hi, lo) fp16 pair.
__global__ __launch_bounds__(256) void splith_kernel(
    const float* __restrict__ src,
    __half* __restrict__ hi, __half* __restrict__ lo)
{
    int i = (blockIdx.x * 256 + threadIdx.x) * 4;
    float4 v = *(const float4*)(src + i);
    uint2 ho, loo;
    splith2(v.x, v.y, ho.x, loo.x);
    splith2(v.z, v.w, ho.y, loo.y);
    *(uint2*)(hi + i) = ho;
    *(uint2*)(lo + i) = loo;
}

// ===========================================================================
// HMMA fp16 GEMM v3: C[m,n] = sum_k A[m,k]*W[n,k]
//   A = Ah (fp16), W = Wh + Wl (exact fp16 pair): 2 products Ah*Wh + Ah*Wl.
// Tile BM=BN=128, BK=32, 256 threads, 2 CTAs/SM, 3-stage cp.async pipeline.
// ===========================================================================
constexpr int STR      = 40;                       // smem row stride (fp16)
constexpr int MAT_B    = 128 * STR * 2;            // 10240 bytes per matrix
constexpr int OFF_AH   = 0;
constexpr int OFF_WH   = MAT_B;
constexpr int OFF_WL   = 2 * MAT_B;
constexpr int STAGE_B  = 3 * MAT_B;                // 30720
constexpr int NSTAGE   = 3;
constexpr int SMEM_GEMM = NSTAGE * STAGE_B;        // 92160
constexpr int NCH      = K_ / 32;                  // 32

template <int MODE>
__global__ __launch_bounds__(256, 2) void gemm_mma(
    const __half* __restrict__ Ah,
    const __half* __restrict__ WhiAll,
    const __half* __restrict__ WloAll,
    float* __restrict__ Cout)
{
    extern __shared__ char dsm[];
    const uint32_t sb = smem_u32(dsm);

    const int tid    = threadIdx.x;
    const int wid    = tid >> 5;
    const int lane   = tid & 31;
    const int warp_m = wid & 1;
    const int warp_n = wid >> 1;
    const int m0     = blockIdx.y * 128;
    const int n0     = blockIdx.x * 128;
    const int z      = (MODE == 0) ? blockIdx.z : 3;

    const __half* Whi = WhiAll + (size_t)z * K_ * K_;
    const __half* Wlo = WloAll + (size_t)z * K_ * K_;

    // cp.async geometry: 512 x 16B per matrix; thread does rows grow, grow+64
    const int grow = tid >> 2;
    const int gseg = (tid & 3) * 8;
    const uint32_t cst0 = (uint32_t)grow * 80 + (uint32_t)(tid & 3) * 16;
    const uint32_t cst1 = cst0 + 64 * 80;

    // ldmatrix per-lane byte offsets
    const int lm = lane & 7;
    const uint32_t a_off = (uint32_t)(warp_m * 64 + lm + ((lane >> 3) & 1) * 8) * 80
                         + (uint32_t)((lane >> 4) & 1) * 16;
    const uint32_t b_off = (uint32_t)(warp_n * 32 + lm + ((lane >> 4) & 1) * 8) * 80
                         + (uint32_t)((lane >> 3) & 1) * 16;

    float acc[4][4][4];
#pragma unroll
    for (int i = 0; i < 4; i++)
#pragma unroll
        for (int j = 0; j < 4; j++)
#pragma unroll
            for (int r = 0; r < 4; r++) acc[i][j][r] = 0.0f;

    auto load_stage = [&](int c, int s) {
        const uint32_t base = sb + (uint32_t)s * STAGE_B;
        const int kt0 = c * 32;
        size_t ao0 = (size_t)(m0 + grow) * K_ + kt0 + gseg;
        size_t wo0 = (size_t)(n0 + grow) * K_ + kt0 + gseg;
        size_t ao1 = ao0 + (size_t)64 * K_;
        size_t wo1 = wo0 + (size_t)64 * K_;
        CP_ASYNC16(base + OFF_AH + cst0, Ah  + ao0);
        CP_ASYNC16(base + OFF_WH + cst0, Whi + wo0);
        CP_ASYNC16(base + OFF_WL + cst0, Wlo + wo0);
        CP_ASYNC16(base + OFF_AH + cst1, Ah  + ao1);
        CP_ASYNC16(base + OFF_WH + cst1, Whi + wo1);
        CP_ASYNC16(base + OFF_WL + cst1, Wlo + wo1);
        CP_COMMIT();
    };

    load_stage(0, 0);
    load_stage(1, 1);

    int sc = 0;   // compute stage
    int sp = 2;   // prefetch stage
    for (int c = 0; c < NCH; c++) {
        if (c + 2 < NCH) {
            load_stage(c + 2, sp);
            sp = (sp == 2) ? 0 : sp + 1;
            CP_WAIT(2);
        } else if (c + 1 < NCH) {
            CP_WAIT(1);
        } else {
            CP_WAIT(0);
        }
        __syncthreads();

        const uint32_t base = sb + (uint32_t)sc * STAGE_B;
        sc = (sc == 2) ? 0 : sc + 1;

#pragma unroll
        for (int ks = 0; ks < 2; ks++) {
            const uint32_t kadd = (uint32_t)ks * 32;
            uint32_t bh[4][2], bl[4][2];
#pragma unroll
            for (int jp = 0; jp < 4; jp += 2) {
                const uint32_t badd = b_off + (uint32_t)jp * 8 * 80 + kadd;
                LDSM_X4(bh[jp][0], bh[jp][1], bh[jp + 1][0], bh[jp + 1][1],
                        base + OFF_WH + badd);
                LDSM_X4(bl[jp][0], bl[jp][1], bl[jp + 1][0], bl[jp + 1][1],
                        base + OFF_WL + badd);
            }
#pragma unroll
            for (int i = 0; i < 4; i++) {
                const uint32_t aadd = a_off + (uint32_t)i * 16 * 80 + kadd;
                uint32_t ah[4];
                LDSM_X4(ah[0], ah[1], ah[2], ah[3], base + OFF_AH + aadd);
                // dependent pairs spread 4 apart: sweep bh over j, then bl
#pragma unroll
                for (int j = 0; j < 4; j++) MMA16816H(acc[i][j], ah, bh[j]);
#pragma unroll
                for (int j = 0; j < 4; j++) MMA16816H(acc[i][j], ah, bl[j]);
            }
        }
        __syncthreads();
    }

    // epilogue
    const int lr = lane >> 2;
    const int lc = (lane & 3) * 2;
#pragma unroll
    for (int i = 0; i < 4; i++) {
        int mr = m0 + warp_m * 64 + i * 16 + lr;
#pragma unroll
        for (int rr = 0; rr < 2; rr++) {
            int m = mr + rr * 8;
            if (MODE == 0) {
                float* Out = (blockIdx.z == 0) ? g_q : ((blockIdx.z == 1) ? g_klin : g_v);
                int bb = m >> 11;
                int l  = m & (L_ - 1);
#pragma unroll
                for (int j = 0; j < 4; j++) {
                    int n = n0 + warp_n * 32 + j * 8 + lc;
                    int h = n >> 6;
                    int d = n & 63;
                    float2 v = make_float2(acc[i][j][rr * 2 + 0], acc[i][j][rr * 2 + 1]);
                    *(float2*)&Out[(((size_t)(bb * H_ + h)) * L_ + l) * HD_ + d] = v;
                }
            } else {
#pragma unroll
                for (int j = 0; j < 4; j++) {
                    int n = n0 + warp_n * 32 + j * 8 + lc;
                    float2 v = make_float2(acc[i][j][rr * 2 + 0], acc[i][j][rr * 2 + 1]);
                    *(float2*)&Cout[(size_t)m * D_ + n] = v;
                }
            }
        }
    }
}

// ---------------------------------------------------------------------------
// RoPE (q, k in place) + V transpose: g_v [l][d] -> g_vt [d][l].
// ---------------------------------------------------------------------------
__global__ __launch_bounds__(256) void rope_vt_kernel(
    const float* __restrict__ cosT,
    const float* __restrict__ sinT)
{
    __shared__ float vt_s[64][65];

    const int bh = blockIdx.x;
    const int l0 = blockIdx.y * 64;
    const int tid = threadIdx.x;
    const int dp   = tid & 31;
    const int lrow = tid >> 5;

    float* kbuf = g_klin + (size_t)bh * L_ * HD_;
    float* qbuf = g_q + (size_t)bh * L_ * HD_;
    const float* vbuf = g_v + (size_t)bh * L_ * HD_;

#pragma unroll
    for (int r = 0; r < 8; r++) {
        int ll = lrow + r * 8;
        int l  = l0 + ll;
        float c0 = cosT[l * HD_ + dp];
        float s0 = sinT[l * HD_ + dp];
        float c1 = cosT[l * HD_ + dp + 32];
        float s1 = sinT[l * HD_ + dp + 32];

        size_t base = (size_t)l * HD_;

        float q1 = qbuf[base + dp], q2 = qbuf[base + dp + 32];
        qbuf[base + dp]      = q1 * c0 - q2 * s0;
        qbuf[base + dp + 32] = q2 * c1 + q1 * s1;

        float k1 = kbuf[base + dp], k2 = kbuf[base + dp + 32];
        kbuf[base + dp]      = k1 * c0 - k2 * s0;
        kbuf[base + dp + 32] = k2 * c1 + k1 * s1;

        vt_s[dp][ll]      = vbuf[base + dp];
        vt_s[dp + 32][ll] = vbuf[base + dp + 32];
    }
    __syncthreads();

    float* vtbuf = g_vt + (size_t)bh * HD_ * L_;
#pragma unroll
    for (int i = 0; i < 16; i++) {
        int idx = tid + i * 256;
        int d = idx >> 6;
        int c = idx & 63;
        vtbuf[(size_t)d * L_ + l0 + c] = vt_s[d][c];
    }
}

// ===========================================================================
// Flash attention on HMMA (bf16 3-product internals, proven R6/R7).
// Epilogue emits fp16 g_oh directly for the output projection.
// ===========================================================================
constexpr int SKT = 72;

__global__ __launch_bounds__(128) void attn_mma_kernel()
{
    __shared__ __nv_bfloat16 sKh[64 * SKT], sKl[64 * SKT];
    __shared__ __nv_bfloat16 sVh[64 * SKT], sVl[64 * SKT];

    const int tid  = threadIdx.x;
    const int wid  = tid >> 5;
    const int lane = tid & 31;
    const int lr   = lane >> 2;
    const int kp   = (lane & 3) * 2;

    const int bh = blockIdx.x;
    const int q0 = blockIdx.y * 64;

    const float* qb  = g_q    + ((size_t)bh * L_ + q0) * HD_;
    const float* kb  = g_klin + (size_t)bh * L_ * HD_;
    const float* vtb = g_vt   + (size_t)bh * HD_ * L_;

    uint32_t qh[4][4], ql[4][4];
#pragma unroll
    for (int ks = 0; ks < 4; ks++) {
#pragma unroll
        for (int e = 0; e < 4; e++) {
            int row  = wid * 16 + lr + (e & 1) * 8;
            int kcol = ks * 16 + kp + (e >= 2 ? 8 : 0);
            float2 v = *(const float2*)(qb + (size_t)row * HD_ + kcol);
            split2(v.x, v.y, qh[ks][e], ql[ks][e]);
        }
    }

    float o[8][4];
#pragma unroll
    for (int f = 0; f < 8; f++)
#pragma unroll
        for (int e = 0; e < 4; e++) o[f][e] = 0.0f;
    float m0 = -1e30f, m1 = -1e30f, sum0 = 0.0f, sum1 = 0.0f;

    const int rowa = q0 + wid * 16 + lr;
    const int wmin = q0 + wid * 16;
    const int wmax = wmin + 15;
    const int j0s  = (q0 - WIN_ > 0) ? (q0 - WIN_) : 0;

    for (int j0 = j0s; j0 <= q0; j0 += 64) {
        {
            const int r = tid >> 1;
            const int cb = (tid & 1) * 32;
            const float* krow = kb  + (size_t)(j0 + r) * HD_ + cb;
            const float* vrow = vtb + (size_t)r * L_ + j0 + cb;
            __nv_bfloat16* kh = sKh + r * SKT + cb;
            __nv_bfloat16* kl = sKl + r * SKT + cb;
            __nv_bfloat16* vh = sVh + r * SKT + cb;
            __nv_bfloat16* vl = sVl + r * SKT + cb;
#pragma unroll
            for (int it = 0; it < 8; it++) {
                float4 kv = *(const float4*)(krow + it * 4);
                float4 vv = *(const float4*)(vrow + it * 4);
                uint32_t a, b2;
                split2(kv.x, kv.y, a, b2);
                *(uint32_t*)(kh + it * 4)     = a;
                *(uint32_t*)(kl + it * 4)     = b2;
                split2(kv.z, kv.w, a, b2);
                *(uint32_t*)(kh + it * 4 + 2) = a;
                *(uint32_t*)(kl + it * 4 + 2) = b2;
                split2(vv.x, vv.y, a, b2);
                *(uint32_t*)(vh + it * 4)     = a;
                *(uint32_t*)(vl + it * 4)     = b2;
                split2(vv.z, vv.w, a, b2);
                *(uint32_t*)(vh + it * 4 + 2) = a;
                *(uint32_t*)(vl + it * 4 + 2) = b2;
            }
        }
        __syncthreads();

        float sf[8][4];
#pragma unroll
        for (int f = 0; f < 8; f++)
#pragma unroll
            for (int e = 0; e < 4; e++) sf[f][e] = 0.0f;

#pragma unroll
        for (int ks = 0; ks < 4; ks++) {
#pragma unroll
            for (int f = 0; f < 8; f++) {
                const int nrow = f * 8 + lr;
                const int kc   = ks * 16 + kp;
                uint32_t bhf[2], blf[2];
                bhf[0] = *(const uint32_t*)(sKh + nrow * SKT + kc);
                bhf[1] = *(const uint32_t*)(sKh + nrow * SKT + kc + 8);
                blf[0] = *(const uint32_t*)(sKl + nrow * SKT + kc);
                blf[1] = *(const uint32_t*)(sKl + nrow * SKT + kc + 8);
                MMA16816(sf[f], qh[ks], bhf);
                MMA16816(sf[f], qh[ks], blf);
                MMA16816(sf[f], ql[ks], bhf);
            }
        }

        const bool full = (j0 + 63 <= wmin) && (j0 >= wmax - WIN_);
        if (full) {
#pragma unroll
            for (int f = 0; f < 8; f++)
#pragma unroll
                for (int e = 0; e < 4; e++) sf[f][e] *= 0.125f;
        } else {
#pragma unroll
            for (int f = 0; f < 8; f++) {
#pragma unroll
                for (int e = 0; e < 4; e++) {
                    const int col = j0 + f * 8 + kp + (e & 1);
                    const int row = rowa + (e >= 2 ? 8 : 0);
                    const bool ok = (col <= row) && (col >= row - WIN_);
                    sf[f][e] = ok ? sf[f][e] * 0.125f : -1e30f;
                }
            }
        }

        float rm0 = -1e30f, rm1 = -1e30f;
#pragma unroll
        for (int f = 0; f < 8; f++) {
            rm0 = fmaxf(rm0, fmaxf(sf[f][0], sf[f][1]));
            rm1 = fmaxf(rm1, fmaxf(sf[f][2], sf[f][3]));
        }
        rm0 = fmaxf(rm0, __shfl_xor_sync(0xFFFFFFFFu, rm0, 1));
        rm0 = fmaxf(rm0, __shfl_xor_sync(0xFFFFFFFFu, rm0, 2));
        rm1 = fmaxf(rm1, __shfl_xor_sync(0xFFFFFFFFu, rm1, 1));
        rm1 = fmaxf(rm1, __shfl_xor_sync(0xFFFFFFFFu, rm1, 2));

        const float mn0 = fmaxf(m0, rm0);
        const float mn1 = fmaxf(m1, rm1);
        const float sc0 = __expf(m0 - mn0);
        const float sc1 = __expf(m1 - mn1);

        float rs0 = 0.0f, rs1 = 0.0f;
#pragma unroll
        for (int f = 0; f < 8; f++) {
            sf[f][0] = __expf(sf[f][0] - mn0);
            sf[f][1] = __expf(sf[f][1] - mn0);
            sf[f][2] = __expf(sf[f][2] - mn1);
            sf[f][3] = __expf(sf[f][3] - mn1);
            rs0 += sf[f][0] + sf[f][1];
            rs1 += sf[f][2] + sf[f][3];
        }
        rs0 += __shfl_xor_sync(0xFFFFFFFFu, rs0, 1);
        rs0 += __shfl_xor_sync(0xFFFFFFFFu, rs0, 2);
        rs1 += __shfl_xor_sync(0xFFFFFFFFu, rs1, 1);
        rs1 += __shfl_xor_sync(0xFFFFFFFFu, rs1, 2);

        sum0 = sum0 * sc0 + rs0;
        sum1 = sum1 * sc1 + rs1;
        m0 = mn0;
        m1 = mn1;
#pragma unroll
        for (int f = 0; f < 8; f++) {
            o[f][0] *= sc0;
            o[f][1] *= sc0;
            o[f][2] *= sc1;
            o[f][3] *= sc1;
        }

#pragma unroll
        for (int ks = 0; ks < 4; ks++) {
            uint32_t ph[4], pl[4];
            split2(sf[2 * ks][0],     sf[2 * ks][1],     ph[0], pl[0]);
            split2(sf[2 * ks][2],     sf[2 * ks][3],     ph[1], pl[1]);
            split2(sf[2 * ks + 1][0], sf[2 * ks + 1][1], ph[2], pl[2]);
            split2(sf[2 * ks + 1][2], sf[2 * ks + 1][3], ph[3], pl[3]);
#pragma unroll
            for (int f = 0; f < 8; f++) {
                const int nrow = f * 8 + lr;
                const int kc   = ks * 16 + kp;
                uint32_t bhf[2], blf[2];
                bhf[0] = *(const uint32_t*)(sVh + nrow * SKT + kc);
                bhf[1] = *(const uint32_t*)(sVh + nrow * SKT + kc + 8);
                blf[0] = *(const uint32_t*)(sVl + nrow * SKT + kc);
                blf[1] = *(const uint32_t*)(sVl + nrow * SKT + kc + 8);
                MMA16816(o[f], ph, bhf);
                MMA16816(o[f], ph, blf);
                MMA16816(o[f], pl, bhf);
            }
        }
        __syncthreads();
    }

    // --- epilogue: normalize + convert to fp16, write g_oh ---
    const float inv0 = 1.0f / sum0;
    const float inv1 = 1.0f / sum1;
    const int b = bh >> 4;
    const int h = bh & (H_ - 1);
#pragma unroll
    for (int f = 0; f < 8; f++) {
        const int d = f * 8 + kp;
        const size_t i0 = ((size_t)(b * L_ + rowa)) * D_ + h * HD_ + d;
        const size_t i1 = ((size_t)(b * L_ + rowa + 8)) * D_ + h * HD_ + d;
        *(uint32_t*)&g_oh[i0] = pack_h2(o[f][0] * inv0, o[f][1] * inv0);
        *(uint32_t*)&g_oh[i1] = pack_h2(o[f][2] * inv1, o[f][3] * inv1);
    }
}

// ---------------------------------------------------------------------------
extern "C" void kernel_launch(void* const* d_in, const int* in_sizes, int n_in,
                              void* d_out, int out_size)
{
    const float* x    = (const float*)d_in[0];
    const float* cosT = (const float*)d_in[1];
    const float* sinT = (const float*)d_in[2];
    const float* Wq   = (const float*)d_in[3];
    const float* Wk   = (const float*)d_in[4];
    const float* Wv   = (const float*)d_in[5];
    const float* Wo   = (const float*)d_in[6];
    float* out        = (float*)d_out;

    cudaFuncSetAttribute(gemm_mma<0>, cudaFuncAttributeMaxDynamicSharedMemorySize, SMEM_GEMM);
    cudaFuncSetAttribute(gemm_mma<1>, cudaFuncAttributeMaxDynamicSharedMemorySize, SMEM_GEMM);

    __half *xh, *whi, *wlo, *oh;
    cudaGetSymbolAddress((void**)&xh,  g_xh);
    cudaGetSymbolAddress((void**)&whi, g_whi);
    cudaGetSymbolAddress((void**)&wlo, g_wlo);
    cudaGetSymbolAddress((void**)&oh,  g_oh);

    // 1) convert x to fp16; split W's to exact fp16 hi/lo pairs
    convert_kernel<<<(M_ * K_) / 1024, 256>>>(x, xh);
    splith_kernel<<<(K_ * K_) / 1024, 256>>>(Wq, whi + 0 * (size_t)K_ * K_, wlo + 0 * (size_t)K_ * K_);
    splith_kernel<<<(K_ * K_) / 1024, 256>>>(Wk, whi + 1 * (size_t)K_ * K_, wlo + 1 * (size_t)K_ * K_);
    splith_kernel<<<(K_ * K_) / 1024, 256>>>(Wv, whi + 2 * (size_t)K_ * K_, wlo + 2 * (size_t)K_ * K_);
    splith_kernel<<<(K_ * K_) / 1024, 256>>>(Wo, whi + 3 * (size_t)K_ * K_, wlo + 3 * (size_t)K_ * K_);

    // 2) QKV projection on tensor cores
    gemm_mma<0><<<dim3(D_ / 128, M_ / 128, 3), 256, SMEM_GEMM>>>(xh, whi, wlo, nullptr);

    // 3) RoPE q,k in place + transpose v -> g_vt
    rope_vt_kernel<<<dim3(B_ * H_, L_ / 64), 256>>>(cosT, sinT);

    // 4) Flash attention on tensor cores (epilogue emits fp16)
    attn_mma_kernel<<<dim3(B_ * H_, L_ / 64), 128>>>();

    // 5) Output projection on tensor cores
    gemm_mma<1><<<dim3(D_ / 128, M_ / 128, 1), 256, SMEM_GEMM>>>(oh, whi, wlo, out);
}

// round 9
// speedup vs baseline: 5.5477x; 1.1614x over previous
#include <cuda_runtime.h>
#include <cuda_fp16.h>
#include <math.h>
#include <stdint.h>

// Problem constants
constexpr int B_   = 2;
constexpr int L_   = 2048;
constexpr int D_   = 1024;
constexpr int H_   = 16;
constexpr int HD_  = 64;
constexpr int WIN_ = 256;
constexpr int M_   = B_ * L_;   // 4096 rows
constexpr int K_   = D_;        // 1024 reduction dim

// Scratch (allocation-free: __device__ globals)
__device__ float  g_q  [(size_t)B_ * H_ * L_ * HD_];   // q fp32 [b,h,l,d], roped
__device__ __half g_kh [(size_t)B_ * H_ * L_ * HD_];   // k fp16 [b,h,l,d], roped
__device__ __half g_vth[(size_t)B_ * H_ * HD_ * L_];   // v fp16 transposed [b,h,d,l]

__device__ __half g_xh [(size_t)M_ * K_];
__device__ __half g_whi[(size_t)4 * K_ * K_];          // Wq,Wk,Wv,Wo hi
__device__ __half g_wlo[(size_t)4 * K_ * K_];          // lo (W exact as hi+lo)
__device__ __half g_oh [(size_t)M_ * K_];              // attn out fp16

// fp16 m16n8k16 mma (baseline PTX, works on plain sm_103 target)
#define MMA16816H(d, a, b) \
    asm volatile("mma.sync.aligned.m16n8k16.row.col.f32.f16.f16.f32 " \
        "{%0,%1,%2,%3}, {%4,%5,%6,%7}, {%8,%9}, {%0,%1,%2,%3};" \
        : "+f"((d)[0]), "+f"((d)[1]), "+f"((d)[2]), "+f"((d)[3]) \
        : "r"((a)[0]), "r"((a)[1]), "r"((a)[2]), "r"((a)[3]), \
          "r"((b)[0]), "r"((b)[1]))

#define LDSM_X4(r0, r1, r2, r3, addr) \
    asm volatile("ldmatrix.sync.aligned.m8n8.x4.shared.b16 {%0,%1,%2,%3}, [%4];" \
        : "=r"(r0), "=r"(r1), "=r"(r2), "=r"(r3) : "r"(addr))

#define CP_ASYNC16(smaddr, gptr) \
    asm volatile("cp.async.cg.shared.global [%0], [%1], 16;" :: "r"(smaddr), "l"(gptr))
#define CP_COMMIT() asm volatile("cp.async.commit_group;" ::: "memory")
#define CP_WAIT(n)  asm volatile("cp.async.wait_group %0;" :: "n"(n) : "memory")

__device__ __forceinline__ uint32_t smem_u32(const void* p) {
    uint32_t a;
    asm("{ .reg .u64 t; cvta.to.shared.u64 t, %1; cvt.u32.u64 %0, t; }" : "=r"(a) : "l"(p));
    return a;
}
__device__ __forceinline__ uint32_t pack_h2(float a, float b) {
    __half2 h = __floats2half2_rn(a, b);
    return *(uint32_t*)&h;
}
__device__ __forceinline__ void splith2(float a, float b, uint32_t& hi, uint32_t& lo) {
    __half ha = __float2half_rn(a), hb = __float2half_rn(b);
    hi = (uint32_t)__half_as_ushort(ha) | ((uint32_t)__half_as_ushort(hb) << 16);
    lo = pack_h2(a - __half2float(ha), b - __half2float(hb));
}

// ===========================================================================
// convert x: fp32 -> fp16
// ===========================================================================
__global__ __launch_bounds__(256) void convert_kernel(
    const float* __restrict__ src, __half* __restrict__ dst)
{
    int i = (blockIdx.x * 256 + threadIdx.x) * 4;
    float4 v = *(const float4*)(src + i);
    uint2 o;
    o.x = pack_h2(v.x, v.y);
    o.y = pack_h2(v.z, v.w);
    *(uint2*)(dst + i) = o;
}

// split all 4 weight matrices: fp32 -> exact fp16 (hi, lo) pairs. grid.y = W
__global__ __launch_bounds__(256) void splitw_kernel(
    const float* __restrict__ W0, const float* __restrict__ W1,
    const float* __restrict__ W2, const float* __restrict__ W3,
    __half* __restrict__ hi, __half* __restrict__ lo)
{
    const int z = blockIdx.y;
    const float* src = (z == 0) ? W0 : (z == 1) ? W1 : (z == 2) ? W2 : W3;
    const size_t off = (size_t)z * K_ * K_;
    int i = (blockIdx.x * 256 + threadIdx.x) * 4;
    float4 v = *(const float4*)(src + i);
    uint2 ho, loo;
    splith2(v.x, v.y, ho.x, loo.x);
    splith2(v.z, v.w, ho.y, loo.y);
    *(uint2*)(hi + off + i) = ho;
    *(uint2*)(lo + off + i) = loo;
}

// ===========================================================================
// HMMA fp16 GEMM: C[m,n] = sum_k A[m,k]*W[n,k];  A fp16, W = Wh+Wl exact.
// Tile BM=BN=128, BK=32, 256 threads, 2 CTAs/SM, 3-stage cp.async pipeline.
// MODE 0: z selects Wq/Wk/Wv; epilogue fuses RoPE (q,k) and V-transpose,
//         emitting g_q (fp32), g_kh (fp16), g_vth (fp16, [d][l]).
// MODE 1: W slot 3 (Wo), plain [M,D] fp32 epilogue to Cout.
// ===========================================================================
constexpr int MAT_B    = 128 * 40 * 2;             // 10240 bytes per matrix
constexpr int OFF_AH   = 0;
constexpr int OFF_WH   = MAT_B;
constexpr int OFF_WL   = 2 * MAT_B;
constexpr int STAGE_B  = 3 * MAT_B;                // 30720
constexpr int SMEM_GEMM = 3 * STAGE_B;             // 92160
constexpr int NCH      = K_ / 32;                  // 32

template <int MODE>
__global__ __launch_bounds__(256, 2) void gemm_mma(
    const __half* __restrict__ Ah,
    const __half* __restrict__ WhiAll,
    const __half* __restrict__ WloAll,
    const float* __restrict__ cosT,
    const float* __restrict__ sinT,
    float* __restrict__ Cout)
{
    extern __shared__ char dsm[];
    const uint32_t sb = smem_u32(dsm);

    const int tid    = threadIdx.x;
    const int wid    = tid >> 5;
    const int lane   = tid & 31;
    const int warp_m = wid & 1;
    const int warp_n = wid >> 1;
    const int m0     = blockIdx.y * 128;
    const int n0     = blockIdx.x * 128;
    const int z      = (MODE == 0) ? blockIdx.z : 3;

    const __half* Whi = WhiAll + (size_t)z * K_ * K_;
    const __half* Wlo = WloAll + (size_t)z * K_ * K_;

    const int grow = tid >> 2;
    const int gseg = (tid & 3) * 8;
    const uint32_t cst0 = (uint32_t)grow * 80 + (uint32_t)(tid & 3) * 16;
    const uint32_t cst1 = cst0 + 64 * 80;

    const int lm = lane & 7;
    const uint32_t a_off = (uint32_t)(warp_m * 64 + lm + ((lane >> 3) & 1) * 8) * 80
                         + (uint32_t)((lane >> 4) & 1) * 16;
    const uint32_t b_off = (uint32_t)(warp_n * 32 + lm + ((lane >> 4) & 1) * 8) * 80
                         + (uint32_t)((lane >> 3) & 1) * 16;

    float acc[4][4][4];
#pragma unroll
    for (int i = 0; i < 4; i++)
#pragma unroll
        for (int j = 0; j < 4; j++)
#pragma unroll
            for (int r = 0; r < 4; r++) acc[i][j][r] = 0.0f;

    auto load_stage = [&](int c, int s) {
        const uint32_t base = sb + (uint32_t)s * STAGE_B;
        const int kt0 = c * 32;
        size_t ao0 = (size_t)(m0 + grow) * K_ + kt0 + gseg;
        size_t wo0 = (size_t)(n0 + grow) * K_ + kt0 + gseg;
        size_t ao1 = ao0 + (size_t)64 * K_;
        size_t wo1 = wo0 + (size_t)64 * K_;
        CP_ASYNC16(base + OFF_AH + cst0, Ah  + ao0);
        CP_ASYNC16(base + OFF_WH + cst0, Whi + wo0);
        CP_ASYNC16(base + OFF_WL + cst0, Wlo + wo0);
        CP_ASYNC16(base + OFF_AH + cst1, Ah  + ao1);
        CP_ASYNC16(base + OFF_WH + cst1, Whi + wo1);
        CP_ASYNC16(base + OFF_WL + cst1, Wlo + wo1);
        CP_COMMIT();
    };

    load_stage(0, 0);
    load_stage(1, 1);

    int sc = 0, sp = 2;
    for (int c = 0; c < NCH; c++) {
        if (c + 2 < NCH) {
            load_stage(c + 2, sp);
            sp = (sp == 2) ? 0 : sp + 1;
            CP_WAIT(2);
        } else if (c + 1 < NCH) {
            CP_WAIT(1);
        } else {
            CP_WAIT(0);
        }
        __syncthreads();

        const uint32_t base = sb + (uint32_t)sc * STAGE_B;
        sc = (sc == 2) ? 0 : sc + 1;

#pragma unroll
        for (int ks = 0; ks < 2; ks++) {
            const uint32_t kadd = (uint32_t)ks * 32;
            uint32_t bh[4][2], bl[4][2];
#pragma unroll
            for (int jp = 0; jp < 4; jp += 2) {
                const uint32_t badd = b_off + (uint32_t)jp * 8 * 80 + kadd;
                LDSM_X4(bh[jp][0], bh[jp][1], bh[jp + 1][0], bh[jp + 1][1],
                        base + OFF_WH + badd);
                LDSM_X4(bl[jp][0], bl[jp][1], bl[jp + 1][0], bl[jp + 1][1],
                        base + OFF_WL + badd);
            }
#pragma unroll
            for (int i = 0; i < 4; i++) {
                const uint32_t aadd = a_off + (uint32_t)i * 16 * 80 + kadd;
                uint32_t ah[4];
                LDSM_X4(ah[0], ah[1], ah[2], ah[3], base + OFF_AH + aadd);
#pragma unroll
                for (int j = 0; j < 4; j++) MMA16816H(acc[i][j], ah, bh[j]);
#pragma unroll
                for (int j = 0; j < 4; j++) MMA16816H(acc[i][j], ah, bl[j]);
            }
        }
        __syncthreads();
    }

    const int lr = lane >> 2;
    const int lc = (lane & 3) * 2;

    if (MODE == 0) {
        // fused epilogue: stage 16x128 tiles in smem, apply RoPE / transpose
        float* T = (float*)dsm;                 // [2][16][132] fp32
        const int wgrp = tid >> 7;              // write-phase group
        const int wrow = (tid >> 3) & 15;
        const int wc0  = (tid & 7) * 16;
        const int vc   = tid & 127;

#pragma unroll
        for (int i = 0; i < 4; i++) {
            __syncthreads();
            {
                float* Tg = T + warp_m * (16 * 132);
#pragma unroll
                for (int rr = 0; rr < 2; rr++) {
                    int row = lr + rr * 8;
#pragma unroll
                    for (int j = 0; j < 4; j++) {
                        int col = warp_n * 32 + j * 8 + lc;
                        Tg[row * 132 + col]     = acc[i][j][rr * 2 + 0];
                        Tg[row * 132 + col + 1] = acc[i][j][rr * 2 + 1];
                    }
                }
            }
            __syncthreads();

            if (blockIdx.z == 2) {
                // V: transpose write, fp16 g_vth[(b*H+h)*HD+d][l]
                const float* Tv = T + wgrp * (16 * 132);
                int n = n0 + vc, h = n >> 6, d = n & 63;
                int mbase = m0 + wgrp * 64 + i * 16;
                int b = mbase >> 11, l0i = mbase & (L_ - 1);
                __half tmp[16];
#pragma unroll
                for (int r = 0; r < 16; r++)
                    tmp[r] = __float2half_rn(Tv[r * 132 + vc]);
                size_t dst = (((size_t)(b * H_ + h)) * HD_ + d) * L_ + l0i;
                *(uint4*)&g_vth[dst]     = *(uint4*)tmp;
                *(uint4*)&g_vth[dst + 8] = *(uint4*)(tmp + 8);
            } else {
                const float* Tq = T + wgrp * (16 * 132);
                int m = m0 + wgrp * 64 + i * 16 + wrow;
                int b = m >> 11, l = m & (L_ - 1);
                const float* crow = cosT + l * HD_;
                const float* srow = sinT + l * HD_;
                if (blockIdx.z == 0) {
#pragma unroll
                    for (int c4 = 0; c4 < 16; c4 += 4) {
                        int c = wc0 + c4;
                        float vv[4];
#pragma unroll
                        for (int e = 0; e < 4; e++) {
                            int cc = c + e, d = cc & 63;
                            float a  = Tq[wrow * 132 + cc];
                            float ap = Tq[wrow * 132 + (cc ^ 32)];
                            vv[e] = (d < 32) ? a * crow[d] - ap * srow[d]
                                             : a * crow[d] + ap * srow[d];
                        }
                        int n = n0 + c, h = n >> 6, d = n & 63;
                        *(float4*)&g_q[(((size_t)(b * H_ + h)) * L_ + l) * HD_ + d]
                            = *(float4*)vv;
                    }
                } else {
#pragma unroll
                    for (int c8 = 0; c8 < 16; c8 += 8) {
                        int c = wc0 + c8;
                        __half tmp[8];
#pragma unroll
                        for (int e = 0; e < 8; e++) {
                            int cc = c + e, d = cc & 63;
                            float a  = Tq[wrow * 132 + cc];
                            float ap = Tq[wrow * 132 + (cc ^ 32)];
                            float r = (d < 32) ? a * crow[d] - ap * srow[d]
                                               : a * crow[d] + ap * srow[d];
                            tmp[e] = __float2half_rn(r);
                        }
                        int n = n0 + c, h = n >> 6, d = n & 63;
                        *(uint4*)&g_kh[(((size_t)(b * H_ + h)) * L_ + l) * HD_ + d]
                            = *(uint4*)tmp;
                    }
                }
            }
        }
    } else {
#pragma unroll
        for (int i = 0; i < 4; i++) {
            int mr = m0 + warp_m * 64 + i * 16 + lr;
#pragma unroll
            for (int rr = 0; rr < 2; rr++) {
                int m = mr + rr * 8;
#pragma unroll
                for (int j = 0; j < 4; j++) {
                    int n = n0 + warp_n * 32 + j * 8 + lc;
                    float2 v = make_float2(acc[i][j][rr * 2 + 0], acc[i][j][rr * 2 + 1]);
                    *(float2*)&Cout[(size_t)m * D_ + n] = v;
                }
            }
        }
    }
}

// ===========================================================================
// Flash attention, fp16 2-product form. K/V arrive pre-converted fp16.
// CTA = 64 queries of one (b,h); 4 warps x 16 rows; key chunks of 64.
// S = (Qh+Ql) Kh^T ; O += (Ph+Pl) Vh  (Q,P split exact; K,V single fp16)
// ===========================================================================
constexpr int SKT = 72;   // fp16 smem stride (conflict-free b-frag loads)

__global__ __launch_bounds__(128) void attn_mma_kernel()
{
    __shared__ __half sK[64 * SKT], sV[64 * SKT];

    const int tid  = threadIdx.x;
    const int wid  = tid >> 5;
    const int lane = tid & 31;
    const int lr   = lane >> 2;
    const int kp   = (lane & 3) * 2;

    const int bh = blockIdx.x;
    const int q0 = blockIdx.y * 64;

    const float*  qb  = g_q   + ((size_t)bh * L_ + q0) * HD_;
    const __half* kb  = g_kh  + (size_t)bh * L_ * HD_;
    const __half* vtb = g_vth + (size_t)bh * HD_ * L_;

    // Q fragments (fp16 hi/lo, near-exact), loaded once
    uint32_t qh[4][4], ql[4][4];
#pragma unroll
    for (int ks = 0; ks < 4; ks++) {
#pragma unroll
        for (int e = 0; e < 4; e++) {
            int row  = wid * 16 + lr + (e & 1) * 8;
            int kcol = ks * 16 + kp + (e >= 2 ? 8 : 0);
            float2 v = *(const float2*)(qb + (size_t)row * HD_ + kcol);
            splith2(v.x, v.y, qh[ks][e], ql[ks][e]);
        }
    }

    float o[8][4];
#pragma unroll
    for (int f = 0; f < 8; f++)
#pragma unroll
        for (int e = 0; e < 4; e++) o[f][e] = 0.0f;
    float m0 = -1e30f, m1 = -1e30f, sum0 = 0.0f, sum1 = 0.0f;

    const int rowa = q0 + wid * 16 + lr;
    const int wmin = q0 + wid * 16;
    const int wmax = wmin + 15;
    const int j0s  = (q0 - WIN_ > 0) ? (q0 - WIN_) : 0;

    for (int j0 = j0s; j0 <= q0; j0 += 64) {
        // copy K chunk [64 keys][64 d] and V^T chunk [64 d][64 keys] (fp16)
        {
            const int r  = tid >> 1;
            const int cb = (tid & 1) * 32;
            const uint4* ks4 = (const uint4*)(kb  + (size_t)(j0 + r) * HD_ + cb);
            const uint4* vs4 = (const uint4*)(vtb + (size_t)r * L_ + j0 + cb);
            uint4* kd4 = (uint4*)(sK + r * SKT + cb);
            uint4* vd4 = (uint4*)(sV + r * SKT + cb);
#pragma unroll
            for (int it = 0; it < 4; it++) {
                kd4[it] = ks4[it];
                vd4[it] = vs4[it];
            }
        }
        __syncthreads();

        // S = Q K^T (2 products)
        float sf[8][4];
#pragma unroll
        for (int f = 0; f < 8; f++)
#pragma unroll
            for (int e = 0; e < 4; e++) sf[f][e] = 0.0f;

#pragma unroll
        for (int ks = 0; ks < 4; ks++) {
#pragma unroll
            for (int f = 0; f < 8; f++) {
                const int nrow = f * 8 + lr;
                const int kc   = ks * 16 + kp;
                uint32_t kf[2];
                kf[0] = *(const uint32_t*)(sK + nrow * SKT + kc);
                kf[1] = *(const uint32_t*)(sK + nrow * SKT + kc + 8);
                MMA16816H(sf[f], qh[ks], kf);
                MMA16816H(sf[f], ql[ks], kf);
            }
        }

        // scale + mask
        const bool full = (j0 + 63 <= wmin) && (j0 >= wmax - WIN_);
        if (full) {
#pragma unroll
            for (int f = 0; f < 8; f++)
#pragma unroll
                for (int e = 0; e < 4; e++) sf[f][e] *= 0.125f;
        } else {
#pragma unroll
            for (int f = 0; f < 8; f++) {
#pragma unroll
                for (int e = 0; e < 4; e++) {
                    const int col = j0 + f * 8 + kp + (e & 1);
                    const int row = rowa + (e >= 2 ? 8 : 0);
                    const bool ok = (col <= row) && (col >= row - WIN_);
                    sf[f][e] = ok ? sf[f][e] * 0.125f : -1e30f;
                }
            }
        }

        // online softmax
        float rm0 = -1e30f, rm1 = -1e30f;
#pragma unroll
        for (int f = 0; f < 8; f++) {
            rm0 = fmaxf(rm0, fmaxf(sf[f][0], sf[f][1]));
            rm1 = fmaxf(rm1, fmaxf(sf[f][2], sf[f][3]));
        }
        rm0 = fmaxf(rm0, __shfl_xor_sync(0xFFFFFFFFu, rm0, 1));
        rm0 = fmaxf(rm0, __shfl_xor_sync(0xFFFFFFFFu, rm0, 2));
        rm1 = fmaxf(rm1, __shfl_xor_sync(0xFFFFFFFFu, rm1, 1));
        rm1 = fmaxf(rm1, __shfl_xor_sync(0xFFFFFFFFu, rm1, 2));

        const float mn0 = fmaxf(m0, rm0);
        const float mn1 = fmaxf(m1, rm1);
        const float sc0 = __expf(m0 - mn0);
        const float sc1 = __expf(m1 - mn1);

        float rs0 = 0.0f, rs1 = 0.0f;
#pragma unroll
        for (int f = 0; f < 8; f++) {
            sf[f][0] = __expf(sf[f][0] - mn0);
            sf[f][1] = __expf(sf[f][1] - mn0);
            sf[f][2] = __expf(sf[f][2] - mn1);
            sf[f][3] = __expf(sf[f][3] - mn1);
            rs0 += sf[f][0] + sf[f][1];
            rs1 += sf[f][2] + sf[f][3];
        }
        rs0 += __shfl_xor_sync(0xFFFFFFFFu, rs0, 1);
        rs0 += __shfl_xor_sync(0xFFFFFFFFu, rs0, 2);
        rs1 += __shfl_xor_sync(0xFFFFFFFFu, rs1, 1);
        rs1 += __shfl_xor_sync(0xFFFFFFFFu, rs1, 2);

        sum0 = sum0 * sc0 + rs0;
        sum1 = sum1 * sc1 + rs1;
        m0 = mn0;
        m1 = mn1;
#pragma unroll
        for (int f = 0; f < 8; f++) {
            o[f][0] *= sc0;
            o[f][1] *= sc0;
            o[f][2] *= sc1;
            o[f][3] *= sc1;
        }

        // PV: P split fp16 x V single fp16 (2 products)
#pragma unroll
        for (int ks = 0; ks < 4; ks++) {
            uint32_t ph[4], pl[4];
            splith2(sf[2 * ks][0],     sf[2 * ks][1],     ph[0], pl[0]);
            splith2(sf[2 * ks][2],     sf[2 * ks][3],     ph[1], pl[1]);
            splith2(sf[2 * ks + 1][0], sf[2 * ks + 1][1], ph[2], pl[2]);
            splith2(sf[2 * ks + 1][2], sf[2 * ks + 1][3], ph[3], pl[3]);
#pragma unroll
            for (int f = 0; f < 8; f++) {
                const int nrow = f * 8 + lr;
                const int kc   = ks * 16 + kp;
                uint32_t vf[2];
                vf[0] = *(const uint32_t*)(sV + nrow * SKT + kc);
                vf[1] = *(const uint32_t*)(sV + nrow * SKT + kc + 8);
                MMA16816H(o[f], ph, vf);
                MMA16816H(o[f], pl, vf);
            }
        }
        __syncthreads();
    }

    // epilogue: normalize, emit fp16 for output projection
    const float inv0 = 1.0f / sum0;
    const float inv1 = 1.0f / sum1;
    const int b = bh >> 4;
    const int h = bh & (H_ - 1);
#pragma unroll
    for (int f = 0; f < 8; f++) {
        const int d = f * 8 + kp;
        const size_t i0 = ((size_t)(b * L_ + rowa)) * D_ + h * HD_ + d;
        const size_t i1 = ((size_t)(b * L_ + rowa + 8)) * D_ + h * HD_ + d;
        *(uint32_t*)&g_oh[i0] = pack_h2(o[f][0] * inv0, o[f][1] * inv0);
        *(uint32_t*)&g_oh[i1] = pack_h2(o[f][2] * inv1, o[f][3] * inv1);
    }
}

// ---------------------------------------------------------------------------
extern "C" void kernel_launch(void* const* d_in, const int* in_sizes, int n_in,
                              void* d_out, int out_size)
{
    const float* x    = (const float*)d_in[0];
    const float* cosT = (const float*)d_in[1];
    const float* sinT = (const float*)d_in[2];
    const float* Wq   = (const float*)d_in[3];
    const float* Wk   = (const float*)d_in[4];
    const float* Wv   = (const float*)d_in[5];
    const float* Wo   = (const float*)d_in[6];
    float* out        = (float*)d_out;

    cudaFuncSetAttribute(gemm_mma<0>, cudaFuncAttributeMaxDynamicSharedMemorySize, SMEM_GEMM);
    cudaFuncSetAttribute(gemm_mma<1>, cudaFuncAttributeMaxDynamicSharedMemorySize, SMEM_GEMM);

    __half *xh, *whi, *wlo, *oh;
    cudaGetSymbolAddress((void**)&xh,  g_xh);
    cudaGetSymbolAddress((void**)&whi, g_whi);
    cudaGetSymbolAddress((void**)&wlo, g_wlo);
    cudaGetSymbolAddress((void**)&oh,  g_oh);

    // 1) convert x to fp16; split all W's (one launch)
    convert_kernel<<<(M_ * K_) / 1024, 256>>>(x, xh);
    splitw_kernel<<<dim3((K_ * K_) / 1024, 4), 256>>>(Wq, Wk, Wv, Wo, whi, wlo);

    // 2) QKV projection + fused RoPE / V-transpose epilogue
    gemm_mma<0><<<dim3(D_ / 128, M_ / 128, 3), 256, SMEM_GEMM>>>(
        xh, whi, wlo, cosT, sinT, nullptr);

    // 3) Flash attention (fp16, 2-product)
    attn_mma_kernel<<<dim3(B_ * H_, L_ / 64), 128>>>();

    // 4) Output projection
    gemm_mma<1><<<dim3(D_ / 128, M_ / 128, 1), 256, SMEM_GEMM>>>(
        oh, whi, wlo, nullptr, nullptr, out);
}

// round 10
// speedup vs baseline: 7.5983x; 1.3696x over previous
#include <cuda_runtime.h>
#include <cuda_fp16.h>
#include <math.h>
#include <stdint.h>

// Problem constants
constexpr int B_   = 2;
constexpr int L_   = 2048;
constexpr int D_   = 1024;
constexpr int H_   = 16;
constexpr int HD_  = 64;
constexpr int WIN_ = 256;
constexpr int M_   = B_ * L_;   // 4096 rows
constexpr int K_   = D_;        // 1024 reduction dim

// Scratch (allocation-free: __device__ globals)
__device__ float  g_q  [(size_t)B_ * H_ * L_ * HD_];   // q fp32 [b,h,l,d], roped
__device__ __half g_kh [(size_t)B_ * H_ * L_ * HD_];   // k fp16 [b,h,l,d], roped
__device__ __half g_vth[(size_t)B_ * H_ * HD_ * L_];   // v fp16 transposed [b,h,d,l]

__device__ __half g_xh [(size_t)M_ * K_];
__device__ __half g_wh [(size_t)4 * K_ * K_];          // Wq,Wk,Wv,Wo fp16
__device__ __half g_oh [(size_t)M_ * K_];              // attn out fp16

// fp16 m16n8k16 mma (baseline PTX, works on plain sm_103 target)
#define MMA16816H(d, a, b) \
    asm volatile("mma.sync.aligned.m16n8k16.row.col.f32.f16.f16.f32 " \
        "{%0,%1,%2,%3}, {%4,%5,%6,%7}, {%8,%9}, {%0,%1,%2,%3};" \
        : "+f"((d)[0]), "+f"((d)[1]), "+f"((d)[2]), "+f"((d)[3]) \
        : "r"((a)[0]), "r"((a)[1]), "r"((a)[2]), "r"((a)[3]), \
          "r"((b)[0]), "r"((b)[1]))

#define LDSM_X4(r0, r1, r2, r3, addr) \
    asm volatile("ldmatrix.sync.aligned.m8n8.x4.shared.b16 {%0,%1,%2,%3}, [%4];" \
        : "=r"(r0), "=r"(r1), "=r"(r2), "=r"(r3) : "r"(addr))

#define CP_ASYNC16(smaddr, gptr) \
    asm volatile("cp.async.cg.shared.global [%0], [%1], 16;" :: "r"(smaddr), "l"(gptr))
#define CP_COMMIT() asm volatile("cp.async.commit_group;" ::: "memory")
#define CP_WAIT(n)  asm volatile("cp.async.wait_group %0;" :: "n"(n) : "memory")

__device__ __forceinline__ uint32_t smem_u32(const void* p) {
    uint32_t a;
    asm("{ .reg .u64 t; cvta.to.shared.u64 t, %1; cvt.u32.u64 %0, t; }" : "=r"(a) : "l"(p));
    return a;
}
__device__ __forceinline__ uint32_t pack_h2(float a, float b) {
    __half2 h = __floats2half2_rn(a, b);
    return *(uint32_t*)&h;
}
__device__ __forceinline__ void splith2(float a, float b, uint32_t& hi, uint32_t& lo) {
    __half ha = __float2half_rn(a), hb = __float2half_rn(b);
    hi = (uint32_t)__half_as_ushort(ha) | ((uint32_t)__half_as_ushort(hb) << 16);
    lo = pack_h2(a - __half2float(ha), b - __half2float(hb));
}

// ===========================================================================
// convert x: fp32 -> fp16
// ===========================================================================
__global__ __launch_bounds__(256) void convert_kernel(
    const float* __restrict__ src, __half* __restrict__ dst)
{
    int i = (blockIdx.x * 256 + threadIdx.x) * 4;
    float4 v = *(const float4*)(src + i);
    uint2 o;
    o.x = pack_h2(v.x, v.y);
    o.y = pack_h2(v.z, v.w);
    *(uint2*)(dst + i) = o;
}

// convert all 4 weight matrices: fp32 -> fp16 (single). grid.y = W index
__global__ __launch_bounds__(256) void convertw_kernel(
    const float* __restrict__ W0, const float* __restrict__ W1,
    const float* __restrict__ W2, const float* __restrict__ W3,
    __half* __restrict__ dst)
{
    const int z = blockIdx.y;
    const float* src = (z == 0) ? W0 : (z == 1) ? W1 : (z == 2) ? W2 : W3;
    const size_t off = (size_t)z * K_ * K_;
    int i = (blockIdx.x * 256 + threadIdx.x) * 4;
    float4 v = *(const float4*)(src + i);
    uint2 o;
    o.x = pack_h2(v.x, v.y);
    o.y = pack_h2(v.z, v.w);
    *(uint2*)(dst + off + i) = o;
}

// ===========================================================================
// HMMA fp16 GEMM (single product): C[m,n] = sum_k Ah[m,k]*Wh[n,k]
// Tile BM=BN=128, BK=32, 256 threads, 2 CTAs/SM, 3-stage cp.async pipeline.
// MODE 0: z selects Wq/Wk/Wv; epilogue fuses RoPE (q,k) and V-transpose.
// MODE 1: W slot 3 (Wo), plain [M,D] fp32 epilogue to Cout.
// ===========================================================================
constexpr int MAT_B    = 128 * 40 * 2;             // 10240 bytes per matrix
constexpr int OFF_AH   = 0;
constexpr int OFF_WH   = MAT_B;
constexpr int STAGE_B  = 2 * MAT_B;                // 20480
constexpr int SMEM_GEMM = 3 * STAGE_B;             // 61440
constexpr int NCH      = K_ / 32;                  // 32

template <int MODE>
__global__ __launch_bounds__(256, 2) void gemm_mma(
    const __half* __restrict__ Ah,
    const __half* __restrict__ WhAll,
    const float* __restrict__ cosT,
    const float* __restrict__ sinT,
    float* __restrict__ Cout)
{
    extern __shared__ char dsm[];
    const uint32_t sb = smem_u32(dsm);

    const int tid    = threadIdx.x;
    const int wid    = tid >> 5;
    const int lane   = tid & 31;
    const int warp_m = wid & 1;
    const int warp_n = wid >> 1;
    const int m0     = blockIdx.y * 128;
    const int n0     = blockIdx.x * 128;
    const int z      = (MODE == 0) ? blockIdx.z : 3;

    const __half* Wh = WhAll + (size_t)z * K_ * K_;

    const int grow = tid >> 2;
    const int gseg = (tid & 3) * 8;
    const uint32_t cst0 = (uint32_t)grow * 80 + (uint32_t)(tid & 3) * 16;
    const uint32_t cst1 = cst0 + 64 * 80;

    const int lm = lane & 7;
    const uint32_t a_off = (uint32_t)(warp_m * 64 + lm + ((lane >> 3) & 1) * 8) * 80
                         + (uint32_t)((lane >> 4) & 1) * 16;
    const uint32_t b_off = (uint32_t)(warp_n * 32 + lm + ((lane >> 4) & 1) * 8) * 80
                         + (uint32_t)((lane >> 3) & 1) * 16;

    float acc[4][4][4];
#pragma unroll
    for (int i = 0; i < 4; i++)
#pragma unroll
        for (int j = 0; j < 4; j++)
#pragma unroll
            for (int r = 0; r < 4; r++) acc[i][j][r] = 0.0f;

    auto load_stage = [&](int c, int s) {
        const uint32_t base = sb + (uint32_t)s * STAGE_B;
        const int kt0 = c * 32;
        size_t ao0 = (size_t)(m0 + grow) * K_ + kt0 + gseg;
        size_t wo0 = (size_t)(n0 + grow) * K_ + kt0 + gseg;
        size_t ao1 = ao0 + (size_t)64 * K_;
        size_t wo1 = wo0 + (size_t)64 * K_;
        CP_ASYNC16(base + OFF_AH + cst0, Ah + ao0);
        CP_ASYNC16(base + OFF_WH + cst0, Wh + wo0);
        CP_ASYNC16(base + OFF_AH + cst1, Ah + ao1);
        CP_ASYNC16(base + OFF_WH + cst1, Wh + wo1);
        CP_COMMIT();
    };

    load_stage(0, 0);
    load_stage(1, 1);

    int sc = 0, sp = 2;
    for (int c = 0; c < NCH; c++) {
        if (c + 2 < NCH) {
            load_stage(c + 2, sp);
            sp = (sp == 2) ? 0 : sp + 1;
            CP_WAIT(2);
        } else if (c + 1 < NCH) {
            CP_WAIT(1);
        } else {
            CP_WAIT(0);
        }
        __syncthreads();

        const uint32_t base = sb + (uint32_t)sc * STAGE_B;
        sc = (sc == 2) ? 0 : sc + 1;

#pragma unroll
        for (int ks = 0; ks < 2; ks++) {
            const uint32_t kadd = (uint32_t)ks * 32;
            uint32_t bh[4][2];
#pragma unroll
            for (int jp = 0; jp < 4; jp += 2) {
                const uint32_t badd = b_off + (uint32_t)jp * 8 * 80 + kadd;
                LDSM_X4(bh[jp][0], bh[jp][1], bh[jp + 1][0], bh[jp + 1][1],
                        base + OFF_WH + badd);
            }
#pragma unroll
            for (int i = 0; i < 4; i++) {
                const uint32_t aadd = a_off + (uint32_t)i * 16 * 80 + kadd;
                uint32_t ah[4];
                LDSM_X4(ah[0], ah[1], ah[2], ah[3], base + OFF_AH + aadd);
#pragma unroll
                for (int j = 0; j < 4; j++) MMA16816H(acc[i][j], ah, bh[j]);
            }
        }
        __syncthreads();
    }

    const int lr = lane >> 2;
    const int lc = (lane & 3) * 2;

    if (MODE == 0) {
        // fused epilogue: stage 16x128 tiles in smem, apply RoPE / transpose
        float* T = (float*)dsm;                 // [2][16][132] fp32
        const int wgrp = tid >> 7;
        const int wrow = (tid >> 3) & 15;
        const int wc0  = (tid & 7) * 16;
        const int vc   = tid & 127;

#pragma unroll
        for (int i = 0; i < 4; i++) {
            __syncthreads();
            {
                float* Tg = T + warp_m * (16 * 132);
#pragma unroll
                for (int rr = 0; rr < 2; rr++) {
                    int row = lr + rr * 8;
#pragma unroll
                    for (int j = 0; j < 4; j++) {
                        int col = warp_n * 32 + j * 8 + lc;
                        Tg[row * 132 + col]     = acc[i][j][rr * 2 + 0];
                        Tg[row * 132 + col + 1] = acc[i][j][rr * 2 + 1];
                    }
                }
            }
            __syncthreads();

            if (blockIdx.z == 2) {
                // V: transpose write, fp16 g_vth[(b*H+h)*HD+d][l]
                const float* Tv = T + wgrp * (16 * 132);
                int n = n0 + vc, h = n >> 6, d = n & 63;
                int mbase = m0 + wgrp * 64 + i * 16;
                int b = mbase >> 11, l0i = mbase & (L_ - 1);
                __half tmp[16];
#pragma unroll
                for (int r = 0; r < 16; r++)
                    tmp[r] = __float2half_rn(Tv[r * 132 + vc]);
                size_t dst = (((size_t)(b * H_ + h)) * HD_ + d) * L_ + l0i;
                *(uint4*)&g_vth[dst]     = *(uint4*)tmp;
                *(uint4*)&g_vth[dst + 8] = *(uint4*)(tmp + 8);
            } else {
                const float* Tq = T + wgrp * (16 * 132);
                int m = m0 + wgrp * 64 + i * 16 + wrow;
                int b = m >> 11, l = m & (L_ - 1);
                const float* crow = cosT + l * HD_;
                const float* srow = sinT + l * HD_;
                if (blockIdx.z == 0) {
#pragma unroll
                    for (int c4 = 0; c4 < 16; c4 += 4) {
                        int c = wc0 + c4;
                        float vv[4];
#pragma unroll
                        for (int e = 0; e < 4; e++) {
                            int cc = c + e, d = cc & 63;
                            float a  = Tq[wrow * 132 + cc];
                            float ap = Tq[wrow * 132 + (cc ^ 32)];
                            vv[e] = (d < 32) ? a * crow[d] - ap * srow[d]
                                             : a * crow[d] + ap * srow[d];
                        }
                        int n = n0 + c, h = n >> 6, d = n & 63;
                        *(float4*)&g_q[(((size_t)(b * H_ + h)) * L_ + l) * HD_ + d]
                            = *(float4*)vv;
                    }
                } else {
#pragma unroll
                    for (int c8 = 0; c8 < 16; c8 += 8) {
                        int c = wc0 + c8;
                        __half tmp[8];
#pragma unroll
                        for (int e = 0; e < 8; e++) {
                            int cc = c + e, d = cc & 63;
                            float a  = Tq[wrow * 132 + cc];
                            float ap = Tq[wrow * 132 + (cc ^ 32)];
                            float r = (d < 32) ? a * crow[d] - ap * srow[d]
                                               : a * crow[d] + ap * srow[d];
                            tmp[e] = __float2half_rn(r);
                        }
                        int n = n0 + c, h = n >> 6, d = n & 63;
                        *(uint4*)&g_kh[(((size_t)(b * H_ + h)) * L_ + l) * HD_ + d]
                            = *(uint4*)tmp;
                    }
                }
            }
        }
    } else {
#pragma unroll
        for (int i = 0; i < 4; i++) {
            int mr = m0 + warp_m * 64 + i * 16 + lr;
#pragma unroll
            for (int rr = 0; rr < 2; rr++) {
                int m = mr + rr * 8;
#pragma unroll
                for (int j = 0; j < 4; j++) {
                    int n = n0 + warp_n * 32 + j * 8 + lc;
                    float2 v = make_float2(acc[i][j][rr * 2 + 0], acc[i][j][rr * 2 + 1]);
                    *(float2*)&Cout[(size_t)m * D_ + n] = v;
                }
            }
        }
    }
}

// ===========================================================================
// Flash attention, fp16 2-product form (unchanged from R9, passing).
// ===========================================================================
constexpr int SKT = 72;

__global__ __launch_bounds__(128) void attn_mma_kernel()
{
    __shared__ __half sK[64 * SKT], sV[64 * SKT];

    const int tid  = threadIdx.x;
    const int wid  = tid >> 5;
    const int lane = tid & 31;
    const int lr   = lane >> 2;
    const int kp   = (lane & 3) * 2;

    const int bh = blockIdx.x;
    const int q0 = blockIdx.y * 64;

    const float*  qb  = g_q   + ((size_t)bh * L_ + q0) * HD_;
    const __half* kb  = g_kh  + (size_t)bh * L_ * HD_;
    const __half* vtb = g_vth + (size_t)bh * HD_ * L_;

    uint32_t qh[4][4], ql[4][4];
#pragma unroll
    for (int ks = 0; ks < 4; ks++) {
#pragma unroll
        for (int e = 0; e < 4; e++) {
            int row  = wid * 16 + lr + (e & 1) * 8;
            int kcol = ks * 16 + kp + (e >= 2 ? 8 : 0);
            float2 v = *(const float2*)(qb + (size_t)row * HD_ + kcol);
            splith2(v.x, v.y, qh[ks][e], ql[ks][e]);
        }
    }

    float o[8][4];
#pragma unroll
    for (int f = 0; f < 8; f++)
#pragma unroll
        for (int e = 0; e < 4; e++) o[f][e] = 0.0f;
    float m0 = -1e30f, m1 = -1e30f, sum0 = 0.0f, sum1 = 0.0f;

    const int rowa = q0 + wid * 16 + lr;
    const int wmin = q0 + wid * 16;
    const int wmax = wmin + 15;
    const int j0s  = (q0 - WIN_ > 0) ? (q0 - WIN_) : 0;

    for (int j0 = j0s; j0 <= q0; j0 += 64) {
        {
            const int r  = tid >> 1;
            const int cb = (tid & 1) * 32;
            const uint4* ks4 = (const uint4*)(kb  + (size_t)(j0 + r) * HD_ + cb);
            const uint4* vs4 = (const uint4*)(vtb + (size_t)r * L_ + j0 + cb);
            uint4* kd4 = (uint4*)(sK + r * SKT + cb);
            uint4* vd4 = (uint4*)(sV + r * SKT + cb);
#pragma unroll
            for (int it = 0; it < 4; it++) {
                kd4[it] = ks4[it];
                vd4[it] = vs4[it];
            }
        }
        __syncthreads();

        float sf[8][4];
#pragma unroll
        for (int f = 0; f < 8; f++)
#pragma unroll
            for (int e = 0; e < 4; e++) sf[f][e] = 0.0f;

#pragma unroll
        for (int ks = 0; ks < 4; ks++) {
#pragma unroll
            for (int f = 0; f < 8; f++) {
                const int nrow = f * 8 + lr;
                const int kc   = ks * 16 + kp;
                uint32_t kf[2];
                kf[0] = *(const uint32_t*)(sK + nrow * SKT + kc);
                kf[1] = *(const uint32_t*)(sK + nrow * SKT + kc + 8);
                MMA16816H(sf[f], qh[ks], kf);
                MMA16816H(sf[f], ql[ks], kf);
            }
        }

        const bool full = (j0 + 63 <= wmin) && (j0 >= wmax - WIN_);
        if (full) {
#pragma unroll
            for (int f = 0; f < 8; f++)
#pragma unroll
                for (int e = 0; e < 4; e++) sf[f][e] *= 0.125f;
        } else {
#pragma unroll
            for (int f = 0; f < 8; f++) {
#pragma unroll
                for (int e = 0; e < 4; e++) {
                    const int col = j0 + f * 8 + kp + (e & 1);
                    const int row = rowa + (e >= 2 ? 8 : 0);
                    const bool ok = (col <= row) && (col >= row - WIN_);
                    sf[f][e] = ok ? sf[f][e] * 0.125f : -1e30f;
                }
            }
        }

        float rm0 = -1e30f, rm1 = -1e30f;
#pragma unroll
        for (int f = 0; f < 8; f++) {
            rm0 = fmaxf(rm0, fmaxf(sf[f][0], sf[f][1]));
            rm1 = fmaxf(rm1, fmaxf(sf[f][2], sf[f][3]));
        }
        rm0 = fmaxf(rm0, __shfl_xor_sync(0xFFFFFFFFu, rm0, 1));
        rm0 = fmaxf(rm0, __shfl_xor_sync(0xFFFFFFFFu, rm0, 2));
        rm1 = fmaxf(rm1, __shfl_xor_sync(0xFFFFFFFFu, rm1, 1));
        rm1 = fmaxf(rm1, __shfl_xor_sync(0xFFFFFFFFu, rm1, 2));

        const float mn0 = fmaxf(m0, rm0);
        const float mn1 = fmaxf(m1, rm1);
        const float sc0 = __expf(m0 - mn0);
        const float sc1 = __expf(m1 - mn1);

        float rs0 = 0.0f, rs1 = 0.0f;
#pragma unroll
        for (int f = 0; f < 8; f++) {
            sf[f][0] = __expf(sf[f][0] - mn0);
            sf[f][1] = __expf(sf[f][1] - mn0);
            sf[f][2] = __expf(sf[f][2] - mn1);
            sf[f][3] = __expf(sf[f][3] - mn1);
            rs0 += sf[f][0] + sf[f][1];
            rs1 += sf[f][2] + sf[f][3];
        }
        rs0 += __shfl_xor_sync(0xFFFFFFFFu, rs0, 1);
        rs0 += __shfl_xor_sync(0xFFFFFFFFu, rs0, 2);
        rs1 += __shfl_xor_sync(0xFFFFFFFFu, rs1, 1);
        rs1 += __shfl_xor_sync(0xFFFFFFFFu, rs1, 2);

        sum0 = sum0 * sc0 + rs0;
        sum1 = sum1 * sc1 + rs1;
        m0 = mn0;
        m1 = mn1;
#pragma unroll
        for (int f = 0; f < 8; f++) {
            o[f][0] *= sc0;
            o[f][1] *= sc0;
            o[f][2] *= sc1;
            o[f][3] *= sc1;
        }

#pragma unroll
        for (int ks = 0; ks < 4; ks++) {
            uint32_t ph[4], pl[4];
            splith2(sf[2 * ks][0],     sf[2 * ks][1],     ph[0], pl[0]);
            splith2(sf[2 * ks][2],     sf[2 * ks][3],     ph[1], pl[1]);
            splith2(sf[2 * ks + 1][0], sf[2 * ks + 1][1], ph[2], pl[2]);
            splith2(sf[2 * ks + 1][2], sf[2 * ks + 1][3], ph[3], pl[3]);
#pragma unroll
            for (int f = 0; f < 8; f++) {
                const int nrow = f * 8 + lr;
                const int kc   = ks * 16 + kp;
                uint32_t vf[2];
                vf[0] = *(const uint32_t*)(sV + nrow * SKT + kc);
                vf[1] = *(const uint32_t*)(sV + nrow * SKT + kc + 8);
                MMA16816H(o[f], ph, vf);
                MMA16816H(o[f], pl, vf);
            }
        }
        __syncthreads();
    }

    const float inv0 = 1.0f / sum0;
    const float inv1 = 1.0f / sum1;
    const int b = bh >> 4;
    const int h = bh & (H_ - 1);
#pragma unroll
    for (int f = 0; f < 8; f++) {
        const int d = f * 8 + kp;
        const size_t i0 = ((size_t)(b * L_ + rowa)) * D_ + h * HD_ + d;
        const size_t i1 = ((size_t)(b * L_ + rowa + 8)) * D_ + h * HD_ + d;
        *(uint32_t*)&g_oh[i0] = pack_h2(o[f][0] * inv0, o[f][1] * inv0);
        *(uint32_t*)&g_oh[i1] = pack_h2(o[f][2] * inv1, o[f][3] * inv1);
    }
}

// ---------------------------------------------------------------------------
extern "C" void kernel_launch(void* const* d_in, const int* in_sizes, int n_in,
                              void* d_out, int out_size)
{
    const float* x    = (const float*)d_in[0];
    const float* cosT = (const float*)d_in[1];
    const float* sinT = (const float*)d_in[2];
    const float* Wq   = (const float*)d_in[3];
    const float* Wk   = (const float*)d_in[4];
    const float* Wv   = (const float*)d_in[5];
    const float* Wo   = (const float*)d_in[6];
    float* out        = (float*)d_out;

    cudaFuncSetAttribute(gemm_mma<0>, cudaFuncAttributeMaxDynamicSharedMemorySize, SMEM_GEMM);
    cudaFuncSetAttribute(gemm_mma<1>, cudaFuncAttributeMaxDynamicSharedMemorySize, SMEM_GEMM);

    __half *xh, *wh, *oh;
    cudaGetSymbolAddress((void**)&xh, g_xh);
    cudaGetSymbolAddress((void**)&wh, g_wh);
    cudaGetSymbolAddress((void**)&oh, g_oh);

    // 1) convert x and all W's to fp16
    convert_kernel<<<(M_ * K_) / 1024, 256>>>(x, xh);
    convertw_kernel<<<dim3((K_ * K_) / 1024, 4), 256>>>(Wq, Wk, Wv, Wo, wh);

    // 2) QKV projection + fused RoPE / V-transpose epilogue
    gemm_mma<0><<<dim3(D_ / 128, M_ / 128, 3), 256, SMEM_GEMM>>>(
        xh, wh, cosT, sinT, nullptr);

    // 3) Flash attention (fp16, 2-product)
    attn_mma_kernel<<<dim3(B_ * H_, L_ / 64), 128>>>();

    // 4) Output projection
    gemm_mma<1><<<dim3(D_ / 128, M_ / 128, 1), 256, SMEM_GEMM>>>(
        oh, wh, nullptr, nullptr, out);
}

// round 11
// speedup vs baseline: 8.2519x; 1.0860x over previous
#include <cuda_runtime.h>
#include <cuda_fp16.h>
#include <math.h>
#include <stdint.h>

// Problem constants
constexpr int B_   = 2;
constexpr int L_   = 2048;
constexpr int D_   = 1024;
constexpr int H_   = 16;
constexpr int HD_  = 64;
constexpr int WIN_ = 256;
constexpr int M_   = B_ * L_;   // 4096 rows
constexpr int K_   = D_;        // 1024 reduction dim

// Scratch (allocation-free: __device__ globals)
__device__ __half g_qh [(size_t)B_ * H_ * L_ * HD_];   // q fp16 [b,h,l,d], roped, pre-scaled 1/8
__device__ __half g_kh [(size_t)B_ * H_ * L_ * HD_];   // k fp16 [b,h,l,d], roped
__device__ __half g_vth[(size_t)B_ * H_ * HD_ * L_];   // v fp16 transposed [b,h,d,l]

__device__ __half g_xh [(size_t)M_ * K_];
__device__ __half g_wh [(size_t)4 * K_ * K_];          // Wq,Wk,Wv,Wo fp16
__device__ __half g_oh [(size_t)M_ * K_];              // attn out fp16

// fp16 m16n8k16 mma (baseline PTX, works on plain sm_103 target)
#define MMA16816H(d, a, b) \
    asm volatile("mma.sync.aligned.m16n8k16.row.col.f32.f16.f16.f32 " \
        "{%0,%1,%2,%3}, {%4,%5,%6,%7}, {%8,%9}, {%0,%1,%2,%3};" \
        : "+f"((d)[0]), "+f"((d)[1]), "+f"((d)[2]), "+f"((d)[3]) \
        : "r"((a)[0]), "r"((a)[1]), "r"((a)[2]), "r"((a)[3]), \
          "r"((b)[0]), "r"((b)[1]))

#define LDSM_X4(r0, r1, r2, r3, addr) \
    asm volatile("ldmatrix.sync.aligned.m8n8.x4.shared.b16 {%0,%1,%2,%3}, [%4];" \
        : "=r"(r0), "=r"(r1), "=r"(r2), "=r"(r3) : "r"(addr))

#define CP_ASYNC16(smaddr, gptr) \
    asm volatile("cp.async.cg.shared.global [%0], [%1], 16;" :: "r"(smaddr), "l"(gptr))
#define CP_COMMIT() asm volatile("cp.async.commit_group;" ::: "memory")
#define CP_WAIT(n)  asm volatile("cp.async.wait_group %0;" :: "n"(n) : "memory")

__device__ __forceinline__ uint32_t smem_u32(const void* p) {
    uint32_t a;
    asm("{ .reg .u64 t; cvta.to.shared.u64 t, %1; cvt.u32.u64 %0, t; }" : "=r"(a) : "l"(p));
    return a;
}
__device__ __forceinline__ uint32_t pack_h2(float a, float b) {
    __half2 h = __floats2half2_rn(a, b);
    return *(uint32_t*)&h;
}

// ===========================================================================
// convert x (4 chunks) + all 4 W's to fp16 in ONE launch. grid=(1024, 8).
//   y in [0,4): W_y ; y in [4,8): x chunk y-4. All segments are K_*K_ elems.
// ===========================================================================
__global__ __launch_bounds__(256) void convert_all_kernel(
    const float* __restrict__ x,
    const float* __restrict__ W0, const float* __restrict__ W1,
    const float* __restrict__ W2, const float* __restrict__ W3,
    __half* __restrict__ wh, __half* __restrict__ xh)
{
    const int y = blockIdx.y;
    const float* src;
    __half* dst;
    if (y < 4) {
        src = (y == 0) ? W0 : (y == 1) ? W1 : (y == 2) ? W2 : W3;
        dst = wh + (size_t)y * K_ * K_;
    } else {
        src = x + (size_t)(y - 4) * K_ * K_;
        dst = xh + (size_t)(y - 4) * K_ * K_;
    }
    int i = (blockIdx.x * 256 + threadIdx.x) * 4;
    float4 v = *(const float4*)(src + i);
    uint2 o;
    o.x = pack_h2(v.x, v.y);
    o.y = pack_h2(v.z, v.w);
    *(uint2*)(dst + i) = o;
}

// ===========================================================================
// HMMA fp16 GEMM (single product): C[m,n] = sum_k Ah[m,k]*Wh[n,k]
// Tile BM=BN=128, BK=32, 256 threads, 2 CTAs/SM, 3-stage cp.async pipeline.
// MODE 0: z selects Wq/Wk/Wv; epilogue fuses RoPE (q scaled 1/8, k) and
//         V-transpose, all emitted fp16.
// MODE 1: W slot 3 (Wo), plain [M,D] fp32 epilogue to Cout.
// ===========================================================================
constexpr int MAT_B    = 128 * 40 * 2;             // 10240 bytes per matrix
constexpr int OFF_AH   = 0;
constexpr int OFF_WH   = MAT_B;
constexpr int STAGE_B  = 2 * MAT_B;                // 20480
constexpr int SMEM_GEMM = 3 * STAGE_B;             // 61440
constexpr int NCH      = K_ / 32;                  // 32

template <int MODE>
__global__ __launch_bounds__(256, 2) void gemm_mma(
    const __half* __restrict__ Ah,
    const __half* __restrict__ WhAll,
    const float* __restrict__ cosT,
    const float* __restrict__ sinT,
    float* __restrict__ Cout)
{
    extern __shared__ char dsm[];
    const uint32_t sb = smem_u32(dsm);

    const int tid    = threadIdx.x;
    const int wid    = tid >> 5;
    const int lane   = tid & 31;
    const int warp_m = wid & 1;
    const int warp_n = wid >> 1;
    const int m0     = blockIdx.y * 128;
    const int n0     = blockIdx.x * 128;
    const int z      = (MODE == 0) ? blockIdx.z : 3;

    const __half* Wh = WhAll + (size_t)z * K_ * K_;

    const int grow = tid >> 2;
    const int gseg = (tid & 3) * 8;
    const uint32_t cst0 = (uint32_t)grow * 80 + (uint32_t)(tid & 3) * 16;
    const uint32_t cst1 = cst0 + 64 * 80;

    const int lm = lane & 7;
    const uint32_t a_off = (uint32_t)(warp_m * 64 + lm + ((lane >> 3) & 1) * 8) * 80
                         + (uint32_t)((lane >> 4) & 1) * 16;
    const uint32_t b_off = (uint32_t)(warp_n * 32 + lm + ((lane >> 4) & 1) * 8) * 80
                         + (uint32_t)((lane >> 3) & 1) * 16;

    float acc[4][4][4];
#pragma unroll
    for (int i = 0; i < 4; i++)
#pragma unroll
        for (int j = 0; j < 4; j++)
#pragma unroll
            for (int r = 0; r < 4; r++) acc[i][j][r] = 0.0f;

    auto load_stage = [&](int c, int s) {
        const uint32_t base = sb + (uint32_t)s * STAGE_B;
        const int kt0 = c * 32;
        size_t ao0 = (size_t)(m0 + grow) * K_ + kt0 + gseg;
        size_t wo0 = (size_t)(n0 + grow) * K_ + kt0 + gseg;
        size_t ao1 = ao0 + (size_t)64 * K_;
        size_t wo1 = wo0 + (size_t)64 * K_;
        CP_ASYNC16(base + OFF_AH + cst0, Ah + ao0);
        CP_ASYNC16(base + OFF_WH + cst0, Wh + wo0);
        CP_ASYNC16(base + OFF_AH + cst1, Ah + ao1);
        CP_ASYNC16(base + OFF_WH + cst1, Wh + wo1);
        CP_COMMIT();
    };

    load_stage(0, 0);
    load_stage(1, 1);

    int sc = 0, sp = 2;
    for (int c = 0; c < NCH; c++) {
        if (c + 2 < NCH) {
            load_stage(c + 2, sp);
            sp = (sp == 2) ? 0 : sp + 1;
            CP_WAIT(2);
        } else if (c + 1 < NCH) {
            CP_WAIT(1);
        } else {
            CP_WAIT(0);
        }
        __syncthreads();

        const uint32_t base = sb + (uint32_t)sc * STAGE_B;
        sc = (sc == 2) ? 0 : sc + 1;

#pragma unroll
        for (int ks = 0; ks < 2; ks++) {
            const uint32_t kadd = (uint32_t)ks * 32;
            uint32_t bh[4][2];
#pragma unroll
            for (int jp = 0; jp < 4; jp += 2) {
                const uint32_t badd = b_off + (uint32_t)jp * 8 * 80 + kadd;
                LDSM_X4(bh[jp][0], bh[jp][1], bh[jp + 1][0], bh[jp + 1][1],
                        base + OFF_WH + badd);
            }
#pragma unroll
            for (int i = 0; i < 4; i++) {
                const uint32_t aadd = a_off + (uint32_t)i * 16 * 80 + kadd;
                uint32_t ah[4];
                LDSM_X4(ah[0], ah[1], ah[2], ah[3], base + OFF_AH + aadd);
#pragma unroll
                for (int j = 0; j < 4; j++) MMA16816H(acc[i][j], ah, bh[j]);
            }
        }
        __syncthreads();
    }

    const int lr = lane >> 2;
    const int lc = (lane & 3) * 2;

    if (MODE == 0) {
        // fused epilogue: stage 16x128 tiles in smem, apply RoPE / transpose
        float* T = (float*)dsm;                 // [2][16][132] fp32
        const int wgrp = tid >> 7;
        const int wrow = (tid >> 3) & 15;
        const int wc0  = (tid & 7) * 16;
        const int vc   = tid & 127;

#pragma unroll
        for (int i = 0; i < 4; i++) {
            __syncthreads();
            {
                float* Tg = T + warp_m * (16 * 132);
#pragma unroll
                for (int rr = 0; rr < 2; rr++) {
                    int row = lr + rr * 8;
#pragma unroll
                    for (int j = 0; j < 4; j++) {
                        int col = warp_n * 32 + j * 8 + lc;
                        Tg[row * 132 + col]     = acc[i][j][rr * 2 + 0];
                        Tg[row * 132 + col + 1] = acc[i][j][rr * 2 + 1];
                    }
                }
            }
            __syncthreads();

            if (blockIdx.z == 2) {
                // V: transpose write, fp16 g_vth[(b*H+h)*HD+d][l]
                const float* Tv = T + wgrp * (16 * 132);
                int n = n0 + vc, h = n >> 6, d = n & 63;
                int mbase = m0 + wgrp * 64 + i * 16;
                int b = mbase >> 11, l0i = mbase & (L_ - 1);
                __half tmp[16];
#pragma unroll
                for (int r = 0; r < 16; r++)
                    tmp[r] = __float2half_rn(Tv[r * 132 + vc]);
                size_t dst = (((size_t)(b * H_ + h)) * HD_ + d) * L_ + l0i;
                *(uint4*)&g_vth[dst]     = *(uint4*)tmp;
                *(uint4*)&g_vth[dst + 8] = *(uint4*)(tmp + 8);
            } else {
                // Q / K: rope + fp16 write (q pre-scaled by 1/8)
                const float* Tq = T + wgrp * (16 * 132);
                int m = m0 + wgrp * 64 + i * 16 + wrow;
                int b = m >> 11, l = m & (L_ - 1);
                const float* crow = cosT + l * HD_;
                const float* srow = sinT + l * HD_;
                const float qsc = (blockIdx.z == 0) ? 0.125f : 1.0f;
                __half* dstbuf = (blockIdx.z == 0) ? g_qh : g_kh;
#pragma unroll
                for (int c8 = 0; c8 < 16; c8 += 8) {
                    int c = wc0 + c8;
                    __half tmp[8];
#pragma unroll
                    for (int e = 0; e < 8; e++) {
                        int cc = c + e, d = cc & 63;
                        float a  = Tq[wrow * 132 + cc];
                        float ap = Tq[wrow * 132 + (cc ^ 32)];
                        float r = (d < 32) ? a * crow[d] - ap * srow[d]
                                           : a * crow[d] + ap * srow[d];
                        tmp[e] = __float2half_rn(r * qsc);
                    }
                    int n = n0 + c, h = n >> 6, d = n & 63;
                    *(uint4*)&dstbuf[(((size_t)(b * H_ + h)) * L_ + l) * HD_ + d]
                        = *(uint4*)tmp;
                }
            }
        }
    } else {
#pragma unroll
        for (int i = 0; i < 4; i++) {
            int mr = m0 + warp_m * 64 + i * 16 + lr;
#pragma unroll
            for (int rr = 0; rr < 2; rr++) {
                int m = mr + rr * 8;
#pragma unroll
                for (int j = 0; j < 4; j++) {
                    int n = n0 + warp_n * 32 + j * 8 + lc;
                    float2 v = make_float2(acc[i][j][rr * 2 + 0], acc[i][j][rr * 2 + 1]);
                    *(float2*)&Cout[(size_t)m * D_ + n] = v;
                }
            }
        }
    }
}

// ===========================================================================
// Flash attention, fp16 single-product form.
// Q arrives fp16 roped pre-scaled (direct fragment loads); K, V, P single fp16.
// CTA = 64 queries of one (b,h); 4 warps x 16 rows; key chunks of 64.
// ===========================================================================
constexpr int SKT = 72;

__global__ __launch_bounds__(128) void attn_mma_kernel()
{
    __shared__ __half sK[64 * SKT], sV[64 * SKT];

    const int tid  = threadIdx.x;
    const int wid  = tid >> 5;
    const int lane = tid & 31;
    const int lr   = lane >> 2;
    const int kp   = (lane & 3) * 2;

    const int bh = blockIdx.x;
    const int q0 = blockIdx.y * 64;

    const __half* qb  = g_qh  + ((size_t)bh * L_ + q0) * HD_;
    const __half* kb  = g_kh  + (size_t)bh * L_ * HD_;
    const __half* vtb = g_vth + (size_t)bh * HD_ * L_;

    // Q fragments: direct uint32 loads (fp16 pairs), loaded once
    uint32_t qh[4][4];
#pragma unroll
    for (int ks = 0; ks < 4; ks++) {
#pragma unroll
        for (int e = 0; e < 4; e++) {
            int row  = wid * 16 + lr + (e & 1) * 8;
            int kcol = ks * 16 + kp + (e >= 2 ? 8 : 0);
            qh[ks][e] = *(const uint32_t*)(qb + (size_t)row * HD_ + kcol);
        }
    }

    float o[8][4];
#pragma unroll
    for (int f = 0; f < 8; f++)
#pragma unroll
        for (int e = 0; e < 4; e++) o[f][e] = 0.0f;
    float m0 = -1e30f, m1 = -1e30f, sum0 = 0.0f, sum1 = 0.0f;

    const int rowa = q0 + wid * 16 + lr;
    const int wmin = q0 + wid * 16;
    const int wmax = wmin + 15;
    const int j0s  = (q0 - WIN_ > 0) ? (q0 - WIN_) : 0;

    for (int j0 = j0s; j0 <= q0; j0 += 64) {
        // copy K chunk [64 keys][64 d] and V^T chunk [64 d][64 keys]
        {
            const int r  = tid >> 1;
            const int cb = (tid & 1) * 32;
            const uint4* ks4 = (const uint4*)(kb  + (size_t)(j0 + r) * HD_ + cb);
            const uint4* vs4 = (const uint4*)(vtb + (size_t)r * L_ + j0 + cb);
            uint4* kd4 = (uint4*)(sK + r * SKT + cb);
            uint4* vd4 = (uint4*)(sV + r * SKT + cb);
#pragma unroll
            for (int it = 0; it < 4; it++) {
                kd4[it] = ks4[it];
                vd4[it] = vs4[it];
            }
        }
        __syncthreads();

        // S = Q K^T (single product; scores pre-scaled via q)
        float sf[8][4];
#pragma unroll
        for (int f = 0; f < 8; f++)
#pragma unroll
            for (int e = 0; e < 4; e++) sf[f][e] = 0.0f;

#pragma unroll
        for (int ks = 0; ks < 4; ks++) {
#pragma unroll
            for (int f = 0; f < 8; f++) {
                const int nrow = f * 8 + lr;
                const int kc   = ks * 16 + kp;
                uint32_t kf[2];
                kf[0] = *(const uint32_t*)(sK + nrow * SKT + kc);
                kf[1] = *(const uint32_t*)(sK + nrow * SKT + kc + 8);
                MMA16816H(sf[f], qh[ks], kf);
            }
        }

        // mask (boundary chunks only)
        const bool full = (j0 + 63 <= wmin) && (j0 >= wmax - WIN_);
        if (!full) {
#pragma unroll
            for (int f = 0; f < 8; f++) {
#pragma unroll
                for (int e = 0; e < 4; e++) {
                    const int col = j0 + f * 8 + kp + (e & 1);
                    const int row = rowa + (e >= 2 ? 8 : 0);
                    const bool ok = (col <= row) && (col >= row - WIN_);
                    if (!ok) sf[f][e] = -1e30f;
                }
            }
        }

        // online softmax
        float rm0 = -1e30f, rm1 = -1e30f;
#pragma unroll
        for (int f = 0; f < 8; f++) {
            rm0 = fmaxf(rm0, fmaxf(sf[f][0], sf[f][1]));
            rm1 = fmaxf(rm1, fmaxf(sf[f][2], sf[f][3]));
        }
        rm0 = fmaxf(rm0, __shfl_xor_sync(0xFFFFFFFFu, rm0, 1));
        rm0 = fmaxf(rm0, __shfl_xor_sync(0xFFFFFFFFu, rm0, 2));
        rm1 = fmaxf(rm1, __shfl_xor_sync(0xFFFFFFFFu, rm1, 1));
        rm1 = fmaxf(rm1, __shfl_xor_sync(0xFFFFFFFFu, rm1, 2));

        const float mn0 = fmaxf(m0, rm0);
        const float mn1 = fmaxf(m1, rm1);
        const float sc0 = __expf(m0 - mn0);
        const float sc1 = __expf(m1 - mn1);

        float rs0 = 0.0f, rs1 = 0.0f;
#pragma unroll
        for (int f = 0; f < 8; f++) {
            sf[f][0] = __expf(sf[f][0] - mn0);
            sf[f][1] = __expf(sf[f][1] - mn0);
            sf[f][2] = __expf(sf[f][2] - mn1);
            sf[f][3] = __expf(sf[f][3] - mn1);
            rs0 += sf[f][0] + sf[f][1];
            rs1 += sf[f][2] + sf[f][3];
        }
        rs0 += __shfl_xor_sync(0xFFFFFFFFu, rs0, 1);
        rs0 += __shfl_xor_sync(0xFFFFFFFFu, rs0, 2);
        rs1 += __shfl_xor_sync(0xFFFFFFFFu, rs1, 1);
        rs1 += __shfl_xor_sync(0xFFFFFFFFu, rs1, 2);

        sum0 = sum0 * sc0 + rs0;
        sum1 = sum1 * sc1 + rs1;
        m0 = mn0;
        m1 = mn1;
#pragma unroll
        for (int f = 0; f < 8; f++) {
            o[f][0] *= sc0;
            o[f][1] *= sc0;
            o[f][2] *= sc1;
            o[f][3] *= sc1;
        }

        // PV: P single fp16 x V single fp16
#pragma unroll
        for (int ks = 0; ks < 4; ks++) {
            uint32_t ph[4];
            ph[0] = pack_h2(sf[2 * ks][0],     sf[2 * ks][1]);
            ph[1] = pack_h2(sf[2 * ks][2],     sf[2 * ks][3]);
            ph[2] = pack_h2(sf[2 * ks + 1][0], sf[2 * ks + 1][1]);
            ph[3] = pack_h2(sf[2 * ks + 1][2], sf[2 * ks + 1][3]);
#pragma unroll
            for (int f = 0; f < 8; f++) {
                const int nrow = f * 8 + lr;
                const int kc   = ks * 16 + kp;
                uint32_t vf[2];
                vf[0] = *(const uint32_t*)(sV + nrow * SKT + kc);
                vf[1] = *(const uint32_t*)(sV + nrow * SKT + kc + 8);
                MMA16816H(o[f], ph, vf);
            }
        }
        __syncthreads();
    }

    // epilogue: normalize, emit fp16 for output projection
    const float inv0 = 1.0f / sum0;
    const float inv1 = 1.0f / sum1;
    const int b = bh >> 4;
    const int h = bh & (H_ - 1);
#pragma unroll
    for (int f = 0; f < 8; f++) {
        const int d = f * 8 + kp;
        const size_t i0 = ((size_t)(b * L_ + rowa)) * D_ + h * HD_ + d;
        const size_t i1 = ((size_t)(b * L_ + rowa + 8)) * D_ + h * HD_ + d;
        *(uint32_t*)&g_oh[i0] = pack_h2(o[f][0] * inv0, o[f][1] * inv0);
        *(uint32_t*)&g_oh[i1] = pack_h2(o[f][2] * inv1, o[f][3] * inv1);
    }
}

// ---------------------------------------------------------------------------
extern "C" void kernel_launch(void* const* d_in, const int* in_sizes, int n_in,
                              void* d_out, int out_size)
{
    const float* x    = (const float*)d_in[0];
    const float* cosT = (const float*)d_in[1];
    const float* sinT = (const float*)d_in[2];
    const float* Wq   = (const float*)d_in[3];
    const float* Wk   = (const float*)d_in[4];
    const float* Wv   = (const float*)d_in[5];
    const float* Wo   = (const float*)d_in[6];
    float* out        = (float*)d_out;

    cudaFuncSetAttribute(gemm_mma<0>, cudaFuncAttributeMaxDynamicSharedMemorySize, SMEM_GEMM);
    cudaFuncSetAttribute(gemm_mma<1>, cudaFuncAttributeMaxDynamicSharedMemorySize, SMEM_GEMM);

    __half *xh, *wh, *oh;
    cudaGetSymbolAddress((void**)&xh, g_xh);
    cudaGetSymbolAddress((void**)&wh, g_wh);
    cudaGetSymbolAddress((void**)&oh, g_oh);

    // 1) convert x and all W's to fp16 (one launch)
    convert_all_kernel<<<dim3((K_ * K_) / 1024, 8), 256>>>(x, Wq, Wk, Wv, Wo, wh, xh);

    // 2) QKV projection + fused RoPE / V-transpose epilogue (all fp16 out)
    gemm_mma<0><<<dim3(D_ / 128, M_ / 128, 3), 256, SMEM_GEMM>>>(
        xh, wh, cosT, sinT, nullptr);

    // 3) Flash attention (fp16, single-product)
    attn_mma_kernel<<<dim3(B_ * H_, L_ / 64), 128>>>();

    // 4) Output projection
    gemm_mma<1><<<dim3(D_ / 128, M_ / 128, 1), 256, SMEM_GEMM>>>(
        oh, wh, nullptr, nullptr, out);
}

// round 12
// speedup vs baseline: 9.2573x; 1.1218x over previous
#include <cuda_runtime.h>
#include <cuda_fp16.h>
#include <math.h>
#include <stdint.h>

// Problem constants
constexpr int B_   = 2;
constexpr int L_   = 2048;
constexpr int D_   = 1024;
constexpr int H_   = 16;
constexpr int HD_  = 64;
constexpr int WIN_ = 256;
constexpr int M_   = B_ * L_;   // 4096 rows
constexpr int K_   = D_;        // 1024 reduction dim

// Scratch (allocation-free: __device__ globals)
__device__ __half g_qh [(size_t)B_ * H_ * L_ * HD_];   // q fp16, roped, pre-scaled 1/8
__device__ __half g_kh [(size_t)B_ * H_ * L_ * HD_];   // k fp16, roped
__device__ __half g_vth[(size_t)B_ * H_ * HD_ * L_];   // v fp16 transposed [b,h,d,l]

__device__ __half g_xh [(size_t)M_ * K_];
__device__ __half g_wh [(size_t)4 * K_ * K_];          // Wq,Wk,Wv,Wo fp16
__device__ __half g_oh [(size_t)M_ * K_];              // attn out fp16

// fp16 m16n8k16 mma (baseline PTX, works on plain sm_103 target)
#define MMA16816H(d, a, b) \
    asm volatile("mma.sync.aligned.m16n8k16.row.col.f32.f16.f16.f32 " \
        "{%0,%1,%2,%3}, {%4,%5,%6,%7}, {%8,%9}, {%0,%1,%2,%3};" \
        : "+f"((d)[0]), "+f"((d)[1]), "+f"((d)[2]), "+f"((d)[3]) \
        : "r"((a)[0]), "r"((a)[1]), "r"((a)[2]), "r"((a)[3]), \
          "r"((b)[0]), "r"((b)[1]))

#define LDSM_X4(r0, r1, r2, r3, addr) \
    asm volatile("ldmatrix.sync.aligned.m8n8.x4.shared.b16 {%0,%1,%2,%3}, [%4];" \
        : "=r"(r0), "=r"(r1), "=r"(r2), "=r"(r3) : "r"(addr))

#define CP_ASYNC16(smaddr, gptr) \
    asm volatile("cp.async.cg.shared.global [%0], [%1], 16;" :: "r"(smaddr), "l"(gptr))
#define CP_COMMIT() asm volatile("cp.async.commit_group;" ::: "memory")
#define CP_WAIT(n)  asm volatile("cp.async.wait_group %0;" :: "n"(n) : "memory")

__device__ __forceinline__ uint32_t smem_u32(const void* p) {
    uint32_t a;
    asm("{ .reg .u64 t; cvta.to.shared.u64 t, %1; cvt.u32.u64 %0, t; }" : "=r"(a) : "l"(p));
    return a;
}
__device__ __forceinline__ uint32_t pack_h2(float a, float b) {
    __half2 h = __floats2half2_rn(a, b);
    return *(uint32_t*)&h;
}

// ===========================================================================
// convert x (4 chunks) + all 4 W's to fp16 in ONE launch. grid=(1024, 8).
// ===========================================================================
__global__ __launch_bounds__(256) void convert_all_kernel(
    const float* __restrict__ x,
    const float* __restrict__ W0, const float* __restrict__ W1,
    const float* __restrict__ W2, const float* __restrict__ W3,
    __half* __restrict__ wh, __half* __restrict__ xh)
{
    const int y = blockIdx.y;
    const float* src;
    __half* dst;
    if (y < 4) {
        src = (y == 0) ? W0 : (y == 1) ? W1 : (y == 2) ? W2 : W3;
        dst = wh + (size_t)y * K_ * K_;
    } else {
        src = x + (size_t)(y - 4) * K_ * K_;
        dst = xh + (size_t)(y - 4) * K_ * K_;
    }
    int i = (blockIdx.x * 256 + threadIdx.x) * 4;
    float4 v = *(const float4*)(src + i);
    uint2 o;
    o.x = pack_h2(v.x, v.y);
    o.y = pack_h2(v.z, v.w);
    *(uint2*)(dst + i) = o;
}

// ===========================================================================
// HMMA fp16 GEMM: C[m,n] = sum_k Ah[m,k]*Wh[n,k]
// Tile BM=BN=128, BK=64, 256 threads, 2 CTAs/SM, 3-stage cp.async pipeline,
// ONE barrier per chunk (wait -> sync -> prefetch -> compute).
// MODE 0: z selects Wq/Wk/Wv; epilogue fuses RoPE (q scaled 1/8, k) and
//         V-transpose, all emitted fp16.
// MODE 1: W slot 3 (Wo), plain [M,D] fp32 epilogue to Cout.
// ===========================================================================
constexpr int RSTR     = 144;                      // smem row stride bytes (64 fp16 + 8 pad)
constexpr int MAT_B    = 128 * RSTR;               // 18432 bytes per matrix
constexpr int OFF_AH   = 0;
constexpr int OFF_WH   = MAT_B;
constexpr int STAGE_B  = 2 * MAT_B;                // 36864
constexpr int SMEM_GEMM = 3 * STAGE_B;             // 110592
constexpr int NCH      = K_ / 64;                  // 16

template <int MODE>
__global__ __launch_bounds__(256, 2) void gemm_mma(
    const __half* __restrict__ Ah,
    const __half* __restrict__ WhAll,
    const float* __restrict__ cosT,
    const float* __restrict__ sinT,
    float* __restrict__ Cout)
{
    extern __shared__ char dsm[];
    const uint32_t sb = smem_u32(dsm);

    const int tid    = threadIdx.x;
    const int wid    = tid >> 5;
    const int lane   = tid & 31;
    const int warp_m = wid & 1;
    const int warp_n = wid >> 1;
    const int m0     = blockIdx.y * 128;
    const int n0     = blockIdx.x * 128;
    const int z      = (MODE == 0) ? blockIdx.z : 3;

    const __half* Wh = WhAll + (size_t)z * K_ * K_;

    // cp.async geometry: 1024 x 16B per matrix; thread does 4 rows per matrix
    const int crow = tid >> 3;                       // [0,32)
    const int cseg = tid & 7;                        // 16B segment
    const uint32_t cso = (uint32_t)crow * RSTR + (uint32_t)cseg * 16;

    // ldmatrix per-lane byte offsets
    const int lm = lane & 7;
    const uint32_t a_off = (uint32_t)(warp_m * 64 + lm + ((lane >> 3) & 1) * 8) * RSTR
                         + (uint32_t)((lane >> 4) & 1) * 16;
    const uint32_t b_off = (uint32_t)(warp_n * 32 + lm + ((lane >> 4) & 1) * 8) * RSTR
                         + (uint32_t)((lane >> 3) & 1) * 16;

    float acc[4][4][4];
#pragma unroll
    for (int i = 0; i < 4; i++)
#pragma unroll
        for (int j = 0; j < 4; j++)
#pragma unroll
            for (int r = 0; r < 4; r++) acc[i][j][r] = 0.0f;

    auto load_stage = [&](int c, int s) {
        const uint32_t base = sb + (uint32_t)s * STAGE_B;
        const int kt0 = c * 64;
#pragma unroll
        for (int t = 0; t < 4; t++) {
            const int row = crow + 32 * t;
            size_t ao = (size_t)(m0 + row) * K_ + kt0 + cseg * 8;
            size_t wo = (size_t)(n0 + row) * K_ + kt0 + cseg * 8;
            const uint32_t so = cso + (uint32_t)(32 * t) * RSTR;
            CP_ASYNC16(base + OFF_AH + so, Ah + ao);
            CP_ASYNC16(base + OFF_WH + so, Wh + wo);
        }
        CP_COMMIT();
    };

    load_stage(0, 0);
    load_stage(1, 1);

    int sc = 0, sp = 2;
    for (int c = 0; c < NCH; c++) {
        if (c == NCH - 1) { CP_WAIT(0); } else { CP_WAIT(1); }
        __syncthreads();
        if (c + 2 < NCH) {
            load_stage(c + 2, sp);
            sp = (sp == 2) ? 0 : sp + 1;
        }

        const uint32_t base = sb + (uint32_t)sc * STAGE_B;
        sc = (sc == 2) ? 0 : sc + 1;

#pragma unroll
        for (int ks = 0; ks < 4; ks++) {
            const uint32_t kadd = (uint32_t)ks * 32;
            uint32_t bh[4][2];
#pragma unroll
            for (int jp = 0; jp < 4; jp += 2) {
                const uint32_t badd = b_off + (uint32_t)jp * 8 * RSTR + kadd;
                LDSM_X4(bh[jp][0], bh[jp][1], bh[jp + 1][0], bh[jp + 1][1],
                        base + OFF_WH + badd);
            }
#pragma unroll
            for (int i = 0; i < 4; i++) {
                const uint32_t aadd = a_off + (uint32_t)i * 16 * RSTR + kadd;
                uint32_t ah[4];
                LDSM_X4(ah[0], ah[1], ah[2], ah[3], base + OFF_AH + aadd);
#pragma unroll
                for (int j = 0; j < 4; j++) MMA16816H(acc[i][j], ah, bh[j]);
            }
        }
    }

    const int lr = lane >> 2;
    const int lc = (lane & 3) * 2;

    if (MODE == 0) {
        // fused epilogue: stage 16x128 tiles in smem, apply RoPE / transpose
        float* T = (float*)dsm;                 // [2][16][132] fp32
        const int wgrp = tid >> 7;
        const int wrow = (tid >> 3) & 15;
        const int wc0  = (tid & 7) * 16;
        const int vc   = tid & 127;

#pragma unroll
        for (int i = 0; i < 4; i++) {
            __syncthreads();
            {
                float* Tg = T + warp_m * (16 * 132);
#pragma unroll
                for (int rr = 0; rr < 2; rr++) {
                    int row = lr + rr * 8;
#pragma unroll
                    for (int j = 0; j < 4; j++) {
                        int col = warp_n * 32 + j * 8 + lc;
                        Tg[row * 132 + col]     = acc[i][j][rr * 2 + 0];
                        Tg[row * 132 + col + 1] = acc[i][j][rr * 2 + 1];
                    }
                }
            }
            __syncthreads();

            if (blockIdx.z == 2) {
                // V: transpose write, fp16 g_vth[(b*H+h)*HD+d][l]
                const float* Tv = T + wgrp * (16 * 132);
                int n = n0 + vc, h = n >> 6, d = n & 63;
                int mbase = m0 + wgrp * 64 + i * 16;
                int b = mbase >> 11, l0i = mbase & (L_ - 1);
                __half tmp[16];
#pragma unroll
                for (int r = 0; r < 16; r++)
                    tmp[r] = __float2half_rn(Tv[r * 132 + vc]);
                size_t dst = (((size_t)(b * H_ + h)) * HD_ + d) * L_ + l0i;
                *(uint4*)&g_vth[dst]     = *(uint4*)tmp;
                *(uint4*)&g_vth[dst + 8] = *(uint4*)(tmp + 8);
            } else {
                // Q / K: rope + fp16 write (q pre-scaled by 1/8)
                const float* Tq = T + wgrp * (16 * 132);
                int m = m0 + wgrp * 64 + i * 16 + wrow;
                int b = m >> 11, l = m & (L_ - 1);
                const float* crw = cosT + l * HD_;
                const float* srw = sinT + l * HD_;
                const float qsc = (blockIdx.z == 0) ? 0.125f : 1.0f;
                __half* dstbuf = (blockIdx.z == 0) ? g_qh : g_kh;
#pragma unroll
                for (int c8 = 0; c8 < 16; c8 += 8) {
                    int c = wc0 + c8;
                    __half tmp[8];
#pragma unroll
                    for (int e = 0; e < 8; e++) {
                        int cc = c + e, d = cc & 63;
                        float a  = Tq[wrow * 132 + cc];
                        float ap = Tq[wrow * 132 + (cc ^ 32)];
                        float r = (d < 32) ? a * crw[d] - ap * srw[d]
                                           : a * crw[d] + ap * srw[d];
                        tmp[e] = __float2half_rn(r * qsc);
                    }
                    int n = n0 + c, h = n >> 6, d = n & 63;
                    *(uint4*)&dstbuf[(((size_t)(b * H_ + h)) * L_ + l) * HD_ + d]
                        = *(uint4*)tmp;
                }
            }
        }
    } else {
#pragma unroll
        for (int i = 0; i < 4; i++) {
            int mr = m0 + warp_m * 64 + i * 16 + lr;
#pragma unroll
            for (int rr = 0; rr < 2; rr++) {
                int m = mr + rr * 8;
#pragma unroll
                for (int j = 0; j < 4; j++) {
                    int n = n0 + warp_n * 32 + j * 8 + lc;
                    float2 v = make_float2(acc[i][j][rr * 2 + 0], acc[i][j][rr * 2 + 1]);
                    *(float2*)&Cout[(size_t)m * D_ + n] = v;
                }
            }
        }
    }
}

// ===========================================================================
// Flash attention, fp16 single-product form (unchanged from R11, passing).
// ===========================================================================
constexpr int SKT = 72;

__global__ __launch_bounds__(128) void attn_mma_kernel()
{
    __shared__ __half sK[64 * SKT], sV[64 * SKT];

    const int tid  = threadIdx.x;
    const int wid  = tid >> 5;
    const int lane = tid & 31;
    const int lr   = lane >> 2;
    const int kp   = (lane & 3) * 2;

    const int bh = blockIdx.x;
    const int q0 = blockIdx.y * 64;

    const __half* qb  = g_qh  + ((size_t)bh * L_ + q0) * HD_;
    const __half* kb  = g_kh  + (size_t)bh * L_ * HD_;
    const __half* vtb = g_vth + (size_t)bh * HD_ * L_;

    uint32_t qh[4][4];
#pragma unroll
    for (int ks = 0; ks < 4; ks++) {
#pragma unroll
        for (int e = 0; e < 4; e++) {
            int row  = wid * 16 + lr + (e & 1) * 8;
            int kcol = ks * 16 + kp + (e >= 2 ? 8 : 0);
            qh[ks][e] = *(const uint32_t*)(qb + (size_t)row * HD_ + kcol);
        }
    }

    float o[8][4];
#pragma unroll
    for (int f = 0; f < 8; f++)
#pragma unroll
        for (int e = 0; e < 4; e++) o[f][e] = 0.0f;
    float m0 = -1e30f, m1 = -1e30f, sum0 = 0.0f, sum1 = 0.0f;

    const int rowa = q0 + wid * 16 + lr;
    const int wmin = q0 + wid * 16;
    const int wmax = wmin + 15;
    const int j0s  = (q0 - WIN_ > 0) ? (q0 - WIN_) : 0;

    for (int j0 = j0s; j0 <= q0; j0 += 64) {
        {
            const int r  = tid >> 1;
            const int cb = (tid & 1) * 32;
            const uint4* ks4 = (const uint4*)(kb  + (size_t)(j0 + r) * HD_ + cb);
            const uint4* vs4 = (const uint4*)(vtb + (size_t)r * L_ + j0 + cb);
            uint4* kd4 = (uint4*)(sK + r * SKT + cb);
            uint4* vd4 = (uint4*)(sV + r * SKT + cb);
#pragma unroll
            for (int it = 0; it < 4; it++) {
                kd4[it] = ks4[it];
                vd4[it] = vs4[it];
            }
        }
        __syncthreads();

        float sf[8][4];
#pragma unroll
        for (int f = 0; f < 8; f++)
#pragma unroll
            for (int e = 0; e < 4; e++) sf[f][e] = 0.0f;

#pragma unroll
        for (int ks = 0; ks < 4; ks++) {
#pragma unroll
            for (int f = 0; f < 8; f++) {
                const int nrow = f * 8 + lr;
                const int kc   = ks * 16 + kp;
                uint32_t kf[2];
                kf[0] = *(const uint32_t*)(sK + nrow * SKT + kc);
                kf[1] = *(const uint32_t*)(sK + nrow * SKT + kc + 8);
                MMA16816H(sf[f], qh[ks], kf);
            }
        }

        const bool full = (j0 + 63 <= wmin) && (j0 >= wmax - WIN_);
        if (!full) {
#pragma unroll
            for (int f = 0; f < 8; f++) {
#pragma unroll
                for (int e = 0; e < 4; e++) {
                    const int col = j0 + f * 8 + kp + (e & 1);
                    const int row = rowa + (e >= 2 ? 8 : 0);
                    const bool ok = (col <= row) && (col >= row - WIN_);
                    if (!ok) sf[f][e] = -1e30f;
                }
            }
        }

        float rm0 = -1e30f, rm1 = -1e30f;
#pragma unroll
        for (int f = 0; f < 8; f++) {
            rm0 = fmaxf(rm0, fmaxf(sf[f][0], sf[f][1]));
            rm1 = fmaxf(rm1, fmaxf(sf[f][2], sf[f][3]));
        }
        rm0 = fmaxf(rm0, __shfl_xor_sync(0xFFFFFFFFu, rm0, 1));
        rm0 = fmaxf(rm0, __shfl_xor_sync(0xFFFFFFFFu, rm0, 2));
        rm1 = fmaxf(rm1, __shfl_xor_sync(0xFFFFFFFFu, rm1, 1));
        rm1 = fmaxf(rm1, __shfl_xor_sync(0xFFFFFFFFu, rm1, 2));

        const float mn0 = fmaxf(m0, rm0);
        const float mn1 = fmaxf(m1, rm1);
        const float sc0 = __expf(m0 - mn0);
        const float sc1 = __expf(m1 - mn1);

        float rs0 = 0.0f, rs1 = 0.0f;
#pragma unroll
        for (int f = 0; f < 8; f++) {
            sf[f][0] = __expf(sf[f][0] - mn0);
            sf[f][1] = __expf(sf[f][1] - mn0);
            sf[f][2] = __expf(sf[f][2] - mn1);
            sf[f][3] = __expf(sf[f][3] - mn1);
            rs0 += sf[f][0] + sf[f][1];
            rs1 += sf[f][2] + sf[f][3];
        }
        rs0 += __shfl_xor_sync(0xFFFFFFFFu, rs0, 1);
        rs0 += __shfl_xor_sync(0xFFFFFFFFu, rs0, 2);
        rs1 += __shfl_xor_sync(0xFFFFFFFFu, rs1, 1);
        rs1 += __shfl_xor_sync(0xFFFFFFFFu, rs1, 2);

        sum0 = sum0 * sc0 + rs0;
        sum1 = sum1 * sc1 + rs1;
        m0 = mn0;
        m1 = mn1;
#pragma unroll
        for (int f = 0; f < 8; f++) {
            o[f][0] *= sc0;
            o[f][1] *= sc0;
            o[f][2] *= sc1;
            o[f][3] *= sc1;
        }

#pragma unroll
        for (int ks = 0; ks < 4; ks++) {
            uint32_t ph[4];
            ph[0] = pack_h2(sf[2 * ks][0],     sf[2 * ks][1]);
            ph[1] = pack_h2(sf[2 * ks][2],     sf[2 * ks][3]);
            ph[2] = pack_h2(sf[2 * ks + 1][0], sf[2 * ks + 1][1]);
            ph[3] = pack_h2(sf[2 * ks + 1][2], sf[2 * ks + 1][3]);
#pragma unroll
            for (int f = 0; f < 8; f++) {
                const int nrow = f * 8 + lr;
                const int kc   = ks * 16 + kp;
                uint32_t vf[2];
                vf[0] = *(const uint32_t*)(sV + nrow * SKT + kc);
                vf[1] = *(const uint32_t*)(sV + nrow * SKT + kc + 8);
                MMA16816H(o[f], ph, vf);
            }
        }
        __syncthreads();
    }

    const float inv0 = 1.0f / sum0;
    const float inv1 = 1.0f / sum1;
    const int b = bh >> 4;
    const int h = bh & (H_ - 1);
#pragma unroll
    for (int f = 0; f < 8; f++) {
        const int d = f * 8 + kp;
        const size_t i0 = ((size_t)(b * L_ + rowa)) * D_ + h * HD_ + d;
        const size_t i1 = ((size_t)(b * L_ + rowa + 8)) * D_ + h * HD_ + d;
        *(uint32_t*)&g_oh[i0] = pack_h2(o[f][0] * inv0, o[f][1] * inv0);
        *(uint32_t*)&g_oh[i1] = pack_h2(o[f][2] * inv1, o[f][3] * inv1);
    }
}

// ---------------------------------------------------------------------------
extern "C" void kernel_launch(void* const* d_in, const int* in_sizes, int n_in,
                              void* d_out, int out_size)
{
    const float* x    = (const float*)d_in[0];
    const float* cosT = (const float*)d_in[1];
    const float* sinT = (const float*)d_in[2];
    const float* Wq   = (const float*)d_in[3];
    const float* Wk   = (const float*)d_in[4];
    const float* Wv   = (const float*)d_in[5];
    const float* Wo   = (const float*)d_in[6];
    float* out        = (float*)d_out;

    cudaFuncSetAttribute(gemm_mma<0>, cudaFuncAttributeMaxDynamicSharedMemorySize, SMEM_GEMM);
    cudaFuncSetAttribute(gemm_mma<1>, cudaFuncAttributeMaxDynamicSharedMemorySize, SMEM_GEMM);

    __half *xh, *wh, *oh;
    cudaGetSymbolAddress((void**)&xh, g_xh);
    cudaGetSymbolAddress((void**)&wh, g_wh);
    cudaGetSymbolAddress((void**)&oh, g_oh);

    // 1) convert x and all W's to fp16 (one launch)
    convert_all_kernel<<<dim3((K_ * K_) / 1024, 8), 256>>>(x, Wq, Wk, Wv, Wo, wh, xh);

    // 2) QKV projection + fused RoPE / V-transpose epilogue (all fp16 out)
    gemm_mma<0><<<dim3(D_ / 128, M_ / 128, 3), 256, SMEM_GEMM>>>(
        xh, wh, cosT, sinT, nullptr);

    // 3) Flash attention (fp16, single-product)
    attn_mma_kernel<<<dim3(B_ * H_, L_ / 64), 128>>>();

    // 4) Output projection
    gemm_mma<1><<<dim3(D_ / 128, M_ / 128, 1), 256, SMEM_GEMM>>>(
        oh, wh, nullptr, nullptr, out);
}

// round 13
// speedup vs baseline: 9.4720x; 1.0232x over previous
#include <cuda_runtime.h>
#include <cuda_fp16.h>
#include <math.h>
#include <stdint.h>

// Problem constants
constexpr int B_   = 2;
constexpr int L_   = 2048;
constexpr int D_   = 1024;
constexpr int H_   = 16;
constexpr int HD_  = 64;
constexpr int WIN_ = 256;
constexpr int M_   = B_ * L_;   // 4096 rows
constexpr int K_   = D_;        // 1024 reduction dim

// Scratch (allocation-free: __device__ globals)
__device__ __half g_qh [(size_t)B_ * H_ * L_ * HD_];   // q fp16, roped, pre-scaled 1/8
__device__ __half g_kh [(size_t)B_ * H_ * L_ * HD_];   // k fp16, roped
__device__ __half g_vth[(size_t)B_ * H_ * HD_ * L_];   // v fp16 transposed [b,h,d,l]

__device__ __half g_xh [(size_t)M_ * K_];
__device__ __half g_wh [(size_t)4 * K_ * K_];          // Wq,Wk,Wv,Wo fp16
__device__ __half g_oh [(size_t)M_ * K_];              // attn out fp16

// fp16 m16n8k16 mma (baseline PTX, works on plain sm_103 target)
#define MMA16816H(d, a, b) \
    asm volatile("mma.sync.aligned.m16n8k16.row.col.f32.f16.f16.f32 " \
        "{%0,%1,%2,%3}, {%4,%5,%6,%7}, {%8,%9}, {%0,%1,%2,%3};" \
        : "+f"((d)[0]), "+f"((d)[1]), "+f"((d)[2]), "+f"((d)[3]) \
        : "r"((a)[0]), "r"((a)[1]), "r"((a)[2]), "r"((a)[3]), \
          "r"((b)[0]), "r"((b)[1]))

#define LDSM_X4(r0, r1, r2, r3, addr) \
    asm volatile("ldmatrix.sync.aligned.m8n8.x4.shared.b16 {%0,%1,%2,%3}, [%4];" \
        : "=r"(r0), "=r"(r1), "=r"(r2), "=r"(r3) : "r"(addr))

#define CP_ASYNC16(smaddr, gptr) \
    asm volatile("cp.async.cg.shared.global [%0], [%1], 16;" :: "r"(smaddr), "l"(gptr))
#define CP_COMMIT() asm volatile("cp.async.commit_group;" ::: "memory")
#define CP_WAIT(n)  asm volatile("cp.async.wait_group %0;" :: "n"(n) : "memory")

__device__ __forceinline__ uint32_t smem_u32(const void* p) {
    uint32_t a;
    asm("{ .reg .u64 t; cvta.to.shared.u64 t, %1; cvt.u32.u64 %0, t; }" : "=r"(a) : "l"(p));
    return a;
}
__device__ __forceinline__ uint32_t pack_h2(float a, float b) {
    __half2 h = __floats2half2_rn(a, b);
    return *(uint32_t*)&h;
}

// ===========================================================================
// convert x (4 chunks) + all 4 W's to fp16 in ONE launch. grid=(1024, 8).
// ===========================================================================
__global__ __launch_bounds__(256) void convert_all_kernel(
    const float* __restrict__ x,
    const float* __restrict__ W0, const float* __restrict__ W1,
    const float* __restrict__ W2, const float* __restrict__ W3,
    __half* __restrict__ wh, __half* __restrict__ xh)
{
    const int y = blockIdx.y;
    const float* src;
    __half* dst;
    if (y < 4) {
        src = (y == 0) ? W0 : (y == 1) ? W1 : (y == 2) ? W2 : W3;
        dst = wh + (size_t)y * K_ * K_;
    } else {
        src = x + (size_t)(y - 4) * K_ * K_;
        dst = xh + (size_t)(y - 4) * K_ * K_;
    }
    int i = (blockIdx.x * 256 + threadIdx.x) * 4;
    float4 v = *(const float4*)(src + i);
    uint2 o;
    o.x = pack_h2(v.x, v.y);
    o.y = pack_h2(v.z, v.w);
    *(uint2*)(dst + i) = o;
}

// ===========================================================================
// HMMA fp16 GEMM: C[m,n] = sum_k Ah[m,k]*Wh[n,k]
// Tile BM=BN=128, BK=64, 256 threads, 2 CTAs/SM, 3-stage cp.async pipeline,
// one barrier per chunk. MODE 0 epilogue: double-buffered smem staging in
// stage-1 space (quiescent after mainloop), ONE sync per i-frag.
// ===========================================================================
constexpr int RSTR     = 144;                      // smem row stride bytes
constexpr int MAT_B    = 128 * RSTR;               // 18432 bytes per matrix
constexpr int OFF_AH   = 0;
constexpr int OFF_WH   = MAT_B;
constexpr int STAGE_B  = 2 * MAT_B;                // 36864
constexpr int SMEM_GEMM = 3 * STAGE_B;             // 110592
constexpr int NCH      = K_ / 64;                  // 16

template <int MODE>
__global__ __launch_bounds__(256, 2) void gemm_mma(
    const __half* __restrict__ Ah,
    const __half* __restrict__ WhAll,
    const float* __restrict__ cosT,
    const float* __restrict__ sinT,
    float* __restrict__ Cout)
{
    extern __shared__ char dsm[];
    const uint32_t sb = smem_u32(dsm);

    const int tid    = threadIdx.x;
    const int wid    = tid >> 5;
    const int lane   = tid & 31;
    const int warp_m = wid & 1;
    const int warp_n = wid >> 1;
    const int m0     = blockIdx.y * 128;
    const int n0     = blockIdx.x * 128;
    const int z      = (MODE == 0) ? blockIdx.z : 3;

    const __half* Wh = WhAll + (size_t)z * K_ * K_;

    const int crow = tid >> 3;
    const int cseg = tid & 7;
    const uint32_t cso = (uint32_t)crow * RSTR + (uint32_t)cseg * 16;

    const int lm = lane & 7;
    const uint32_t a_off = (uint32_t)(warp_m * 64 + lm + ((lane >> 3) & 1) * 8) * RSTR
                         + (uint32_t)((lane >> 4) & 1) * 16;
    const uint32_t b_off = (uint32_t)(warp_n * 32 + lm + ((lane >> 4) & 1) * 8) * RSTR
                         + (uint32_t)((lane >> 3) & 1) * 16;

    float acc[4][4][4];
#pragma unroll
    for (int i = 0; i < 4; i++)
#pragma unroll
        for (int j = 0; j < 4; j++)
#pragma unroll
            for (int r = 0; r < 4; r++) acc[i][j][r] = 0.0f;

    auto load_stage = [&](int c, int s) {
        const uint32_t base = sb + (uint32_t)s * STAGE_B;
        const int kt0 = c * 64;
#pragma unroll
        for (int t = 0; t < 4; t++) {
            const int row = crow + 32 * t;
            size_t ao = (size_t)(m0 + row) * K_ + kt0 + cseg * 8;
            size_t wo = (size_t)(n0 + row) * K_ + kt0 + cseg * 8;
            const uint32_t so = cso + (uint32_t)(32 * t) * RSTR;
            CP_ASYNC16(base + OFF_AH + so, Ah + ao);
            CP_ASYNC16(base + OFF_WH + so, Wh + wo);
        }
        CP_COMMIT();
    };

    load_stage(0, 0);
    load_stage(1, 1);

    int sc = 0, sp = 2;
    for (int c = 0; c < NCH; c++) {
        if (c == NCH - 1) { CP_WAIT(0); } else { CP_WAIT(1); }
        __syncthreads();
        if (c + 2 < NCH) {
            load_stage(c + 2, sp);
            sp = (sp == 2) ? 0 : sp + 1;
        }

        const uint32_t base = sb + (uint32_t)sc * STAGE_B;
        sc = (sc == 2) ? 0 : sc + 1;

#pragma unroll
        for (int ks = 0; ks < 4; ks++) {
            const uint32_t kadd = (uint32_t)ks * 32;
            uint32_t bh[4][2];
#pragma unroll
            for (int jp = 0; jp < 4; jp += 2) {
                const uint32_t badd = b_off + (uint32_t)jp * 8 * RSTR + kadd;
                LDSM_X4(bh[jp][0], bh[jp][1], bh[jp + 1][0], bh[jp + 1][1],
                        base + OFF_WH + badd);
            }
#pragma unroll
            for (int i = 0; i < 4; i++) {
                const uint32_t aadd = a_off + (uint32_t)i * 16 * RSTR + kadd;
                uint32_t ah[4];
                LDSM_X4(ah[0], ah[1], ah[2], ah[3], base + OFF_AH + aadd);
#pragma unroll
                for (int j = 0; j < 4; j++) MMA16816H(acc[i][j], ah, bh[j]);
            }
        }
    }

    const int lr = lane >> 2;
    const int lc = (lane & 3) * 2;

    if (MODE == 0) {
        // fused epilogue, double-buffered in stage-1 smem (quiescent: last
        // chunk read stage 0, and the c=14 barrier drained stage-1 readers).
        // One __syncthreads per i-frag.
        float* T = (float*)(dsm + STAGE_B);     // [2 bufs][2 wgrp][16][132] fp32
        const int wgrp = tid >> 7;
        const int wrow = (tid >> 3) & 15;
        const int wc0  = (tid & 7) * 16;
        const int vc   = tid & 127;

#pragma unroll
        for (int i = 0; i < 4; i++) {
            float* Tb = T + (i & 1) * (2 * 16 * 132) + warp_m * (16 * 132);
#pragma unroll
            for (int rr = 0; rr < 2; rr++) {
                int row = lr + rr * 8;
#pragma unroll
                for (int j = 0; j < 4; j++) {
                    int col = warp_n * 32 + j * 8 + lc;
                    Tb[row * 132 + col]     = acc[i][j][rr * 2 + 0];
                    Tb[row * 132 + col + 1] = acc[i][j][rr * 2 + 1];
                }
            }
            __syncthreads();
            const float* Tr = T + (i & 1) * (2 * 16 * 132) + wgrp * (16 * 132);

            if (blockIdx.z == 2) {
                // V: transpose write, fp16 g_vth[(b*H+h)*HD+d][l]
                int n = n0 + vc, h = n >> 6, d = n & 63;
                int mbase = m0 + wgrp * 64 + i * 16;
                int b = mbase >> 11, l0i = mbase & (L_ - 1);
                __half tmp[16];
#pragma unroll
                for (int r = 0; r < 16; r++)
                    tmp[r] = __float2half_rn(Tr[r * 132 + vc]);
                size_t dst = (((size_t)(b * H_ + h)) * HD_ + d) * L_ + l0i;
                *(uint4*)&g_vth[dst]     = *(uint4*)tmp;
                *(uint4*)&g_vth[dst + 8] = *(uint4*)(tmp + 8);
            } else {
                // Q / K: rope + fp16 write (q pre-scaled by 1/8)
                int m = m0 + wgrp * 64 + i * 16 + wrow;
                int b = m >> 11, l = m & (L_ - 1);
                const float* crw = cosT + l * HD_;
                const float* srw = sinT + l * HD_;
                const float qsc = (blockIdx.z == 0) ? 0.125f : 1.0f;
                __half* dstbuf = (blockIdx.z == 0) ? g_qh : g_kh;
#pragma unroll
                for (int c8 = 0; c8 < 16; c8 += 8) {
                    int c = wc0 + c8;
                    __half tmp[8];
#pragma unroll
                    for (int e = 0; e < 8; e++) {
                        int cc = c + e, d = cc & 63;
                        float a  = Tr[wrow * 132 + cc];
                        float ap = Tr[wrow * 132 + (cc ^ 32)];
                        float r = (d < 32) ? a * crw[d] - ap * srw[d]
                                           : a * crw[d] + ap * srw[d];
                        tmp[e] = __float2half_rn(r * qsc);
                    }
                    int n = n0 + c, h = n >> 6, d = n & 63;
                    *(uint4*)&dstbuf[(((size_t)(b * H_ + h)) * L_ + l) * HD_ + d]
                        = *(uint4*)tmp;
                }
            }
        }
    } else {
#pragma unroll
        for (int i = 0; i < 4; i++) {
            int mr = m0 + warp_m * 64 + i * 16 + lr;
#pragma unroll
            for (int rr = 0; rr < 2; rr++) {
                int m = mr + rr * 8;
#pragma unroll
                for (int j = 0; j < 4; j++) {
                    int n = n0 + warp_n * 32 + j * 8 + lc;
                    float2 v = make_float2(acc[i][j][rr * 2 + 0], acc[i][j][rr * 2 + 1]);
                    *(float2*)&Cout[(size_t)m * D_ + n] = v;
                }
            }
        }
    }
}

// ===========================================================================
// Flash attention, fp16 single-product. CTA = 128 queries (8 warps); K/V
// chunk load amortized over 2x the queries; per-warp chunk-skip guards.
// ===========================================================================
constexpr int SKT = 72;

__global__ __launch_bounds__(256) void attn_mma_kernel()
{
    __shared__ __half sK[64 * SKT], sV[64 * SKT];

    const int tid  = threadIdx.x;
    const int wid  = tid >> 5;
    const int lane = tid & 31;
    const int lr   = lane >> 2;
    const int kp   = (lane & 3) * 2;

    const int bh = blockIdx.x;
    const int q0 = blockIdx.y * 128;

    const __half* qb  = g_qh  + ((size_t)bh * L_ + q0) * HD_;
    const __half* kb  = g_kh  + (size_t)bh * L_ * HD_;
    const __half* vtb = g_vth + (size_t)bh * HD_ * L_;

    // Q fragments (warp owns rows q0 + wid*16 .. +15)
    uint32_t qh[4][4];
#pragma unroll
    for (int ks = 0; ks < 4; ks++) {
#pragma unroll
        for (int e = 0; e < 4; e++) {
            int row  = wid * 16 + lr + (e & 1) * 8;
            int kcol = ks * 16 + kp + (e >= 2 ? 8 : 0);
            qh[ks][e] = *(const uint32_t*)(qb + (size_t)row * HD_ + kcol);
        }
    }

    float o[8][4];
#pragma unroll
    for (int f = 0; f < 8; f++)
#pragma unroll
        for (int e = 0; e < 4; e++) o[f][e] = 0.0f;
    float m0 = -1e30f, m1 = -1e30f, sum0 = 0.0f, sum1 = 0.0f;

    const int rowa = q0 + wid * 16 + lr;
    const int wmin = q0 + wid * 16;
    const int wmax = wmin + 15;
    const int j0s  = (q0 - WIN_ > 0) ? (q0 - WIN_) : 0;

    for (int j0 = j0s; j0 <= q0 + 64; j0 += 64) {
        // cooperative load: K chunk [64 keys][64 d], V^T chunk [64 d][64 keys]
        {
            const int r  = tid >> 2;             // row 0..63
            const int cb = (tid & 3) * 16;       // 16-elem (32B) segment
            const uint4* ks4 = (const uint4*)(kb  + (size_t)(j0 + r) * HD_ + cb);
            const uint4* vs4 = (const uint4*)(vtb + (size_t)r * L_ + j0 + cb);
            uint4* kd4 = (uint4*)(sK + r * SKT + cb);
            uint4* vd4 = (uint4*)(sV + r * SKT + cb);
            kd4[0] = ks4[0]; kd4[1] = ks4[1];
            vd4[0] = vs4[0]; vd4[1] = vs4[1];
        }
        __syncthreads();

        // per-warp relevance guard: skip chunks outside this warp's window
        const bool active = (j0 <= wmax) && (j0 + 63 >= wmin - WIN_);
        if (active) {
            float sf[8][4];
#pragma unroll
            for (int f = 0; f < 8; f++)
#pragma unroll
                for (int e = 0; e < 4; e++) sf[f][e] = 0.0f;

#pragma unroll
            for (int ks = 0; ks < 4; ks++) {
#pragma unroll
                for (int f = 0; f < 8; f++) {
                    const int nrow = f * 8 + lr;
                    const int kc   = ks * 16 + kp;
                    uint32_t kf[2];
                    kf[0] = *(const uint32_t*)(sK + nrow * SKT + kc);
                    kf[1] = *(const uint32_t*)(sK + nrow * SKT + kc + 8);
                    MMA16816H(sf[f], qh[ks], kf);
                }
            }

            const bool full = (j0 + 63 <= wmin) && (j0 >= wmax - WIN_);
            if (!full) {
#pragma unroll
                for (int f = 0; f < 8; f++) {
#pragma unroll
                    for (int e = 0; e < 4; e++) {
                        const int col = j0 + f * 8 + kp + (e & 1);
                        const int row = rowa + (e >= 2 ? 8 : 0);
                        const bool ok = (col <= row) && (col >= row - WIN_);
                        if (!ok) sf[f][e] = -1e30f;
                    }
                }
            }

            float rm0 = -1e30f, rm1 = -1e30f;
#pragma unroll
            for (int f = 0; f < 8; f++) {
                rm0 = fmaxf(rm0, fmaxf(sf[f][0], sf[f][1]));
                rm1 = fmaxf(rm1, fmaxf(sf[f][2], sf[f][3]));
            }
            rm0 = fmaxf(rm0, __shfl_xor_sync(0xFFFFFFFFu, rm0, 1));
            rm0 = fmaxf(rm0, __shfl_xor_sync(0xFFFFFFFFu, rm0, 2));
            rm1 = fmaxf(rm1, __shfl_xor_sync(0xFFFFFFFFu, rm1, 1));
            rm1 = fmaxf(rm1, __shfl_xor_sync(0xFFFFFFFFu, rm1, 2));

            const float mn0 = fmaxf(m0, rm0);
            const float mn1 = fmaxf(m1, rm1);
            const float sc0 = __expf(m0 - mn0);
            const float sc1 = __expf(m1 - mn1);

            float rs0 = 0.0f, rs1 = 0.0f;
#pragma unroll
            for (int f = 0; f < 8; f++) {
                sf[f][0] = __expf(sf[f][0] - mn0);
                sf[f][1] = __expf(sf[f][1] - mn0);
                sf[f][2] = __expf(sf[f][2] - mn1);
                sf[f][3] = __expf(sf[f][3] - mn1);
                rs0 += sf[f][0] + sf[f][1];
                rs1 += sf[f][2] + sf[f][3];
            }
            rs0 += __shfl_xor_sync(0xFFFFFFFFu, rs0, 1);
            rs0 += __shfl_xor_sync(0xFFFFFFFFu, rs0, 2);
            rs1 += __shfl_xor_sync(0xFFFFFFFFu, rs1, 1);
            rs1 += __shfl_xor_sync(0xFFFFFFFFu, rs1, 2);

            sum0 = sum0 * sc0 + rs0;
            sum1 = sum1 * sc1 + rs1;
            m0 = mn0;
            m1 = mn1;
#pragma unroll
            for (int f = 0; f < 8; f++) {
                o[f][0] *= sc0;
                o[f][1] *= sc0;
                o[f][2] *= sc1;
                o[f][3] *= sc1;
            }

#pragma unroll
            for (int ks = 0; ks < 4; ks++) {
                uint32_t ph[4];
                ph[0] = pack_h2(sf[2 * ks][0],     sf[2 * ks][1]);
                ph[1] = pack_h2(sf[2 * ks][2],     sf[2 * ks][3]);
                ph[2] = pack_h2(sf[2 * ks + 1][0], sf[2 * ks + 1][1]);
                ph[3] = pack_h2(sf[2 * ks + 1][2], sf[2 * ks + 1][3]);
#pragma unroll
                for (int f = 0; f < 8; f++) {
                    const int nrow = f * 8 + lr;
                    const int kc   = ks * 16 + kp;
                    uint32_t vf[2];
                    vf[0] = *(const uint32_t*)(sV + nrow * SKT + kc);
                    vf[1] = *(const uint32_t*)(sV + nrow * SKT + kc + 8);
                    MMA16816H(o[f], ph, vf);
                }
            }
        }
        __syncthreads();
    }

    // epilogue: normalize, emit fp16 for output projection
    const float inv0 = 1.0f / sum0;
    const float inv1 = 1.0f / sum1;
    const int b = bh >> 4;
    const int h = bh & (H_ - 1);
#pragma unroll
    for (int f = 0; f < 8; f++) {
        const int d = f * 8 + kp;
        const size_t i0 = ((size_t)(b * L_ + rowa)) * D_ + h * HD_ + d;
        const size_t i1 = ((size_t)(b * L_ + rowa + 8)) * D_ + h * HD_ + d;
        *(uint32_t*)&g_oh[i0] = pack_h2(o[f][0] * inv0, o[f][1] * inv0);
        *(uint32_t*)&g_oh[i1] = pack_h2(o[f][2] * inv1, o[f][3] * inv1);
    }
}

// ---------------------------------------------------------------------------
extern "C" void kernel_launch(void* const* d_in, const int* in_sizes, int n_in,
                              void* d_out, int out_size)
{
    const float* x    = (const float*)d_in[0];
    const float* cosT = (const float*)d_in[1];
    const float* sinT = (const float*)d_in[2];
    const float* Wq   = (const float*)d_in[3];
    const float* Wk   = (const float*)d_in[4];
    const float* Wv   = (const float*)d_in[5];
    const float* Wo   = (const float*)d_in[6];
    float* out        = (float*)d_out;

    cudaFuncSetAttribute(gemm_mma<0>, cudaFuncAttributeMaxDynamicSharedMemorySize, SMEM_GEMM);
    cudaFuncSetAttribute(gemm_mma<1>, cudaFuncAttributeMaxDynamicSharedMemorySize, SMEM_GEMM);

    __half *xh, *wh, *oh;
    cudaGetSymbolAddress((void**)&xh, g_xh);
    cudaGetSymbolAddress((void**)&wh, g_wh);
    cudaGetSymbolAddress((void**)&oh, g_oh);

    // 1) convert x and all W's to fp16 (one launch)
    convert_all_kernel<<<dim3((K_ * K_) / 1024, 8), 256>>>(x, Wq, Wk, Wv, Wo, wh, xh);

    // 2) QKV projection + fused RoPE / V-transpose epilogue (all fp16 out)
    gemm_mma<0><<<dim3(D_ / 128, M_ / 128, 3), 256, SMEM_GEMM>>>(
        xh, wh, cosT, sinT, nullptr);

    // 3) Flash attention (fp16, single-product, 128 queries/CTA)
    attn_mma_kernel<<<dim3(B_ * H_, L_ / 128), 256>>>();

    // 4) Output projection
    gemm_mma<1><<<dim3(D_ / 128, M_ / 128, 1), 256, SMEM_GEMM>>>(
        oh, wh, nullptr, nullptr, out);
}